// round 1
// baseline (speedup 1.0000x reference)
#include <cuda_runtime.h>
#include <math.h>

#define BB  8
#define SS  512
#define DD  768
#define NHH 12
#define HDD 64
#define FFF 3072
#define NLL 12
#define MT  (BB*SS)   // 4096 tokens

// ---------------- scratch (static device globals; no allocation) ----------------
__device__ float g_h[MT*DD];
__device__ float g_q[MT*DD];
__device__ float g_k[MT*DD];
__device__ float g_v[MT*DD];
__device__ float g_qg[MT*DD];
__device__ float g_attn[(size_t)BB*NHH*SS*SS];   // 100 MB
__device__ float g_ctx[MT*DD];
__device__ float g_a[MT*DD];
__device__ float g_f[MT*FFF];
__device__ float g_o[MT*DD];
__device__ float g_hmean[BB*DD];
__device__ float g_cw[BB*HDD];
__device__ float g_ginv[BB*HDD*HDD];

// ---------------- embedding gather + LayerNorm ----------------
__global__ __launch_bounds__(256)
void embed_ln_kernel(const int* __restrict__ ids, const int* __restrict__ tts,
                     const float* __restrict__ we, const float* __restrict__ pe,
                     const float* __restrict__ te,
                     const float* __restrict__ w, const float* __restrict__ bb,
                     float* __restrict__ out)
{
    int t = blockIdx.x;
    int s = t % SS;
    int tid = threadIdx.x;
    int id = ids[t], tt = tts[t];
    const float* wr = we + (size_t)id * DD;
    const float* pr = pe + (size_t)s  * DD;
    const float* tr = te + (size_t)tt * DD;
    __shared__ float red[256];
    float v[3];
    float sum = 0.f;
    #pragma unroll
    for (int i = 0; i < 3; i++) {
        int d = tid + i * 256;
        v[i] = wr[d] + pr[d] + tr[d];
        sum += v[i];
    }
    red[tid] = sum; __syncthreads();
    for (int o = 128; o > 0; o >>= 1) { if (tid < o) red[tid] += red[tid + o]; __syncthreads(); }
    float mean = red[0] * (1.0f / DD);
    __syncthreads();
    float vs = 0.f;
    #pragma unroll
    for (int i = 0; i < 3; i++) { float d0 = v[i] - mean; vs += d0 * d0; }
    red[tid] = vs; __syncthreads();
    for (int o = 128; o > 0; o >>= 1) { if (tid < o) red[tid] += red[tid + o]; __syncthreads(); }
    float var = red[0] * (1.0f / DD);
    float rstd = rsqrtf(var + 1e-12f);
    size_t base = (size_t)t * DD;
    #pragma unroll
    for (int i = 0; i < 3; i++) {
        int d = tid + i * 256;
        out[base + d] = (v[i] - mean) * rstd * w[d] + bb[d];
    }
}

// ---------------- out = LayerNorm(x + y) * w + b ----------------
__global__ __launch_bounds__(256)
void add_ln_kernel(const float* __restrict__ x, const float* __restrict__ y,
                   const float* __restrict__ w, const float* __restrict__ bb,
                   float* __restrict__ out)
{
    int t = blockIdx.x;
    int tid = threadIdx.x;
    __shared__ float red[256];
    size_t base = (size_t)t * DD;
    float v[3];
    float sum = 0.f;
    #pragma unroll
    for (int i = 0; i < 3; i++) {
        int d = tid + i * 256;
        v[i] = x[base + d] + y[base + d];
        sum += v[i];
    }
    red[tid] = sum; __syncthreads();
    for (int o = 128; o > 0; o >>= 1) { if (tid < o) red[tid] += red[tid + o]; __syncthreads(); }
    float mean = red[0] * (1.0f / DD);
    __syncthreads();
    float vs = 0.f;
    #pragma unroll
    for (int i = 0; i < 3; i++) { float d0 = v[i] - mean; vs += d0 * d0; }
    red[tid] = vs; __syncthreads();
    for (int o = 128; o > 0; o >>= 1) { if (tid < o) red[tid] += red[tid + o]; __syncthreads(); }
    float var = red[0] * (1.0f / DD);
    float rstd = rsqrtf(var + 1e-12f);
    #pragma unroll
    for (int i = 0; i < 3; i++) {
        int d = tid + i * 256;
        out[base + d] = (v[i] - mean) * rstd * w[d] + bb[d];
    }
}

// ---------------- generic SGEMM: C[M,N] = A[M,K] @ W[K,N] + bias, opt GELU ----------------
__global__ __launch_bounds__(256, 2)
void sgemm_kernel(const float* __restrict__ A, const float* __restrict__ W,
                  const float* __restrict__ bias, float* __restrict__ C,
                  int M, int N, int K, int act)
{
    __shared__ float As[8][128];
    __shared__ float Bs[8][128];
    const int bm = blockIdx.y * 128;
    const int bn = blockIdx.x * 128;
    const int tid = threadIdx.x;
    const int tx = tid & 15;
    const int ty = tid >> 4;
    const int arow = tid >> 1;
    const int acol = (tid & 1) * 4;
    const int brow = tid >> 5;
    const int bcol = (tid & 31) * 4;

    const float* Ap = A + (size_t)(bm + arow) * K + acol;
    const float* Wp = W + (size_t)brow * N + bn + bcol;

    float acc[8][8];
    #pragma unroll
    for (int i = 0; i < 8; i++)
        #pragma unroll
        for (int j = 0; j < 8; j++) acc[i][j] = 0.f;

    for (int k0 = 0; k0 < K; k0 += 8) {
        float4 av = *(const float4*)Ap;
        float4 wv = *(const float4*)Wp;
        As[acol + 0][arow] = av.x;
        As[acol + 1][arow] = av.y;
        As[acol + 2][arow] = av.z;
        As[acol + 3][arow] = av.w;
        *(float4*)&Bs[brow][bcol] = wv;
        __syncthreads();
        #pragma unroll
        for (int kk = 0; kk < 8; kk++) {
            float4 a0 = *(const float4*)&As[kk][ty * 4];
            float4 a1 = *(const float4*)&As[kk][64 + ty * 4];
            float4 b0 = *(const float4*)&Bs[kk][tx * 4];
            float4 b1 = *(const float4*)&Bs[kk][64 + tx * 4];
            float ar[8] = {a0.x, a0.y, a0.z, a0.w, a1.x, a1.y, a1.z, a1.w};
            float br[8] = {b0.x, b0.y, b0.z, b0.w, b1.x, b1.y, b1.z, b1.w};
            #pragma unroll
            for (int i = 0; i < 8; i++)
                #pragma unroll
                for (int j = 0; j < 8; j++)
                    acc[i][j] = fmaf(ar[i], br[j], acc[i][j]);
        }
        __syncthreads();
        Ap += 8;
        Wp += (size_t)8 * N;
    }

    #pragma unroll
    for (int i = 0; i < 8; i++) {
        int m = bm + ((i < 4) ? (ty * 4 + i) : (64 + ty * 4 + i - 4));
        #pragma unroll
        for (int j = 0; j < 8; j++) {
            int n = bn + ((j < 4) ? (tx * 4 + j) : (64 + tx * 4 + j - 4));
            float vv = acc[i][j] + bias[n];
            if (act == 1) vv = 0.5f * vv * (1.f + erff(vv * 0.70710678118654752f));
            C[(size_t)m * N + n] = vv;
        }
    }
}

// ---------------- per-batch mean over sequence ----------------
__global__ void pool_kernel(const float* __restrict__ h, float* __restrict__ hmean)
{
    int b = blockIdx.x;
    int d = threadIdx.x;
    float s = 0.f;
    for (int t = 0; t < SS; t++) s += h[((size_t)b * SS + t) * DD + d];
    hmean[b * DD + d] = s * (1.0f / SS);
}

// ---------------- cw = sigmoid((hmean @ Wcp + bcp)[:64]) ----------------
__global__ void cw_kernel(const float* __restrict__ hmean, const float* __restrict__ Wcp,
                          const float* __restrict__ bcp, float* __restrict__ cw)
{
    int b = blockIdx.x;
    int j = threadIdx.x; // 0..63
    float acc = bcp[j];
    const float* hm = hmean + b * DD;
    for (int d = 0; d < DD; d++) acc = fmaf(hm[d], Wcp[(size_t)d * DD + j], acc);
    cw[b * HDD + j] = 1.f / (1.f + expf(-acc));
}

// ---------------- metric build + 64x64 inverse (Gauss-Jordan, SPD dominant) ----------------
__global__ __launch_bounds__(256)
void ginv_kernel(const float* __restrict__ Lm_l, const float* __restrict__ diag_l,
                 const float* __restrict__ cw, float* __restrict__ ginv)
{
    int b = blockIdx.x, tid = threadIdx.x;
    __shared__ float L[64][64];   // first l_mod, later the right (inverse) half
    __shared__ float A[64][65];   // metric (left half)
    __shared__ float fcol[64];

    for (int it = 0; it < 16; it++) {
        int idx = it * 256 + tid; int i = idx >> 6, j = idx & 63;
        L[i][j] = Lm_l[i * 64 + j] * cw[b * HDD + i];
    }
    __syncthreads();
    for (int it = 0; it < 16; it++) {
        int idx = it * 256 + tid; int i = idx >> 6, j = idx & 63;
        float s = 0.f;
        for (int t2 = 0; t2 < 64; t2++) s = fmaf(L[i][t2], L[j][t2], s);
        if (i == j) s += diag_l[i] + 1e-6f + 0.1f;
        A[i][j] = s;
    }
    __syncthreads();
    for (int it = 0; it < 16; it++) {
        int idx = it * 256 + tid; int i = idx >> 6, j = idx & 63;
        L[i][j] = (i == j) ? 1.f : 0.f;
    }
    __syncthreads();

    for (int p = 0; p < 64; p++) {
        float ip = 1.f / A[p][p];
        float myf = (tid < 64) ? A[tid][p] : 0.f;
        __syncthreads();
        if (tid < 64)        A[p][tid]       *= ip;
        else if (tid < 128)  L[p][tid - 64]  *= ip;
        if (tid < 64) fcol[tid] = (tid == p) ? 0.f : myf;
        __syncthreads();
        for (int it = 0; it < 32; it++) {
            int idx = it * 256 + tid;
            int r = idx >> 7, c = idx & 127;
            if (r != p) {
                if (c < 64) A[r][c]      -= fcol[r] * A[p][c];
                else        L[r][c - 64] -= fcol[r] * L[p][c - 64];
            }
        }
        __syncthreads();
    }
    for (int it = 0; it < 16; it++) {
        int idx = it * 256 + tid;
        ginv[b * (HDD * HDD) + idx] = L[idx >> 6][idx & 63];
    }
}

// ---------------- qg = q @ g_inv (per batch, shared across heads) ----------------
__global__ __launch_bounds__(256)
void qg_kernel(const float* __restrict__ q, const float* __restrict__ ginv,
               float* __restrict__ qg)
{
    int m0 = blockIdx.x * 64;
    int h  = blockIdx.y;
    int b  = m0 / SS;
    __shared__ float Qt[64][65];   // Qt[d][i]
    __shared__ float G[64][65];    // G[d][e]
    int tid = threadIdx.x;
    const float* gb = ginv + b * (HDD * HDD);
    #pragma unroll
    for (int it = 0; it < 16; it++) {
        int idx = it * 256 + tid;
        int r = idx >> 6, c = idx & 63;
        Qt[c][r] = q[(size_t)(m0 + r) * DD + h * HDD + c];
        G[r][c]  = gb[idx];
    }
    __syncthreads();
    int tx = tid & 15, ty = tid >> 4;
    float acc[4][4] = {};
    for (int d = 0; d < 64; d++) {
        float a[4], bb[4];
        #pragma unroll
        for (int i = 0; i < 4; i++) a[i] = Qt[d][ty * 4 + i];
        #pragma unroll
        for (int j = 0; j < 4; j++) bb[j] = G[d][tx * 4 + j];
        #pragma unroll
        for (int i = 0; i < 4; i++)
            #pragma unroll
            for (int j = 0; j < 4; j++)
                acc[i][j] = fmaf(a[i], bb[j], acc[i][j]);
    }
    #pragma unroll
    for (int i = 0; i < 4; i++)
        #pragma unroll
        for (int j = 0; j < 4; j++)
            qg[(size_t)(m0 + ty * 4 + i) * DD + h * HDD + tx * 4 + j] = acc[i][j];
}

// ---------------- scores = qg @ k^T / 8 ----------------
__global__ __launch_bounds__(256)
void scores_kernel(const float* __restrict__ qg, const float* __restrict__ k,
                   float* __restrict__ sc)
{
    int bh = blockIdx.z;
    int b = bh / NHH, h = bh % NHH;
    int i0 = blockIdx.y * 64, j0 = blockIdx.x * 64;
    __shared__ float Qt[64][65];   // Qt[d][i]
    __shared__ float Kt[64][65];   // Kt[d][j]
    int tid = threadIdx.x;
    #pragma unroll
    for (int it = 0; it < 16; it++) {
        int idx = it * 256 + tid;
        int r = idx >> 6, c = idx & 63;
        Qt[c][r] = qg[(size_t)(b * SS + i0 + r) * DD + h * HDD + c];
        Kt[c][r] = k [(size_t)(b * SS + j0 + r) * DD + h * HDD + c];
    }
    __syncthreads();
    int tx = tid & 15, ty = tid >> 4;
    float acc[4][4] = {};
    for (int d = 0; d < 64; d++) {
        float a[4], bb[4];
        #pragma unroll
        for (int i = 0; i < 4; i++) a[i] = Qt[d][ty * 4 + i];
        #pragma unroll
        for (int j = 0; j < 4; j++) bb[j] = Kt[d][tx * 4 + j];
        #pragma unroll
        for (int i = 0; i < 4; i++)
            #pragma unroll
            for (int j = 0; j < 4; j++)
                acc[i][j] = fmaf(a[i], bb[j], acc[i][j]);
    }
    #pragma unroll
    for (int i = 0; i < 4; i++)
        #pragma unroll
        for (int j = 0; j < 4; j++)
            sc[((size_t)bh * SS + i0 + ty * 4 + i) * SS + j0 + tx * 4 + j] = acc[i][j] * 0.125f;
}

// ---------------- row softmax over 512 ----------------
__global__ __launch_bounds__(256)
void softmax_kernel(float* __restrict__ sc)
{
    size_t row = blockIdx.x;
    float* p = sc + row * SS;
    int tid = threadIdx.x;
    __shared__ float red[256];
    float v0 = p[tid], v1 = p[tid + 256];
    red[tid] = fmaxf(v0, v1); __syncthreads();
    for (int o = 128; o > 0; o >>= 1) { if (tid < o) red[tid] = fmaxf(red[tid], red[tid + o]); __syncthreads(); }
    float mx = red[0];
    __syncthreads();
    float e0 = expf(v0 - mx), e1 = expf(v1 - mx);
    red[tid] = e0 + e1; __syncthreads();
    for (int o = 128; o > 0; o >>= 1) { if (tid < o) red[tid] += red[tid + o]; __syncthreads(); }
    float inv = 1.f / red[0];
    p[tid] = e0 * inv;
    p[tid + 256] = e1 * inv;
}

// ---------------- ctx = attn @ v, written directly in [B,S,D] layout ----------------
__global__ __launch_bounds__(256)
void ctx_kernel(const float* __restrict__ attn, const float* __restrict__ v,
                float* __restrict__ ctx)
{
    int bh = blockIdx.y;
    int b = bh / NHH, h = bh % NHH;
    int i0 = blockIdx.x * 64;
    __shared__ float Pt[64][65];  // Pt[j][i]
    __shared__ float Vs[64][65];  // Vs[j][d]
    int tid = threadIdx.x;
    int tx = tid & 15, ty = tid >> 4;
    float acc[4][4] = {};
    for (int jt = 0; jt < 8; jt++) {
        int j0 = jt * 64;
        #pragma unroll
        for (int it = 0; it < 16; it++) {
            int idx = it * 256 + tid;
            int r = idx >> 6, c = idx & 63;
            Pt[c][r] = attn[((size_t)bh * SS + i0 + r) * SS + j0 + c];
            Vs[r][c] = v[(size_t)(b * SS + j0 + r) * DD + h * HDD + c];
        }
        __syncthreads();
        for (int jj = 0; jj < 64; jj++) {
            float a[4], bb[4];
            #pragma unroll
            for (int i = 0; i < 4; i++) a[i] = Pt[jj][ty * 4 + i];
            #pragma unroll
            for (int j = 0; j < 4; j++) bb[j] = Vs[jj][tx * 4 + j];
            #pragma unroll
            for (int i = 0; i < 4; i++)
                #pragma unroll
                for (int j = 0; j < 4; j++)
                    acc[i][j] = fmaf(a[i], bb[j], acc[i][j]);
        }
        __syncthreads();
    }
    #pragma unroll
    for (int i = 0; i < 4; i++)
        #pragma unroll
        for (int j = 0; j < 4; j++)
            ctx[(size_t)(b * SS + i0 + ty * 4 + i) * DD + h * HDD + tx * 4 + j] = acc[i][j];
}

// ---------------- launcher ----------------
extern "C" void kernel_launch(void* const* d_in, const int* in_sizes, int n_in,
                              void* d_out, int out_size)
{
    const int*   ids  = (const int*)d_in[0];
    const int*   tts  = (const int*)d_in[1];
    const float* we   = (const float*)d_in[2];
    const float* pe   = (const float*)d_in[3];
    const float* te   = (const float*)d_in[4];
    const float* lnew = (const float*)d_in[5];
    const float* lneb = (const float*)d_in[6];
    const float* Wq   = (const float*)d_in[7];
    const float* bq   = (const float*)d_in[8];
    const float* Wk   = (const float*)d_in[9];
    const float* bk   = (const float*)d_in[10];
    const float* Wv   = (const float*)d_in[11];
    const float* bv   = (const float*)d_in[12];
    const float* Lm   = (const float*)d_in[13];
    const float* dg   = (const float*)d_in[14];
    const float* Wcp  = (const float*)d_in[15];
    const float* bcp  = (const float*)d_in[16];
    const float* Wi   = (const float*)d_in[17];
    const float* bi   = (const float*)d_in[18];
    const float* Wo   = (const float*)d_in[19];
    const float* bo   = (const float*)d_in[20];
    const float* l1w  = (const float*)d_in[21];
    const float* l1b  = (const float*)d_in[22];
    const float* l2w  = (const float*)d_in[23];
    const float* l2b  = (const float*)d_in[24];

    float *h, *q, *k, *v, *qg, *attn, *ctx, *a, *f, *o, *hmean, *cw, *ginv;
    cudaGetSymbolAddress((void**)&h,     g_h);
    cudaGetSymbolAddress((void**)&q,     g_q);
    cudaGetSymbolAddress((void**)&k,     g_k);
    cudaGetSymbolAddress((void**)&v,     g_v);
    cudaGetSymbolAddress((void**)&qg,    g_qg);
    cudaGetSymbolAddress((void**)&attn,  g_attn);
    cudaGetSymbolAddress((void**)&ctx,   g_ctx);
    cudaGetSymbolAddress((void**)&a,     g_a);
    cudaGetSymbolAddress((void**)&f,     g_f);
    cudaGetSymbolAddress((void**)&o,     g_o);
    cudaGetSymbolAddress((void**)&hmean, g_hmean);
    cudaGetSymbolAddress((void**)&cw,    g_cw);
    cudaGetSymbolAddress((void**)&ginv,  g_ginv);

    embed_ln_kernel<<<MT, 256>>>(ids, tts, we, pe, te, lnew, lneb, h);

    for (int l = 0; l < NLL; l++) {
        const float* Wq_l  = Wq  + (size_t)l * DD * DD;
        const float* Wk_l  = Wk  + (size_t)l * DD * DD;
        const float* Wv_l  = Wv  + (size_t)l * DD * DD;
        const float* Wcp_l = Wcp + (size_t)l * DD * DD;
        const float* Wi_l  = Wi  + (size_t)l * DD * FFF;
        const float* Wo_l  = Wo  + (size_t)l * FFF * DD;
        const float* Lm_l  = Lm  + (size_t)l * DD * 64;
        const float* dg_l  = dg  + (size_t)l * DD;
        const float* bq_l  = bq  + (size_t)l * DD;
        const float* bk_l  = bk  + (size_t)l * DD;
        const float* bv_l  = bv  + (size_t)l * DD;
        const float* bcp_l = bcp + (size_t)l * DD;
        const float* bi_l  = bi  + (size_t)l * FFF;
        const float* bo_l  = bo  + (size_t)l * DD;
        const float* l1w_l = l1w + (size_t)l * DD;
        const float* l1b_l = l1b + (size_t)l * DD;
        const float* l2w_l = l2w + (size_t)l * DD;
        const float* l2b_l = l2b + (size_t)l * DD;

        // QKV projections
        sgemm_kernel<<<dim3(DD / 128, MT / 128), 256>>>(h, Wq_l, bq_l, q, MT, DD, DD, 0);
        sgemm_kernel<<<dim3(DD / 128, MT / 128), 256>>>(h, Wk_l, bk_l, k, MT, DD, DD, 0);
        sgemm_kernel<<<dim3(DD / 128, MT / 128), 256>>>(h, Wv_l, bv_l, v, MT, DD, DD, 0);

        // metric tensor path
        pool_kernel<<<BB, DD>>>(h, hmean);
        cw_kernel<<<BB, HDD>>>(hmean, Wcp_l, bcp_l, cw);
        ginv_kernel<<<BB, 256>>>(Lm_l, dg_l, cw, ginv);

        // attention
        qg_kernel<<<dim3(MT / 64, NHH), 256>>>(q, ginv, qg);
        scores_kernel<<<dim3(SS / 64, SS / 64, BB * NHH), 256>>>(qg, k, attn);
        softmax_kernel<<<BB * NHH * SS, 256>>>(attn);
        ctx_kernel<<<dim3(SS / 64, BB * NHH), 256>>>(attn, v, ctx);

        add_ln_kernel<<<MT, 256>>>(ctx, h, l1w_l, l1b_l, a);

        // FFN
        sgemm_kernel<<<dim3(FFF / 128, MT / 128), 256>>>(a, Wi_l, bi_l, f, MT, FFF, DD, 1);
        sgemm_kernel<<<dim3(DD / 128, MT / 128), 256>>>(f, Wo_l, bo_l, o, MT, DD, FFF, 0);

        float* out_h = (l == NLL - 1) ? (float*)d_out : h;
        add_ln_kernel<<<MT, 256>>>(o, a, l2w_l, l2b_l, out_h);
    }
}

// round 4
// speedup vs baseline: 1.4799x; 1.4799x over previous
#include <cuda_runtime.h>
#include <cuda_bf16.h>
#include <stdint.h>
#include <math.h>

#define BB  8
#define SS  512
#define DD  768
#define NHH 12
#define HDD 64
#define FFF 3072
#define NLL 12
#define MT  (BB*SS)   // 4096 tokens

// ---------------- scratch (static device globals; no allocation) ----------------
__device__ float g_h[MT*DD];
__device__ float g_q[MT*DD];
__device__ float g_k[MT*DD];
__device__ float g_v[MT*DD];
__device__ float g_qg[MT*DD];
__device__ float g_attn[(size_t)BB*NHH*SS*SS];   // 100 MB
__device__ float g_ctx[MT*DD];
__device__ float g_a[MT*DD];
__device__ float g_f[MT*FFF];
__device__ float g_o[MT*DD];
__device__ float g_hmean[BB*DD];
__device__ float g_cw[BB*HDD];
__device__ float g_ginv[BB*HDD*HDD];

// ---------------- embedding gather + LayerNorm ----------------
__global__ __launch_bounds__(256)
void embed_ln_kernel(const int* __restrict__ ids, const int* __restrict__ tts,
                     const float* __restrict__ we, const float* __restrict__ pe,
                     const float* __restrict__ te,
                     const float* __restrict__ w, const float* __restrict__ bb,
                     float* __restrict__ out)
{
    int t = blockIdx.x;
    int s = t % SS;
    int tid = threadIdx.x;
    int id = ids[t], tt = tts[t];
    const float* wr = we + (size_t)id * DD;
    const float* pr = pe + (size_t)s  * DD;
    const float* tr = te + (size_t)tt * DD;
    __shared__ float red[256];
    float v[3];
    float sum = 0.f;
    #pragma unroll
    for (int i = 0; i < 3; i++) {
        int d = tid + i * 256;
        v[i] = wr[d] + pr[d] + tr[d];
        sum += v[i];
    }
    red[tid] = sum; __syncthreads();
    for (int o = 128; o > 0; o >>= 1) { if (tid < o) red[tid] += red[tid + o]; __syncthreads(); }
    float mean = red[0] * (1.0f / DD);
    __syncthreads();
    float vs = 0.f;
    #pragma unroll
    for (int i = 0; i < 3; i++) { float d0 = v[i] - mean; vs += d0 * d0; }
    red[tid] = vs; __syncthreads();
    for (int o = 128; o > 0; o >>= 1) { if (tid < o) red[tid] += red[tid + o]; __syncthreads(); }
    float var = red[0] * (1.0f / DD);
    float rstd = rsqrtf(var + 1e-12f);
    size_t base = (size_t)t * DD;
    #pragma unroll
    for (int i = 0; i < 3; i++) {
        int d = tid + i * 256;
        out[base + d] = (v[i] - mean) * rstd * w[d] + bb[d];
    }
}

// ---------------- out = LayerNorm(x + y) * w + b ----------------
__global__ __launch_bounds__(256)
void add_ln_kernel(const float* __restrict__ x, const float* __restrict__ y,
                   const float* __restrict__ w, const float* __restrict__ bb,
                   float* __restrict__ out)
{
    int t = blockIdx.x;
    int tid = threadIdx.x;
    __shared__ float red[256];
    size_t base = (size_t)t * DD;
    float v[3];
    float sum = 0.f;
    #pragma unroll
    for (int i = 0; i < 3; i++) {
        int d = tid + i * 256;
        v[i] = x[base + d] + y[base + d];
        sum += v[i];
    }
    red[tid] = sum; __syncthreads();
    for (int o = 128; o > 0; o >>= 1) { if (tid < o) red[tid] += red[tid + o]; __syncthreads(); }
    float mean = red[0] * (1.0f / DD);
    __syncthreads();
    float vs = 0.f;
    #pragma unroll
    for (int i = 0; i < 3; i++) { float d0 = v[i] - mean; vs += d0 * d0; }
    red[tid] = vs; __syncthreads();
    for (int o = 128; o > 0; o >>= 1) { if (tid < o) red[tid] += red[tid + o]; __syncthreads(); }
    float var = red[0] * (1.0f / DD);
    float rstd = rsqrtf(var + 1e-12f);
    #pragma unroll
    for (int i = 0; i < 3; i++) {
        int d = tid + i * 256;
        out[base + d] = (v[i] - mean) * rstd * w[d] + bb[d];
    }
}

// ================= bf16x3 tensor-core GEMM =================
// C[M,N] = A[M,K] @ W[K,N] + bias, optional exact GELU.
// A,W fp32 in global; split on the fly into hi/lo bf16 in smem.
// C = A0*W0 + A0*W1 + A1*W0  (fp32 accum; dropped terms ~2^-18 relative)

#define RA 40    // A smem row stride in bf16 elems (80B: 8 rows hit distinct 16B phases)
#define RB 136   // B smem row stride in bf16 elems (272B: likewise conflict-free)

__device__ __forceinline__ void ldsm_x4(uint32_t& r0, uint32_t& r1, uint32_t& r2, uint32_t& r3, uint32_t addr)
{
    asm volatile("ldmatrix.sync.aligned.m8n8.x4.shared.b16 {%0,%1,%2,%3}, [%4];\n"
                 : "=r"(r0), "=r"(r1), "=r"(r2), "=r"(r3) : "r"(addr));
}
__device__ __forceinline__ void ldsm_x4_t(uint32_t& r0, uint32_t& r1, uint32_t& r2, uint32_t& r3, uint32_t addr)
{
    asm volatile("ldmatrix.sync.aligned.m8n8.x4.trans.shared.b16 {%0,%1,%2,%3}, [%4];\n"
                 : "=r"(r0), "=r"(r1), "=r"(r2), "=r"(r3) : "r"(addr));
}
__device__ __forceinline__ void mma_bf16(float* c, const uint32_t* a, const uint32_t* b)
{
    asm volatile("mma.sync.aligned.m16n8k16.row.col.f32.bf16.bf16.f32 "
                 "{%0,%1,%2,%3}, {%4,%5,%6,%7}, {%8,%9}, {%0,%1,%2,%3};\n"
                 : "+f"(c[0]), "+f"(c[1]), "+f"(c[2]), "+f"(c[3])
                 : "r"(a[0]), "r"(a[1]), "r"(a[2]), "r"(a[3]), "r"(b[0]), "r"(b[1]));
}

__device__ __forceinline__ void split4(const float4 v, __nv_bfloat16* S0, __nv_bfloat16* S1, int o)
{
    __nv_bfloat16 h0 = __float2bfloat16(v.x);
    __nv_bfloat16 h1 = __float2bfloat16(v.y);
    __nv_bfloat16 h2 = __float2bfloat16(v.z);
    __nv_bfloat16 h3 = __float2bfloat16(v.w);
    S0[o + 0] = h0; S0[o + 1] = h1; S0[o + 2] = h2; S0[o + 3] = h3;
    S1[o + 0] = __float2bfloat16(v.x - __bfloat162float(h0));
    S1[o + 1] = __float2bfloat16(v.y - __bfloat162float(h1));
    S1[o + 2] = __float2bfloat16(v.z - __bfloat162float(h2));
    S1[o + 3] = __float2bfloat16(v.w - __bfloat162float(h3));
}

__global__ __launch_bounds__(512, 1)
void gemm3_kernel(const float* __restrict__ A, const float* __restrict__ W,
                  const float* __restrict__ bias, float* __restrict__ C,
                  int M, int N, int K, int act)
{
    __shared__ __nv_bfloat16 As0[128 * RA];
    __shared__ __nv_bfloat16 As1[128 * RA];
    __shared__ __nv_bfloat16 Bs0[32 * RB];
    __shared__ __nv_bfloat16 Bs1[32 * RB];

    const int tid  = threadIdx.x;
    const int warp = tid >> 5;
    const int lane = tid & 31;
    const int wm = (warp & 3) * 32;   // warp m offset in tile
    const int wn = (warp >> 2) * 32;  // warp n offset in tile
    const int bm = blockIdx.y * 128;
    const int bn = blockIdx.x * 128;

    // global load assignment: A tile 128x32 fp32, B tile 32x128 fp32
    const int ar = tid >> 2;          // 0..127
    const int ac = (tid & 3) * 8;     // 0,8,16,24
    const int br = tid >> 4;          // 0..31
    const int bc = (tid & 15) * 8;    // 0..120

    const float* Ag = A + (size_t)(bm + ar) * K + ac;
    const float* Wg = W + (size_t)br * N + bn + bc;

    float4 pa0 = *(const float4*)(Ag);
    float4 pa1 = *(const float4*)(Ag + 4);
    float4 pb0 = *(const float4*)(Wg);
    float4 pb1 = *(const float4*)(Wg + 4);

    float acc[2][4][4];
    #pragma unroll
    for (int i = 0; i < 2; i++)
        #pragma unroll
        for (int j = 0; j < 4; j++)
            #pragma unroll
            for (int e = 0; e < 4; e++) acc[i][j][e] = 0.f;

    const uint32_t as0 = (uint32_t)__cvta_generic_to_shared(As0);
    const uint32_t as1 = (uint32_t)__cvta_generic_to_shared(As1);
    const uint32_t bs0 = (uint32_t)__cvta_generic_to_shared(Bs0);
    const uint32_t bs1 = (uint32_t)__cvta_generic_to_shared(Bs1);

    const int KT = K >> 5;
    for (int t = 0; t < KT; t++) {
        // stage prefetched fp32 into split bf16 smem
        {
            int oa = ar * RA + ac;
            split4(pa0, As0, As1, oa);
            split4(pa1, As0, As1, oa + 4);
            int ob = br * RB + bc;
            split4(pb0, Bs0, Bs1, ob);
            split4(pb1, Bs0, Bs1, ob + 4);
        }
        __syncthreads();
        if (t + 1 < KT) {
            Ag += 32;
            Wg += (size_t)32 * N;
            pa0 = *(const float4*)(Ag);
            pa1 = *(const float4*)(Ag + 4);
            pb0 = *(const float4*)(Wg);
            pb1 = *(const float4*)(Wg + 4);
        }
        #pragma unroll
        for (int ks = 0; ks < 2; ks++) {
            // A fragments: [term][mtile 0..1][4 regs]
            uint32_t af[2][2][4];
            #pragma unroll
            for (int i = 0; i < 2; i++) {
                uint32_t off = (uint32_t)(((wm + i * 16 + (lane & 15)) * RA + ks * 16 + ((lane >> 4) << 3)) * 2);
                ldsm_x4(af[0][i][0], af[0][i][1], af[0][i][2], af[0][i][3], as0 + off);
                ldsm_x4(af[1][i][0], af[1][i][1], af[1][i][2], af[1][i][3], as1 + off);
            }
            // B fragments: [term][ntile 0..3][2 regs]
            uint32_t bf[2][4][2];
            #pragma unroll
            for (int j = 0; j < 2; j++) {
                uint32_t off = (uint32_t)(((ks * 16 + (lane & 15)) * RB + wn + j * 16 + ((lane >> 4) << 3)) * 2);
                uint32_t r0, r1, r2, r3;
                ldsm_x4_t(r0, r1, r2, r3, bs0 + off);
                bf[0][j * 2 + 0][0] = r0; bf[0][j * 2 + 0][1] = r1;
                bf[0][j * 2 + 1][0] = r2; bf[0][j * 2 + 1][1] = r3;
                ldsm_x4_t(r0, r1, r2, r3, bs1 + off);
                bf[1][j * 2 + 0][0] = r0; bf[1][j * 2 + 0][1] = r1;
                bf[1][j * 2 + 1][0] = r2; bf[1][j * 2 + 1][1] = r3;
            }
            #pragma unroll
            for (int i = 0; i < 2; i++)
                #pragma unroll
                for (int j = 0; j < 4; j++) {
                    mma_bf16(acc[i][j], af[0][i], bf[0][j]);  // A0*B0
                    mma_bf16(acc[i][j], af[0][i], bf[1][j]);  // A0*B1
                    mma_bf16(acc[i][j], af[1][i], bf[0][j]);  // A1*B0
                }
        }
        __syncthreads();
    }

    // epilogue
    #pragma unroll
    for (int i = 0; i < 2; i++) {
        int r0 = bm + wm + i * 16 + (lane >> 2);
        #pragma unroll
        for (int j = 0; j < 4; j++) {
            int c0 = bn + wn + j * 8 + (lane & 3) * 2;
            float b0 = bias[c0], b1 = bias[c0 + 1];
            float v0 = acc[i][j][0] + b0;
            float v1 = acc[i][j][1] + b1;
            float v2 = acc[i][j][2] + b0;
            float v3 = acc[i][j][3] + b1;
            if (act == 1) {
                v0 = 0.5f * v0 * (1.f + erff(v0 * 0.70710678118654752f));
                v1 = 0.5f * v1 * (1.f + erff(v1 * 0.70710678118654752f));
                v2 = 0.5f * v2 * (1.f + erff(v2 * 0.70710678118654752f));
                v3 = 0.5f * v3 * (1.f + erff(v3 * 0.70710678118654752f));
            }
            *(float2*)&C[(size_t)r0 * N + c0]       = make_float2(v0, v1);
            *(float2*)&C[(size_t)(r0 + 8) * N + c0] = make_float2(v2, v3);
        }
    }
}

// ---------------- per-batch mean over sequence ----------------
__global__ void pool_kernel(const float* __restrict__ h, float* __restrict__ hmean)
{
    int b = blockIdx.x;
    int d = threadIdx.x;
    float s = 0.f;
    for (int t = 0; t < SS; t++) s += h[((size_t)b * SS + t) * DD + d];
    hmean[b * DD + d] = s * (1.0f / SS);
}

// ---------------- cw = sigmoid((hmean @ Wcp + bcp)[:64]) ----------------
__global__ void cw_kernel(const float* __restrict__ hmean, const float* __restrict__ Wcp,
                          const float* __restrict__ bcp, float* __restrict__ cw)
{
    int b = blockIdx.x;
    int j = threadIdx.x; // 0..63
    float acc = bcp[j];
    const float* hm = hmean + b * DD;
    for (int d = 0; d < DD; d++) acc = fmaf(hm[d], Wcp[(size_t)d * DD + j], acc);
    cw[b * HDD + j] = 1.f / (1.f + expf(-acc));
}

// ---------------- metric build + 64x64 inverse (Gauss-Jordan, SPD dominant) ----------------
__global__ __launch_bounds__(256)
void ginv_kernel(const float* __restrict__ Lm_l, const float* __restrict__ diag_l,
                 const float* __restrict__ cw, float* __restrict__ ginv)
{
    int b = blockIdx.x, tid = threadIdx.x;
    __shared__ float L[64][64];   // first l_mod, later the right (inverse) half
    __shared__ float A[64][65];   // metric (left half)
    __shared__ float fcol[64];

    for (int it = 0; it < 16; it++) {
        int idx = it * 256 + tid; int i = idx >> 6, j = idx & 63;
        L[i][j] = Lm_l[i * 64 + j] * cw[b * HDD + i];
    }
    __syncthreads();
    for (int it = 0; it < 16; it++) {
        int idx = it * 256 + tid; int i = idx >> 6, j = idx & 63;
        float s = 0.f;
        for (int t2 = 0; t2 < 64; t2++) s = fmaf(L[i][t2], L[j][t2], s);
        if (i == j) s += diag_l[i] + 1e-6f + 0.1f;
        A[i][j] = s;
    }
    __syncthreads();
    for (int it = 0; it < 16; it++) {
        int idx = it * 256 + tid; int i = idx >> 6, j = idx & 63;
        L[i][j] = (i == j) ? 1.f : 0.f;
    }
    __syncthreads();

    for (int p = 0; p < 64; p++) {
        float ip = 1.f / A[p][p];
        float myf = (tid < 64) ? A[tid][p] : 0.f;
        __syncthreads();
        if (tid < 64)        A[p][tid]       *= ip;
        else if (tid < 128)  L[p][tid - 64]  *= ip;
        if (tid < 64) fcol[tid] = (tid == p) ? 0.f : myf;
        __syncthreads();
        for (int it = 0; it < 32; it++) {
            int idx = it * 256 + tid;
            int r = idx >> 7, c = idx & 127;
            if (r != p) {
                if (c < 64) A[r][c]      -= fcol[r] * A[p][c];
                else        L[r][c - 64] -= fcol[r] * L[p][c - 64];
            }
        }
        __syncthreads();
    }
    for (int it = 0; it < 16; it++) {
        int idx = it * 256 + tid;
        ginv[b * (HDD * HDD) + idx] = L[idx >> 6][idx & 63];
    }
}

// ---------------- qg = q @ g_inv (per batch, shared across heads) ----------------
__global__ __launch_bounds__(256)
void qg_kernel(const float* __restrict__ q, const float* __restrict__ ginv,
               float* __restrict__ qg)
{
    int m0 = blockIdx.x * 64;
    int h  = blockIdx.y;
    int b  = m0 / SS;
    __shared__ float Qt[64][65];   // Qt[d][i]
    __shared__ float G[64][65];    // G[d][e]
    int tid = threadIdx.x;
    const float* gb = ginv + b * (HDD * HDD);
    #pragma unroll
    for (int it = 0; it < 16; it++) {
        int idx = it * 256 + tid;
        int r = idx >> 6, c = idx & 63;
        Qt[c][r] = q[(size_t)(m0 + r) * DD + h * HDD + c];
        G[r][c]  = gb[idx];
    }
    __syncthreads();
    int tx = tid & 15, ty = tid >> 4;
    float acc[4][4] = {};
    for (int d = 0; d < 64; d++) {
        float a[4], bb[4];
        #pragma unroll
        for (int i = 0; i < 4; i++) a[i] = Qt[d][ty * 4 + i];
        #pragma unroll
        for (int j = 0; j < 4; j++) bb[j] = G[d][tx * 4 + j];
        #pragma unroll
        for (int i = 0; i < 4; i++)
            #pragma unroll
            for (int j = 0; j < 4; j++)
                acc[i][j] = fmaf(a[i], bb[j], acc[i][j]);
    }
    #pragma unroll
    for (int i = 0; i < 4; i++)
        #pragma unroll
        for (int j = 0; j < 4; j++)
            qg[(size_t)(m0 + ty * 4 + i) * DD + h * HDD + tx * 4 + j] = acc[i][j];
}

// ---------------- scores = qg @ k^T / 8 ----------------
__global__ __launch_bounds__(256)
void scores_kernel(const float* __restrict__ qg, const float* __restrict__ k,
                   float* __restrict__ sc)
{
    int bh = blockIdx.z;
    int b = bh / NHH, h = bh % NHH;
    int i0 = blockIdx.y * 64, j0 = blockIdx.x * 64;
    __shared__ float Qt[64][65];   // Qt[d][i]
    __shared__ float Kt[64][65];   // Kt[d][j]
    int tid = threadIdx.x;
    #pragma unroll
    for (int it = 0; it < 16; it++) {
        int idx = it * 256 + tid;
        int r = idx >> 6, c = idx & 63;
        Qt[c][r] = qg[(size_t)(b * SS + i0 + r) * DD + h * HDD + c];
        Kt[c][r] = k [(size_t)(b * SS + j0 + r) * DD + h * HDD + c];
    }
    __syncthreads();
    int tx = tid & 15, ty = tid >> 4;
    float acc[4][4] = {};
    for (int d = 0; d < 64; d++) {
        float a[4], bb[4];
        #pragma unroll
        for (int i = 0; i < 4; i++) a[i] = Qt[d][ty * 4 + i];
        #pragma unroll
        for (int j = 0; j < 4; j++) bb[j] = Kt[d][tx * 4 + j];
        #pragma unroll
        for (int i = 0; i < 4; i++)
            #pragma unroll
            for (int j = 0; j < 4; j++)
                acc[i][j] = fmaf(a[i], bb[j], acc[i][j]);
    }
    #pragma unroll
    for (int i = 0; i < 4; i++)
        #pragma unroll
        for (int j = 0; j < 4; j++)
            sc[((size_t)bh * SS + i0 + ty * 4 + i) * SS + j0 + tx * 4 + j] = acc[i][j] * 0.125f;
}

// ---------------- row softmax over 512 ----------------
__global__ __launch_bounds__(256)
void softmax_kernel(float* __restrict__ sc)
{
    size_t row = blockIdx.x;
    float* p = sc + row * SS;
    int tid = threadIdx.x;
    __shared__ float red[256];
    float v0 = p[tid], v1 = p[tid + 256];
    red[tid] = fmaxf(v0, v1); __syncthreads();
    for (int o = 128; o > 0; o >>= 1) { if (tid < o) red[tid] = fmaxf(red[tid], red[tid + o]); __syncthreads(); }
    float mx = red[0];
    __syncthreads();
    float e0 = expf(v0 - mx), e1 = expf(v1 - mx);
    red[tid] = e0 + e1; __syncthreads();
    for (int o = 128; o > 0; o >>= 1) { if (tid < o) red[tid] += red[tid + o]; __syncthreads(); }
    float inv = 1.f / red[0];
    p[tid] = e0 * inv;
    p[tid + 256] = e1 * inv;
}

// ---------------- ctx = attn @ v, written directly in [B,S,D] layout ----------------
__global__ __launch_bounds__(256)
void ctx_kernel(const float* __restrict__ attn, const float* __restrict__ v,
                float* __restrict__ ctx)
{
    int bh = blockIdx.y;
    int b = bh / NHH, h = bh % NHH;
    int i0 = blockIdx.x * 64;
    __shared__ float Pt[64][65];  // Pt[j][i]
    __shared__ float Vs[64][65];  // Vs[j][d]
    int tid = threadIdx.x;
    int tx = tid & 15, ty = tid >> 4;
    float acc[4][4] = {};
    for (int jt = 0; jt < 8; jt++) {
        int j0 = jt * 64;
        #pragma unroll
        for (int it = 0; it < 16; it++) {
            int idx = it * 256 + tid;
            int r = idx >> 6, c = idx & 63;
            Pt[c][r] = attn[((size_t)bh * SS + i0 + r) * SS + j0 + c];
            Vs[r][c] = v[(size_t)(b * SS + j0 + r) * DD + h * HDD + c];
        }
        __syncthreads();
        for (int jj = 0; jj < 64; jj++) {
            float a[4], bb[4];
            #pragma unroll
            for (int i = 0; i < 4; i++) a[i] = Pt[jj][ty * 4 + i];
            #pragma unroll
            for (int j = 0; j < 4; j++) bb[j] = Vs[jj][tx * 4 + j];
            #pragma unroll
            for (int i = 0; i < 4; i++)
                #pragma unroll
                for (int j = 0; j < 4; j++)
                    acc[i][j] = fmaf(a[i], bb[j], acc[i][j]);
        }
        __syncthreads();
    }
    #pragma unroll
    for (int i = 0; i < 4; i++)
        #pragma unroll
        for (int j = 0; j < 4; j++)
            ctx[(size_t)(b * SS + i0 + ty * 4 + i) * DD + h * HDD + tx * 4 + j] = acc[i][j];
}

// ---------------- launcher ----------------
extern "C" void kernel_launch(void* const* d_in, const int* in_sizes, int n_in,
                              void* d_out, int out_size)
{
    const int*   ids  = (const int*)d_in[0];
    const int*   tts  = (const int*)d_in[1];
    const float* we   = (const float*)d_in[2];
    const float* pe   = (const float*)d_in[3];
    const float* te   = (const float*)d_in[4];
    const float* lnew = (const float*)d_in[5];
    const float* lneb = (const float*)d_in[6];
    const float* Wq   = (const float*)d_in[7];
    const float* bq   = (const float*)d_in[8];
    const float* Wk   = (const float*)d_in[9];
    const float* bk   = (const float*)d_in[10];
    const float* Wv   = (const float*)d_in[11];
    const float* bv   = (const float*)d_in[12];
    const float* Lm   = (const float*)d_in[13];
    const float* dg   = (const float*)d_in[14];
    const float* Wcp  = (const float*)d_in[15];
    const float* bcp  = (const float*)d_in[16];
    const float* Wi   = (const float*)d_in[17];
    const float* bi   = (const float*)d_in[18];
    const float* Wo   = (const float*)d_in[19];
    const float* bo   = (const float*)d_in[20];
    const float* l1w  = (const float*)d_in[21];
    const float* l1b  = (const float*)d_in[22];
    const float* l2w  = (const float*)d_in[23];
    const float* l2b  = (const float*)d_in[24];

    float *h, *q, *k, *v, *qg, *attn, *ctx, *a, *f, *o, *hmean, *cw, *ginv;
    cudaGetSymbolAddress((void**)&h,     g_h);
    cudaGetSymbolAddress((void**)&q,     g_q);
    cudaGetSymbolAddress((void**)&k,     g_k);
    cudaGetSymbolAddress((void**)&v,     g_v);
    cudaGetSymbolAddress((void**)&qg,    g_qg);
    cudaGetSymbolAddress((void**)&attn,  g_attn);
    cudaGetSymbolAddress((void**)&ctx,   g_ctx);
    cudaGetSymbolAddress((void**)&a,     g_a);
    cudaGetSymbolAddress((void**)&f,     g_f);
    cudaGetSymbolAddress((void**)&o,     g_o);
    cudaGetSymbolAddress((void**)&hmean, g_hmean);
    cudaGetSymbolAddress((void**)&cw,    g_cw);
    cudaGetSymbolAddress((void**)&ginv,  g_ginv);

    embed_ln_kernel<<<MT, 256>>>(ids, tts, we, pe, te, lnew, lneb, h);

    for (int l = 0; l < NLL; l++) {
        const float* Wq_l  = Wq  + (size_t)l * DD * DD;
        const float* Wk_l  = Wk  + (size_t)l * DD * DD;
        const float* Wv_l  = Wv  + (size_t)l * DD * DD;
        const float* Wcp_l = Wcp + (size_t)l * DD * DD;
        const float* Wi_l  = Wi  + (size_t)l * DD * FFF;
        const float* Wo_l  = Wo  + (size_t)l * FFF * DD;
        const float* Lm_l  = Lm  + (size_t)l * DD * 64;
        const float* dg_l  = dg  + (size_t)l * DD;
        const float* bq_l  = bq  + (size_t)l * DD;
        const float* bk_l  = bk  + (size_t)l * DD;
        const float* bv_l  = bv  + (size_t)l * DD;
        const float* bcp_l = bcp + (size_t)l * DD;
        const float* bi_l  = bi  + (size_t)l * FFF;
        const float* bo_l  = bo  + (size_t)l * DD;
        const float* l1w_l = l1w + (size_t)l * DD;
        const float* l1b_l = l1b + (size_t)l * DD;
        const float* l2w_l = l2w + (size_t)l * DD;
        const float* l2b_l = l2b + (size_t)l * DD;

        // QKV projections (tensor-core bf16x3)
        gemm3_kernel<<<dim3(DD / 128, MT / 128), 512>>>(h, Wq_l, bq_l, q, MT, DD, DD, 0);
        gemm3_kernel<<<dim3(DD / 128, MT / 128), 512>>>(h, Wk_l, bk_l, k, MT, DD, DD, 0);
        gemm3_kernel<<<dim3(DD / 128, MT / 128), 512>>>(h, Wv_l, bv_l, v, MT, DD, DD, 0);

        // metric tensor path
        pool_kernel<<<BB, DD>>>(h, hmean);
        cw_kernel<<<BB, HDD>>>(hmean, Wcp_l, bcp_l, cw);
        ginv_kernel<<<BB, 256>>>(Lm_l, dg_l, cw, ginv);

        // attention
        qg_kernel<<<dim3(MT / 64, NHH), 256>>>(q, ginv, qg);
        scores_kernel<<<dim3(SS / 64, SS / 64, BB * NHH), 256>>>(qg, k, attn);
        softmax_kernel<<<BB * NHH * SS, 256>>>(attn);
        ctx_kernel<<<dim3(SS / 64, BB * NHH), 256>>>(attn, v, ctx);

        add_ln_kernel<<<MT, 256>>>(ctx, h, l1w_l, l1b_l, a);

        // FFN (tensor-core bf16x3)
        gemm3_kernel<<<dim3(FFF / 128, MT / 128), 512>>>(a, Wi_l, bi_l, f, MT, FFF, DD, 1);
        gemm3_kernel<<<dim3(DD / 128, MT / 128), 512>>>(f, Wo_l, bo_l, o, MT, DD, FFF, 0);

        float* out_h = (l == NLL - 1) ? (float*)d_out : h;
        add_ln_kernel<<<MT, 256>>>(o, a, l2w_l, l2b_l, out_h);
    }
}

// round 6
// speedup vs baseline: 2.0569x; 1.3899x over previous
#include <cuda_runtime.h>
#include <cuda_bf16.h>
#include <stdint.h>
#include <math.h>

#define BB  8
#define SS  512
#define DD  768
#define NHH 12
#define HDD 64
#define FFF 3072
#define NLL 12
#define MT  (BB*SS)   // 4096 tokens

// ---------------- scratch (static device globals; no allocation) ----------------
__device__ float g_h[MT*DD];
__device__ float g_q[MT*DD];
__device__ float g_k[MT*DD];
__device__ float g_v[MT*DD];
__device__ float g_qg[MT*DD];
__device__ float g_attn[(size_t)BB*NHH*SS*SS];   // 100 MB
__device__ float g_ctx[MT*DD];
__device__ float g_a[MT*DD];
__device__ float g_f[MT*FFF];
__device__ float g_o[MT*DD];
__device__ float g_hmean[BB*DD];
__device__ float g_cw[BB*HDD];
__device__ float g_ginv[BB*HDD*HDD];

// ---------------- mma helpers ----------------
__device__ __forceinline__ void ldsm_x4(uint32_t& r0, uint32_t& r1, uint32_t& r2, uint32_t& r3, uint32_t addr)
{
    asm volatile("ldmatrix.sync.aligned.m8n8.x4.shared.b16 {%0,%1,%2,%3}, [%4];\n"
                 : "=r"(r0), "=r"(r1), "=r"(r2), "=r"(r3) : "r"(addr));
}
__device__ __forceinline__ void ldsm_x4_t(uint32_t& r0, uint32_t& r1, uint32_t& r2, uint32_t& r3, uint32_t addr)
{
    asm volatile("ldmatrix.sync.aligned.m8n8.x4.trans.shared.b16 {%0,%1,%2,%3}, [%4];\n"
                 : "=r"(r0), "=r"(r1), "=r"(r2), "=r"(r3) : "r"(addr));
}
__device__ __forceinline__ void mma_bf16(float* c, const uint32_t* a, const uint32_t* b)
{
    asm volatile("mma.sync.aligned.m16n8k16.row.col.f32.bf16.bf16.f32 "
                 "{%0,%1,%2,%3}, {%4,%5,%6,%7}, {%8,%9}, {%0,%1,%2,%3};\n"
                 : "+f"(c[0]), "+f"(c[1]), "+f"(c[2]), "+f"(c[3])
                 : "r"(a[0]), "r"(a[1]), "r"(a[2]), "r"(a[3]), "r"(b[0]), "r"(b[1]));
}
__device__ __forceinline__ void split4(const float4 v, __nv_bfloat16* S0, __nv_bfloat16* S1, int o)
{
    __nv_bfloat16 h0 = __float2bfloat16(v.x);
    __nv_bfloat16 h1 = __float2bfloat16(v.y);
    __nv_bfloat16 h2 = __float2bfloat16(v.z);
    __nv_bfloat16 h3 = __float2bfloat16(v.w);
    S0[o + 0] = h0; S0[o + 1] = h1; S0[o + 2] = h2; S0[o + 3] = h3;
    S1[o + 0] = __float2bfloat16(v.x - __bfloat162float(h0));
    S1[o + 1] = __float2bfloat16(v.y - __bfloat162float(h1));
    S1[o + 2] = __float2bfloat16(v.z - __bfloat162float(h2));
    S1[o + 3] = __float2bfloat16(v.w - __bfloat162float(h3));
}

// ---------------- embedding gather + LayerNorm ----------------
__global__ __launch_bounds__(256)
void embed_ln_kernel(const int* __restrict__ ids, const int* __restrict__ tts,
                     const float* __restrict__ we, const float* __restrict__ pe,
                     const float* __restrict__ te,
                     const float* __restrict__ w, const float* __restrict__ bb,
                     float* __restrict__ out)
{
    int t = blockIdx.x;
    int s = t % SS;
    int tid = threadIdx.x;
    int id = ids[t], tt = tts[t];
    const float* wr = we + (size_t)id * DD;
    const float* pr = pe + (size_t)s  * DD;
    const float* tr = te + (size_t)tt * DD;
    __shared__ float red[256];
    float v[3];
    float sum = 0.f;
    #pragma unroll
    for (int i = 0; i < 3; i++) {
        int d = tid + i * 256;
        v[i] = wr[d] + pr[d] + tr[d];
        sum += v[i];
    }
    red[tid] = sum; __syncthreads();
    for (int o = 128; o > 0; o >>= 1) { if (tid < o) red[tid] += red[tid + o]; __syncthreads(); }
    float mean = red[0] * (1.0f / DD);
    __syncthreads();
    float vs = 0.f;
    #pragma unroll
    for (int i = 0; i < 3; i++) { float d0 = v[i] - mean; vs += d0 * d0; }
    red[tid] = vs; __syncthreads();
    for (int o = 128; o > 0; o >>= 1) { if (tid < o) red[tid] += red[tid + o]; __syncthreads(); }
    float var = red[0] * (1.0f / DD);
    float rstd = rsqrtf(var + 1e-12f);
    size_t base = (size_t)t * DD;
    #pragma unroll
    for (int i = 0; i < 3; i++) {
        int d = tid + i * 256;
        out[base + d] = (v[i] - mean) * rstd * w[d] + bb[d];
    }
}

// ---------------- out = LayerNorm(x + y) * w + b ----------------
__global__ __launch_bounds__(256)
void add_ln_kernel(const float* __restrict__ x, const float* __restrict__ y,
                   const float* __restrict__ w, const float* __restrict__ bb,
                   float* __restrict__ out)
{
    int t = blockIdx.x;
    int tid = threadIdx.x;
    __shared__ float red[256];
    size_t base = (size_t)t * DD;
    float v[3];
    float sum = 0.f;
    #pragma unroll
    for (int i = 0; i < 3; i++) {
        int d = tid + i * 256;
        v[i] = x[base + d] + y[base + d];
        sum += v[i];
    }
    red[tid] = sum; __syncthreads();
    for (int o = 128; o > 0; o >>= 1) { if (tid < o) red[tid] += red[tid + o]; __syncthreads(); }
    float mean = red[0] * (1.0f / DD);
    __syncthreads();
    float vs = 0.f;
    #pragma unroll
    for (int i = 0; i < 3; i++) { float d0 = v[i] - mean; vs += d0 * d0; }
    red[tid] = vs; __syncthreads();
    for (int o = 128; o > 0; o >>= 1) { if (tid < o) red[tid] += red[tid + o]; __syncthreads(); }
    float var = red[0] * (1.0f / DD);
    float rstd = rsqrtf(var + 1e-12f);
    #pragma unroll
    for (int i = 0; i < 3; i++) {
        int d = tid + i * 256;
        out[base + d] = (v[i] - mean) * rstd * w[d] + bb[d];
    }
}

// ================= bf16x3 tensor-core GEMM, double-buffered =================
#define RA 40    // A smem row stride in bf16 elems
#define RB 136   // B smem row stride in bf16 elems
#define ASZ (128*RA)               // 5120 elems per term
#define BSZ (32*RB)                // 4352 elems per term
#define STAGE_ELEMS (2*ASZ + 2*BSZ)    // 18944 elems
#define STAGE_BYTES (STAGE_ELEMS*2)    // 37888 B
#define GEMM_SMEM   (2*STAGE_BYTES)    // 75776 B

__global__ __launch_bounds__(512, 1)
void gemm3_kernel(const float* __restrict__ A, const float* __restrict__ W,
                  const float* __restrict__ bias, float* __restrict__ C,
                  int M, int N, int K, int act)
{
    extern __shared__ char dynsmem[];

    const int tid  = threadIdx.x;
    const int warp = tid >> 5;
    const int lane = tid & 31;
    const int wm = (warp & 3) * 32;
    const int wn = (warp >> 2) * 32;
    const int bm = blockIdx.y * 128;
    const int bn = blockIdx.x * 128;

    const int ar = tid >> 2;          // 0..127
    const int ac = (tid & 3) * 8;     // 0,8,16,24
    const int br = tid >> 4;          // 0..31
    const int bc = (tid & 15) * 8;    // 0..120

    const float* Ag = A + (size_t)(bm + ar) * K + ac;
    const float* Wg = W + (size_t)br * N + bn + bc;

    float4 pa0 = *(const float4*)(Ag);
    float4 pa1 = *(const float4*)(Ag + 4);
    float4 pb0 = *(const float4*)(Wg);
    float4 pb1 = *(const float4*)(Wg + 4);

    float acc[2][4][4];
    #pragma unroll
    for (int i = 0; i < 2; i++)
        #pragma unroll
        for (int j = 0; j < 4; j++)
            #pragma unroll
            for (int e = 0; e < 4; e++) acc[i][j][e] = 0.f;

    const uint32_t sb = (uint32_t)__cvta_generic_to_shared(dynsmem);
    const int oa = ar * RA + ac;
    const int ob = br * RB + bc;

    // split prefetched regs into stage st
    #define STAGE_SPLIT(st) do { \
        __nv_bfloat16* A0 = (__nv_bfloat16*)(dynsmem + (st) * STAGE_BYTES); \
        __nv_bfloat16* A1 = A0 + ASZ; \
        __nv_bfloat16* B0 = A0 + 2*ASZ; \
        __nv_bfloat16* B1 = A0 + 2*ASZ + BSZ; \
        split4(pa0, A0, A1, oa); \
        split4(pa1, A0, A1, oa + 4); \
        split4(pb0, B0, B1, ob); \
        split4(pb1, B0, B1, ob + 4); \
    } while (0)

    const int KT = K >> 5;
    STAGE_SPLIT(0);
    __syncthreads();

    for (int t = 0; t < KT; t++) {
        if (t + 1 < KT) {
            Ag += 32;
            Wg += (size_t)32 * N;
            pa0 = *(const float4*)(Ag);
            pa1 = *(const float4*)(Ag + 4);
            pb0 = *(const float4*)(Wg);
            pb1 = *(const float4*)(Wg + 4);
        }
        const uint32_t base = sb + (uint32_t)(t & 1) * STAGE_BYTES;
        const uint32_t as0 = base;
        const uint32_t as1 = base + ASZ * 2;
        const uint32_t bs0 = base + 2 * ASZ * 2;
        const uint32_t bs1 = base + (2 * ASZ + BSZ) * 2;

        #pragma unroll
        for (int ks = 0; ks < 2; ks++) {
            uint32_t af[2][2][4];
            #pragma unroll
            for (int i = 0; i < 2; i++) {
                uint32_t off = (uint32_t)(((wm + i * 16 + (lane & 15)) * RA + ks * 16 + ((lane >> 4) << 3)) * 2);
                ldsm_x4(af[0][i][0], af[0][i][1], af[0][i][2], af[0][i][3], as0 + off);
                ldsm_x4(af[1][i][0], af[1][i][1], af[1][i][2], af[1][i][3], as1 + off);
            }
            uint32_t bf[2][4][2];
            #pragma unroll
            for (int j = 0; j < 2; j++) {
                uint32_t off = (uint32_t)(((ks * 16 + (lane & 15)) * RB + wn + j * 16 + ((lane >> 4) << 3)) * 2);
                uint32_t r0, r1, r2, r3;
                ldsm_x4_t(r0, r1, r2, r3, bs0 + off);
                bf[0][j * 2 + 0][0] = r0; bf[0][j * 2 + 0][1] = r1;
                bf[0][j * 2 + 1][0] = r2; bf[0][j * 2 + 1][1] = r3;
                ldsm_x4_t(r0, r1, r2, r3, bs1 + off);
                bf[1][j * 2 + 0][0] = r0; bf[1][j * 2 + 0][1] = r1;
                bf[1][j * 2 + 1][0] = r2; bf[1][j * 2 + 1][1] = r3;
            }
            #pragma unroll
            for (int i = 0; i < 2; i++)
                #pragma unroll
                for (int j = 0; j < 4; j++) {
                    mma_bf16(acc[i][j], af[0][i], bf[0][j]);
                    mma_bf16(acc[i][j], af[0][i], bf[1][j]);
                    mma_bf16(acc[i][j], af[1][i], bf[0][j]);
                }
        }
        if (t + 1 < KT) STAGE_SPLIT((t + 1) & 1);
        __syncthreads();
    }

    #pragma unroll
    for (int i = 0; i < 2; i++) {
        int r0 = bm + wm + i * 16 + (lane >> 2);
        #pragma unroll
        for (int j = 0; j < 4; j++) {
            int c0 = bn + wn + j * 8 + (lane & 3) * 2;
            float b0 = bias[c0], b1 = bias[c0 + 1];
            float v0 = acc[i][j][0] + b0;
            float v1 = acc[i][j][1] + b1;
            float v2 = acc[i][j][2] + b0;
            float v3 = acc[i][j][3] + b1;
            if (act == 1) {
                v0 = 0.5f * v0 * (1.f + erff(v0 * 0.70710678118654752f));
                v1 = 0.5f * v1 * (1.f + erff(v1 * 0.70710678118654752f));
                v2 = 0.5f * v2 * (1.f + erff(v2 * 0.70710678118654752f));
                v3 = 0.5f * v3 * (1.f + erff(v3 * 0.70710678118654752f));
            }
            *(float2*)&C[(size_t)r0 * N + c0]       = make_float2(v0, v1);
            *(float2*)&C[(size_t)(r0 + 8) * N + c0] = make_float2(v2, v3);
        }
    }
    #undef STAGE_SPLIT
}

// ---------------- per-batch mean over sequence ----------------
__global__ void pool_kernel(const float* __restrict__ h, float* __restrict__ hmean)
{
    int b = blockIdx.x;
    int d = threadIdx.x;
    float s = 0.f;
    for (int t = 0; t < SS; t++) s += h[((size_t)b * SS + t) * DD + d];
    hmean[b * DD + d] = s * (1.0f / SS);
}

// ---------------- cw = sigmoid((hmean @ Wcp + bcp)[:64]) ----------------
__global__ void cw_kernel(const float* __restrict__ hmean, const float* __restrict__ Wcp,
                          const float* __restrict__ bcp, float* __restrict__ cw)
{
    int b = blockIdx.x;
    int j = threadIdx.x; // 0..63
    float acc = bcp[j];
    const float* hm = hmean + b * DD;
    for (int d = 0; d < DD; d++) acc = fmaf(hm[d], Wcp[(size_t)d * DD + j], acc);
    cw[b * HDD + j] = 1.f / (1.f + expf(-acc));
}

// ---------------- metric build + 64x64 inverse (Gauss-Jordan) ----------------
__global__ __launch_bounds__(256)
void ginv_kernel(const float* __restrict__ Lm_l, const float* __restrict__ diag_l,
                 const float* __restrict__ cw, float* __restrict__ ginv)
{
    int b = blockIdx.x, tid = threadIdx.x;
    __shared__ float L[64][64];
    __shared__ float A[64][65];
    __shared__ float fcol[64];

    for (int it = 0; it < 16; it++) {
        int idx = it * 256 + tid; int i = idx >> 6, j = idx & 63;
        L[i][j] = Lm_l[i * 64 + j] * cw[b * HDD + i];
    }
    __syncthreads();
    for (int it = 0; it < 16; it++) {
        int idx = it * 256 + tid; int i = idx >> 6, j = idx & 63;
        float s = 0.f;
        for (int t2 = 0; t2 < 64; t2++) s = fmaf(L[i][t2], L[j][t2], s);
        if (i == j) s += diag_l[i] + 1e-6f + 0.1f;
        A[i][j] = s;
    }
    __syncthreads();
    for (int it = 0; it < 16; it++) {
        int idx = it * 256 + tid; int i = idx >> 6, j = idx & 63;
        L[i][j] = (i == j) ? 1.f : 0.f;
    }
    __syncthreads();

    for (int p = 0; p < 64; p++) {
        float ip = 1.f / A[p][p];
        float myf = (tid < 64) ? A[tid][p] : 0.f;
        __syncthreads();
        if (tid < 64)        A[p][tid]       *= ip;
        else if (tid < 128)  L[p][tid - 64]  *= ip;
        if (tid < 64) fcol[tid] = (tid == p) ? 0.f : myf;
        __syncthreads();
        for (int it = 0; it < 32; it++) {
            int idx = it * 256 + tid;
            int r = idx >> 7, c = idx & 127;
            if (r != p) {
                if (c < 64) A[r][c]      -= fcol[r] * A[p][c];
                else        L[r][c - 64] -= fcol[r] * L[p][c - 64];
            }
        }
        __syncthreads();
    }
    for (int it = 0; it < 16; it++) {
        int idx = it * 256 + tid;
        ginv[b * (HDD * HDD) + idx] = L[idx >> 6][idx & 63];
    }
}

// ---------------- qg = q @ g_inv ----------------
__global__ __launch_bounds__(256)
void qg_kernel(const float* __restrict__ q, const float* __restrict__ ginv,
               float* __restrict__ qg)
{
    int m0 = blockIdx.x * 64;
    int h  = blockIdx.y;
    int b  = m0 / SS;
    __shared__ float Qt[64][65];
    __shared__ float G[64][65];
    int tid = threadIdx.x;
    const float* gb = ginv + b * (HDD * HDD);
    #pragma unroll
    for (int it = 0; it < 16; it++) {
        int idx = it * 256 + tid;
        int r = idx >> 6, c = idx & 63;
        Qt[c][r] = q[(size_t)(m0 + r) * DD + h * HDD + c];
        G[r][c]  = gb[idx];
    }
    __syncthreads();
    int tx = tid & 15, ty = tid >> 4;
    float acc[4][4] = {};
    for (int d = 0; d < 64; d++) {
        float a[4], bb[4];
        #pragma unroll
        for (int i = 0; i < 4; i++) a[i] = Qt[d][ty * 4 + i];
        #pragma unroll
        for (int j = 0; j < 4; j++) bb[j] = G[d][tx * 4 + j];
        #pragma unroll
        for (int i = 0; i < 4; i++)
            #pragma unroll
            for (int j = 0; j < 4; j++)
                acc[i][j] = fmaf(a[i], bb[j], acc[i][j]);
    }
    #pragma unroll
    for (int i = 0; i < 4; i++)
        #pragma unroll
        for (int j = 0; j < 4; j++)
            qg[(size_t)(m0 + ty * 4 + i) * DD + h * HDD + tx * 4 + j] = acc[i][j];
}

// ================= attention with tensor cores =================
#define SCR 72   // smem row stride (bf16) for 64-col tiles

// scores = qg @ k^T / 8, bf16x3. grid (8 j, 8 i, 96 bh), 256 threads.
__global__ __launch_bounds__(256)
void scores_mma_kernel(const float* __restrict__ qg, const float* __restrict__ k,
                       float* __restrict__ sc)
{
    int bh = blockIdx.z;
    int b = bh / NHH, h = bh % NHH;
    int i0 = blockIdx.y * 64, j0 = blockIdx.x * 64;
    __shared__ __nv_bfloat16 Q0[64 * SCR], Q1[64 * SCR];
    __shared__ __nv_bfloat16 K0s[64 * SCR], K1s[64 * SCR];
    const int tid = threadIdx.x;
    const int warp = tid >> 5, lane = tid & 31;

    #pragma unroll
    for (int it = 0; it < 4; it++) {
        int f = it * 256 + tid;          // 0..1023 float4 index
        int row = f >> 4, col = (f & 15) * 4;
        float4 vq = *(const float4*)&qg[(size_t)(b * SS + i0 + row) * DD + h * HDD + col];
        float4 vk = *(const float4*)&k [(size_t)(b * SS + j0 + row) * DD + h * HDD + col];
        split4(vq, Q0, Q1, row * SCR + col);
        split4(vk, K0s, K1s, row * SCR + col);
    }
    __syncthreads();

    const uint32_t q0b = (uint32_t)__cvta_generic_to_shared(Q0);
    const uint32_t q1b = (uint32_t)__cvta_generic_to_shared(Q1);
    const uint32_t k0b = (uint32_t)__cvta_generic_to_shared(K0s);
    const uint32_t k1b = (uint32_t)__cvta_generic_to_shared(K1s);

    const int wm = (warp & 3) * 16;
    const int wn = (warp >> 2) * 32;
    float acc[4][4] = {};

    #pragma unroll
    for (int ks = 0; ks < 4; ks++) {
        uint32_t aoff = (uint32_t)(((wm + (lane & 15)) * SCR + ks * 16 + ((lane >> 4) << 3)) * 2);
        uint32_t a0[4], a1[4];
        ldsm_x4(a0[0], a0[1], a0[2], a0[3], q0b + aoff);
        ldsm_x4(a1[0], a1[1], a1[2], a1[3], q1b + aoff);
        uint32_t b0f[4][2], b1f[4][2];
        #pragma unroll
        for (int jt = 0; jt < 2; jt++) {
            uint32_t boff = (uint32_t)(((wn + jt * 16 + (lane & 15)) * SCR + ks * 16 + ((lane >> 4) << 3)) * 2);
            uint32_t r0, r1, r2, r3;
            ldsm_x4(r0, r1, r2, r3, k0b + boff);
            b0f[jt * 2 + 0][0] = r0; b0f[jt * 2 + 0][1] = r2;   // n rows 0-7 of this 16
            b0f[jt * 2 + 1][0] = r1; b0f[jt * 2 + 1][1] = r3;   // n rows 8-15
            ldsm_x4(r0, r1, r2, r3, k1b + boff);
            b1f[jt * 2 + 0][0] = r0; b1f[jt * 2 + 0][1] = r2;
            b1f[jt * 2 + 1][0] = r1; b1f[jt * 2 + 1][1] = r3;
        }
        #pragma unroll
        for (int n = 0; n < 4; n++) {
            mma_bf16(acc[n], a0, b0f[n]);
            mma_bf16(acc[n], a0, b1f[n]);
            mma_bf16(acc[n], a1, b0f[n]);
        }
    }

    int r0 = i0 + wm + (lane >> 2);
    #pragma unroll
    for (int n = 0; n < 4; n++) {
        int c0 = j0 + wn + n * 8 + (lane & 3) * 2;
        *(float2*)&sc[((size_t)bh * SS + r0) * SS + c0]     = make_float2(acc[n][0] * 0.125f, acc[n][1] * 0.125f);
        *(float2*)&sc[((size_t)bh * SS + r0 + 8) * SS + c0] = make_float2(acc[n][2] * 0.125f, acc[n][3] * 0.125f);
    }
}

// ---------------- warp-per-row softmax over 512 ----------------
__global__ __launch_bounds__(256)
void softmax_kernel(float* __restrict__ sc)
{
    int warp = threadIdx.x >> 5, lane = threadIdx.x & 31;
    size_t row = (size_t)blockIdx.x * 8 + warp;
    float* p = sc + row * SS;
    float4 v[4];
    float mx = -1e30f;
    #pragma unroll
    for (int i = 0; i < 4; i++) {
        v[i] = ((float4*)p)[lane + i * 32];
        mx = fmaxf(mx, fmaxf(fmaxf(v[i].x, v[i].y), fmaxf(v[i].z, v[i].w)));
    }
    #pragma unroll
    for (int o = 16; o > 0; o >>= 1) mx = fmaxf(mx, __shfl_xor_sync(0xffffffffu, mx, o));
    float sum = 0.f;
    #pragma unroll
    for (int i = 0; i < 4; i++) {
        v[i].x = expf(v[i].x - mx); v[i].y = expf(v[i].y - mx);
        v[i].z = expf(v[i].z - mx); v[i].w = expf(v[i].w - mx);
        sum += v[i].x + v[i].y + v[i].z + v[i].w;
    }
    #pragma unroll
    for (int o = 16; o > 0; o >>= 1) sum += __shfl_xor_sync(0xffffffffu, sum, o);
    float inv = 1.f / sum;
    #pragma unroll
    for (int i = 0; i < 4; i++) {
        v[i].x *= inv; v[i].y *= inv; v[i].z *= inv; v[i].w *= inv;
        ((float4*)p)[lane + i * 32] = v[i];
    }
}

// ---------------- ctx = attn @ v, bf16x3 mma. grid (8 itiles, 96 bh), 256 thr ----------------
__global__ __launch_bounds__(256)
void ctx_mma_kernel(const float* __restrict__ attn, const float* __restrict__ v,
                    float* __restrict__ ctx)
{
    int bh = blockIdx.y;
    int b = bh / NHH, h = bh % NHH;
    int i0 = blockIdx.x * 64;
    __shared__ __nv_bfloat16 P0[64 * SCR], P1[64 * SCR];
    __shared__ __nv_bfloat16 V0[64 * SCR], V1[64 * SCR];
    const int tid = threadIdx.x;
    const int warp = tid >> 5, lane = tid & 31;
    const int wm = (warp & 3) * 16;
    const int wn = (warp >> 2) * 32;

    const uint32_t p0b = (uint32_t)__cvta_generic_to_shared(P0);
    const uint32_t p1b = (uint32_t)__cvta_generic_to_shared(P1);
    const uint32_t v0b = (uint32_t)__cvta_generic_to_shared(V0);
    const uint32_t v1b = (uint32_t)__cvta_generic_to_shared(V1);

    float acc[4][4] = {};

    for (int jt8 = 0; jt8 < 8; jt8++) {
        int j0 = jt8 * 64;
        #pragma unroll
        for (int it = 0; it < 4; it++) {
            int f = it * 256 + tid;
            int row = f >> 4, col = (f & 15) * 4;
            float4 vp = *(const float4*)&attn[((size_t)bh * SS + i0 + row) * SS + j0 + col];
            float4 vv = *(const float4*)&v[(size_t)(b * SS + j0 + row) * DD + h * HDD + col];
            split4(vp, P0, P1, row * SCR + col);
            split4(vv, V0, V1, row * SCR + col);
        }
        __syncthreads();

        #pragma unroll
        for (int ks = 0; ks < 4; ks++) {
            uint32_t aoff = (uint32_t)(((wm + (lane & 15)) * SCR + ks * 16 + ((lane >> 4) << 3)) * 2);
            uint32_t a0[4], a1[4];
            ldsm_x4(a0[0], a0[1], a0[2], a0[3], p0b + aoff);
            ldsm_x4(a1[0], a1[1], a1[2], a1[3], p1b + aoff);
            uint32_t b0f[4][2], b1f[4][2];
            #pragma unroll
            for (int jt = 0; jt < 2; jt++) {
                uint32_t boff = (uint32_t)(((ks * 16 + (lane & 15)) * SCR + wn + jt * 16 + ((lane >> 4) << 3)) * 2);
                uint32_t r0, r1, r2, r3;
                ldsm_x4_t(r0, r1, r2, r3, v0b + boff);
                b0f[jt * 2 + 0][0] = r0; b0f[jt * 2 + 0][1] = r1;
                b0f[jt * 2 + 1][0] = r2; b0f[jt * 2 + 1][1] = r3;
                ldsm_x4_t(r0, r1, r2, r3, v1b + boff);
                b1f[jt * 2 + 0][0] = r0; b1f[jt * 2 + 0][1] = r1;
                b1f[jt * 2 + 1][0] = r2; b1f[jt * 2 + 1][1] = r3;
            }
            #pragma unroll
            for (int n = 0; n < 4; n++) {
                mma_bf16(acc[n], a0, b0f[n]);
                mma_bf16(acc[n], a0, b1f[n]);
                mma_bf16(acc[n], a1, b0f[n]);
            }
        }
        __syncthreads();
    }

    int r0 = i0 + wm + (lane >> 2);
    #pragma unroll
    for (int n = 0; n < 4; n++) {
        int c0 = h * HDD + wn + n * 8 + (lane & 3) * 2;
        *(float2*)&ctx[(size_t)(b * SS + r0) * DD + c0]     = make_float2(acc[n][0], acc[n][1]);
        *(float2*)&ctx[(size_t)(b * SS + r0 + 8) * DD + c0] = make_float2(acc[n][2], acc[n][3]);
    }
}

// ---------------- launcher ----------------
extern "C" void kernel_launch(void* const* d_in, const int* in_sizes, int n_in,
                              void* d_out, int out_size)
{
    const int*   ids  = (const int*)d_in[0];
    const int*   tts  = (const int*)d_in[1];
    const float* we   = (const float*)d_in[2];
    const float* pe   = (const float*)d_in[3];
    const float* te   = (const float*)d_in[4];
    const float* lnew = (const float*)d_in[5];
    const float* lneb = (const float*)d_in[6];
    const float* Wq   = (const float*)d_in[7];
    const float* bq   = (const float*)d_in[8];
    const float* Wk   = (const float*)d_in[9];
    const float* bk   = (const float*)d_in[10];
    const float* Wv   = (const float*)d_in[11];
    const float* bv   = (const float*)d_in[12];
    const float* Lm   = (const float*)d_in[13];
    const float* dg   = (const float*)d_in[14];
    const float* Wcp  = (const float*)d_in[15];
    const float* bcp  = (const float*)d_in[16];
    const float* Wi   = (const float*)d_in[17];
    const float* bi   = (const float*)d_in[18];
    const float* Wo   = (const float*)d_in[19];
    const float* bo   = (const float*)d_in[20];
    const float* l1w  = (const float*)d_in[21];
    const float* l1b  = (const float*)d_in[22];
    const float* l2w  = (const float*)d_in[23];
    const float* l2b  = (const float*)d_in[24];

    float *h, *q, *k, *v, *qg, *attn, *ctx, *a, *f, *o, *hmean, *cw, *ginv;
    cudaGetSymbolAddress((void**)&h,     g_h);
    cudaGetSymbolAddress((void**)&q,     g_q);
    cudaGetSymbolAddress((void**)&k,     g_k);
    cudaGetSymbolAddress((void**)&v,     g_v);
    cudaGetSymbolAddress((void**)&qg,    g_qg);
    cudaGetSymbolAddress((void**)&attn,  g_attn);
    cudaGetSymbolAddress((void**)&ctx,   g_ctx);
    cudaGetSymbolAddress((void**)&a,     g_a);
    cudaGetSymbolAddress((void**)&f,     g_f);
    cudaGetSymbolAddress((void**)&o,     g_o);
    cudaGetSymbolAddress((void**)&hmean, g_hmean);
    cudaGetSymbolAddress((void**)&cw,    g_cw);
    cudaGetSymbolAddress((void**)&ginv,  g_ginv);

    cudaFuncSetAttribute(gemm3_kernel, cudaFuncAttributeMaxDynamicSharedMemorySize, GEMM_SMEM);

    embed_ln_kernel<<<MT, 256>>>(ids, tts, we, pe, te, lnew, lneb, h);

    for (int l = 0; l < NLL; l++) {
        const float* Wq_l  = Wq  + (size_t)l * DD * DD;
        const float* Wk_l  = Wk  + (size_t)l * DD * DD;
        const float* Wv_l  = Wv  + (size_t)l * DD * DD;
        const float* Wcp_l = Wcp + (size_t)l * DD * DD;
        const float* Wi_l  = Wi  + (size_t)l * DD * FFF;
        const float* Wo_l  = Wo  + (size_t)l * FFF * DD;
        const float* Lm_l  = Lm  + (size_t)l * DD * 64;
        const float* dg_l  = dg  + (size_t)l * DD;
        const float* bq_l  = bq  + (size_t)l * DD;
        const float* bk_l  = bk  + (size_t)l * DD;
        const float* bv_l  = bv  + (size_t)l * DD;
        const float* bcp_l = bcp + (size_t)l * DD;
        const float* bi_l  = bi  + (size_t)l * FFF;
        const float* bo_l  = bo  + (size_t)l * DD;
        const float* l1w_l = l1w + (size_t)l * DD;
        const float* l1b_l = l1b + (size_t)l * DD;
        const float* l2w_l = l2w + (size_t)l * DD;
        const float* l2b_l = l2b + (size_t)l * DD;

        // QKV projections
        gemm3_kernel<<<dim3(DD / 128, MT / 128), 512, GEMM_SMEM>>>(h, Wq_l, bq_l, q, MT, DD, DD, 0);
        gemm3_kernel<<<dim3(DD / 128, MT / 128), 512, GEMM_SMEM>>>(h, Wk_l, bk_l, k, MT, DD, DD, 0);
        gemm3_kernel<<<dim3(DD / 128, MT / 128), 512, GEMM_SMEM>>>(h, Wv_l, bv_l, v, MT, DD, DD, 0);

        // metric tensor path
        pool_kernel<<<BB, DD>>>(h, hmean);
        cw_kernel<<<BB, HDD>>>(hmean, Wcp_l, bcp_l, cw);
        ginv_kernel<<<BB, 256>>>(Lm_l, dg_l, cw, ginv);

        // attention
        qg_kernel<<<dim3(MT / 64, NHH), 256>>>(q, ginv, qg);
        scores_mma_kernel<<<dim3(SS / 64, SS / 64, BB * NHH), 256>>>(qg, k, attn);
        softmax_kernel<<<BB * NHH * SS / 8, 256>>>(attn);
        ctx_mma_kernel<<<dim3(SS / 64, BB * NHH), 256>>>(attn, v, ctx);

        add_ln_kernel<<<MT, 256>>>(ctx, h, l1w_l, l1b_l, a);

        // FFN
        gemm3_kernel<<<dim3(FFF / 128, MT / 128), 512, GEMM_SMEM>>>(a, Wi_l, bi_l, f, MT, FFF, DD, 1);
        gemm3_kernel<<<dim3(DD / 128, MT / 128), 512, GEMM_SMEM>>>(f, Wo_l, bo_l, o, MT, DD, FFF, 0);

        float* out_h = (l == NLL - 1) ? (float*)d_out : h;
        add_ln_kernel<<<MT, 256>>>(o, a, l2w_l, l2b_l, out_h);
    }
}

// round 7
// speedup vs baseline: 2.3943x; 1.1640x over previous
#include <cuda_runtime.h>
#include <cuda_bf16.h>
#include <stdint.h>
#include <math.h>

#define BB  8
#define SS  512
#define DD  768
#define NHH 12
#define HDD 64
#define FFF 3072
#define NLL 12
#define MT  (BB*SS)   // 4096 tokens

// ---------------- scratch (static device globals; no allocation) ----------------
__device__ float g_h[MT*DD];
__device__ float g_q[MT*DD];
__device__ float g_k[MT*DD];
__device__ float g_v[MT*DD];
__device__ float g_qg[MT*DD];
__device__ float g_attn[(size_t)BB*NHH*SS*SS];   // 100 MB
__device__ float g_ctx[MT*DD];
__device__ float g_a[MT*DD];
__device__ float g_f[MT*FFF];
__device__ float g_o[MT*DD];
__device__ float g_o2[MT*DD];
__device__ float g_hmean[BB*DD];
__device__ float g_cw[BB*HDD];
__device__ float g_ginv[BB*HDD*HDD];

// ---------------- mma helpers ----------------
__device__ __forceinline__ void ldsm_x4(uint32_t& r0, uint32_t& r1, uint32_t& r2, uint32_t& r3, uint32_t addr)
{
    asm volatile("ldmatrix.sync.aligned.m8n8.x4.shared.b16 {%0,%1,%2,%3}, [%4];\n"
                 : "=r"(r0), "=r"(r1), "=r"(r2), "=r"(r3) : "r"(addr));
}
__device__ __forceinline__ void ldsm_x4_t(uint32_t& r0, uint32_t& r1, uint32_t& r2, uint32_t& r3, uint32_t addr)
{
    asm volatile("ldmatrix.sync.aligned.m8n8.x4.trans.shared.b16 {%0,%1,%2,%3}, [%4];\n"
                 : "=r"(r0), "=r"(r1), "=r"(r2), "=r"(r3) : "r"(addr));
}
__device__ __forceinline__ void mma_bf16(float* c, const uint32_t* a, const uint32_t* b)
{
    asm volatile("mma.sync.aligned.m16n8k16.row.col.f32.bf16.bf16.f32 "
                 "{%0,%1,%2,%3}, {%4,%5,%6,%7}, {%8,%9}, {%0,%1,%2,%3};\n"
                 : "+f"(c[0]), "+f"(c[1]), "+f"(c[2]), "+f"(c[3])
                 : "r"(a[0]), "r"(a[1]), "r"(a[2]), "r"(a[3]), "r"(b[0]), "r"(b[1]));
}
// packed split: hi to S0, residual to S1, 4 elems -> 2 x 4B stores each
__device__ __forceinline__ void split4(const float4 v, __nv_bfloat16* S0, __nv_bfloat16* S1, int o)
{
    __nv_bfloat162 h01 = __floats2bfloat162_rn(v.x, v.y);
    __nv_bfloat162 h23 = __floats2bfloat162_rn(v.z, v.w);
    *(__nv_bfloat162*)(S0 + o)     = h01;
    *(__nv_bfloat162*)(S0 + o + 2) = h23;
    __nv_bfloat162 l01 = __floats2bfloat162_rn(v.x - __low2float(h01), v.y - __high2float(h01));
    __nv_bfloat162 l23 = __floats2bfloat162_rn(v.z - __low2float(h23), v.w - __high2float(h23));
    *(__nv_bfloat162*)(S1 + o)     = l01;
    *(__nv_bfloat162*)(S1 + o + 2) = l23;
}

// ---------------- embedding gather + LayerNorm ----------------
__global__ __launch_bounds__(256)
void embed_ln_kernel(const int* __restrict__ ids, const int* __restrict__ tts,
                     const float* __restrict__ we, const float* __restrict__ pe,
                     const float* __restrict__ te,
                     const float* __restrict__ w, const float* __restrict__ bb,
                     float* __restrict__ out)
{
    int t = blockIdx.x;
    int s = t % SS;
    int tid = threadIdx.x;
    int id = ids[t], tt = tts[t];
    const float* wr = we + (size_t)id * DD;
    const float* pr = pe + (size_t)s  * DD;
    const float* tr = te + (size_t)tt * DD;
    __shared__ float red[256];
    float v[3];
    float sum = 0.f;
    #pragma unroll
    for (int i = 0; i < 3; i++) {
        int d = tid + i * 256;
        v[i] = wr[d] + pr[d] + tr[d];
        sum += v[i];
    }
    red[tid] = sum; __syncthreads();
    for (int o = 128; o > 0; o >>= 1) { if (tid < o) red[tid] += red[tid + o]; __syncthreads(); }
    float mean = red[0] * (1.0f / DD);
    __syncthreads();
    float vs = 0.f;
    #pragma unroll
    for (int i = 0; i < 3; i++) { float d0 = v[i] - mean; vs += d0 * d0; }
    red[tid] = vs; __syncthreads();
    for (int o = 128; o > 0; o >>= 1) { if (tid < o) red[tid] += red[tid + o]; __syncthreads(); }
    float var = red[0] * (1.0f / DD);
    float rstd = rsqrtf(var + 1e-12f);
    size_t base = (size_t)t * DD;
    #pragma unroll
    for (int i = 0; i < 3; i++) {
        int d = tid + i * 256;
        out[base + d] = (v[i] - mean) * rstd * w[d] + bb[d];
    }
}

// ---------------- out = LayerNorm(x + y) * w + b ----------------
__global__ __launch_bounds__(256)
void add_ln_kernel(const float* __restrict__ x, const float* __restrict__ y,
                   const float* __restrict__ w, const float* __restrict__ bb,
                   float* __restrict__ out)
{
    int t = blockIdx.x;
    int tid = threadIdx.x;
    __shared__ float red[256];
    size_t base = (size_t)t * DD;
    float v[3];
    float sum = 0.f;
    #pragma unroll
    for (int i = 0; i < 3; i++) {
        int d = tid + i * 256;
        v[i] = x[base + d] + y[base + d];
        sum += v[i];
    }
    red[tid] = sum; __syncthreads();
    for (int o = 128; o > 0; o >>= 1) { if (tid < o) red[tid] += red[tid + o]; __syncthreads(); }
    float mean = red[0] * (1.0f / DD);
    __syncthreads();
    float vs = 0.f;
    #pragma unroll
    for (int i = 0; i < 3; i++) { float d0 = v[i] - mean; vs += d0 * d0; }
    red[tid] = vs; __syncthreads();
    for (int o = 128; o > 0; o >>= 1) { if (tid < o) red[tid] += red[tid + o]; __syncthreads(); }
    float var = red[0] * (1.0f / DD);
    float rstd = rsqrtf(var + 1e-12f);
    #pragma unroll
    for (int i = 0; i < 3; i++) {
        int d = tid + i * 256;
        out[base + d] = (v[i] - mean) * rstd * w[d] + bb[d];
    }
}

// ---------------- out = LayerNorm(x1 + x2 + y) * w + b (split-K epilogue) ----------------
__global__ __launch_bounds__(256)
void add_ln3_kernel(const float* __restrict__ x1, const float* __restrict__ x2,
                    const float* __restrict__ y,
                    const float* __restrict__ w, const float* __restrict__ bb,
                    float* __restrict__ out)
{
    int t = blockIdx.x;
    int tid = threadIdx.x;
    __shared__ float red[256];
    size_t base = (size_t)t * DD;
    float v[3];
    float sum = 0.f;
    #pragma unroll
    for (int i = 0; i < 3; i++) {
        int d = tid + i * 256;
        v[i] = x1[base + d] + x2[base + d] + y[base + d];
        sum += v[i];
    }
    red[tid] = sum; __syncthreads();
    for (int o = 128; o > 0; o >>= 1) { if (tid < o) red[tid] += red[tid + o]; __syncthreads(); }
    float mean = red[0] * (1.0f / DD);
    __syncthreads();
    float vs = 0.f;
    #pragma unroll
    for (int i = 0; i < 3; i++) { float d0 = v[i] - mean; vs += d0 * d0; }
    red[tid] = vs; __syncthreads();
    for (int o = 128; o > 0; o >>= 1) { if (tid < o) red[tid] += red[tid + o]; __syncthreads(); }
    float var = red[0] * (1.0f / DD);
    float rstd = rsqrtf(var + 1e-12f);
    #pragma unroll
    for (int i = 0; i < 3; i++) {
        int d = tid + i * 256;
        out[base + d] = (v[i] - mean) * rstd * w[d] + bb[d];
    }
}

// ================= bf16x3 tensor-core GEMM, double-buffered =================
#define RA 40
#define RB 136
#define ASZ (128*RA)
#define BSZ (32*RB)
#define STAGE_ELEMS (2*ASZ + 2*BSZ)
#define STAGE_BYTES (STAGE_ELEMS*2)
#define GEMM_SMEM   (2*STAGE_BYTES)    // 75776 B

// core mainloop shared by all gemm variants (macro to avoid device-fn reg bloat)
#define GEMM_BODY(Aptr, Wptr, Klen, Nld)                                             \
    extern __shared__ char dynsmem[];                                                \
    const int tid  = threadIdx.x;                                                    \
    const int warp = tid >> 5;                                                       \
    const int lane = tid & 31;                                                       \
    const int wm = (warp & 3) * 32;                                                  \
    const int wn = (warp >> 2) * 32;                                                 \
    const int ar = tid >> 2;                                                         \
    const int ac = (tid & 3) * 8;                                                    \
    const int br = tid >> 4;                                                         \
    const int bc = (tid & 15) * 8;                                                   \
    const float* Ag = (Aptr) + ac;                                                   \
    const float* Wg = (Wptr) + bc;                                                   \
    float4 pa0 = *(const float4*)(Ag);                                               \
    float4 pa1 = *(const float4*)(Ag + 4);                                           \
    float4 pb0 = *(const float4*)(Wg);                                               \
    float4 pb1 = *(const float4*)(Wg + 4);                                           \
    float acc[2][4][4];                                                              \
    _Pragma("unroll") for (int i = 0; i < 2; i++)                                    \
        _Pragma("unroll") for (int j = 0; j < 4; j++)                                \
            _Pragma("unroll") for (int e = 0; e < 4; e++) acc[i][j][e] = 0.f;        \
    const uint32_t sb = (uint32_t)__cvta_generic_to_shared(dynsmem);                 \
    const int oa = ar * RA + ac;                                                     \
    const int ob = br * RB + bc;                                                     \
    const int KT = (Klen) >> 5;                                                      \
    {                                                                                \
        __nv_bfloat16* A0 = (__nv_bfloat16*)(dynsmem);                               \
        split4(pa0, A0, A0 + ASZ, oa);                                               \
        split4(pa1, A0, A0 + ASZ, oa + 4);                                           \
        split4(pb0, A0 + 2*ASZ, A0 + 2*ASZ + BSZ, ob);                               \
        split4(pb1, A0 + 2*ASZ, A0 + 2*ASZ + BSZ, ob + 4);                           \
    }                                                                                \
    __syncthreads();                                                                 \
    for (int t = 0; t < KT; t++) {                                                   \
        if (t + 1 < KT) {                                                            \
            Ag += 32;                                                                \
            Wg += (size_t)32 * (Nld);                                                \
            pa0 = *(const float4*)(Ag);                                              \
            pa1 = *(const float4*)(Ag + 4);                                          \
            pb0 = *(const float4*)(Wg);                                              \
            pb1 = *(const float4*)(Wg + 4);                                          \
        }                                                                            \
        const uint32_t base = sb + (uint32_t)(t & 1) * STAGE_BYTES;                  \
        const uint32_t as0 = base;                                                   \
        const uint32_t as1 = base + ASZ * 2;                                         \
        const uint32_t bs0 = base + 2 * ASZ * 2;                                     \
        const uint32_t bs1 = base + (2 * ASZ + BSZ) * 2;                             \
        _Pragma("unroll")                                                            \
        for (int ks = 0; ks < 2; ks++) {                                             \
            uint32_t af[2][2][4];                                                    \
            _Pragma("unroll")                                                        \
            for (int i = 0; i < 2; i++) {                                            \
                uint32_t off = (uint32_t)(((wm + i * 16 + (lane & 15)) * RA + ks * 16 + ((lane >> 4) << 3)) * 2); \
                ldsm_x4(af[0][i][0], af[0][i][1], af[0][i][2], af[0][i][3], as0 + off); \
                ldsm_x4(af[1][i][0], af[1][i][1], af[1][i][2], af[1][i][3], as1 + off); \
            }                                                                        \
            uint32_t bfr[2][4][2];                                                   \
            _Pragma("unroll")                                                        \
            for (int j = 0; j < 2; j++) {                                            \
                uint32_t off = (uint32_t)(((ks * 16 + (lane & 15)) * RB + wn + j * 16 + ((lane >> 4) << 3)) * 2); \
                uint32_t r0, r1, r2, r3;                                             \
                ldsm_x4_t(r0, r1, r2, r3, bs0 + off);                                \
                bfr[0][j * 2 + 0][0] = r0; bfr[0][j * 2 + 0][1] = r1;                \
                bfr[0][j * 2 + 1][0] = r2; bfr[0][j * 2 + 1][1] = r3;                \
                ldsm_x4_t(r0, r1, r2, r3, bs1 + off);                                \
                bfr[1][j * 2 + 0][0] = r0; bfr[1][j * 2 + 0][1] = r1;                \
                bfr[1][j * 2 + 1][0] = r2; bfr[1][j * 2 + 1][1] = r3;                \
            }                                                                        \
            _Pragma("unroll")                                                        \
            for (int i = 0; i < 2; i++)                                              \
                _Pragma("unroll")                                                    \
                for (int j = 0; j < 4; j++) {                                        \
                    mma_bf16(acc[i][j], af[0][i], bfr[0][j]);                        \
                    mma_bf16(acc[i][j], af[0][i], bfr[1][j]);                        \
                    mma_bf16(acc[i][j], af[1][i], bfr[0][j]);                        \
                }                                                                    \
        }                                                                            \
        if (t + 1 < KT) {                                                            \
            __nv_bfloat16* A0 = (__nv_bfloat16*)(dynsmem + ((t + 1) & 1) * STAGE_BYTES); \
            split4(pa0, A0, A0 + ASZ, oa);                                           \
            split4(pa1, A0, A0 + ASZ, oa + 4);                                       \
            split4(pb0, A0 + 2*ASZ, A0 + 2*ASZ + BSZ, ob);                           \
            split4(pb1, A0 + 2*ASZ, A0 + 2*ASZ + BSZ, ob + 4);                       \
        }                                                                            \
        __syncthreads();                                                             \
    }

// generic: C = A@W + bias, optional GELU
__global__ __launch_bounds__(512, 1)
void gemm3_kernel(const float* __restrict__ A, const float* __restrict__ W,
                  const float* __restrict__ bias, float* __restrict__ C,
                  int M, int N, int K, int act)
{
    const int bm = blockIdx.y * 128;
    const int bn = blockIdx.x * 128;
    GEMM_BODY(A + (size_t)(bm + (threadIdx.x >> 2)) * K,
              W + (size_t)(threadIdx.x >> 4) * N + bn, K, N)

    #pragma unroll
    for (int i = 0; i < 2; i++) {
        int r0 = bm + wm + i * 16 + (lane >> 2);
        #pragma unroll
        for (int j = 0; j < 4; j++) {
            int c0 = bn + wn + j * 8 + (lane & 3) * 2;
            float b0 = bias[c0], b1 = bias[c0 + 1];
            float v0 = acc[i][j][0] + b0;
            float v1 = acc[i][j][1] + b1;
            float v2 = acc[i][j][2] + b0;
            float v3 = acc[i][j][3] + b1;
            if (act == 1) {
                v0 = 0.5f * v0 * (1.f + erff(v0 * 0.70710678118654752f));
                v1 = 0.5f * v1 * (1.f + erff(v1 * 0.70710678118654752f));
                v2 = 0.5f * v2 * (1.f + erff(v2 * 0.70710678118654752f));
                v3 = 0.5f * v3 * (1.f + erff(v3 * 0.70710678118654752f));
            }
            *(float2*)&C[(size_t)r0 * N + c0]       = make_float2(v0, v1);
            *(float2*)&C[(size_t)(r0 + 8) * N + c0] = make_float2(v2, v3);
        }
    }
}

// fused QKV: grid.x = 18 (3 outputs x 6 ntiles), grid.y = 32
__global__ __launch_bounds__(512, 1)
void gemm3_qkv_kernel(const float* __restrict__ A,
                      const float* __restrict__ W0, const float* __restrict__ W1, const float* __restrict__ W2,
                      const float* __restrict__ bias0, const float* __restrict__ bias1, const float* __restrict__ bias2,
                      float* __restrict__ C0, float* __restrict__ C1, float* __restrict__ C2)
{
    const int nt  = blockIdx.x;
    const int sel = nt / 6;
    const int bm = blockIdx.y * 128;
    const int bn = (nt % 6) * 128;
    const float* W    = (sel == 0) ? W0 : (sel == 1) ? W1 : W2;
    const float* bias = (sel == 0) ? bias0 : (sel == 1) ? bias1 : bias2;
    float* C          = (sel == 0) ? C0 : (sel == 1) ? C1 : C2;

    GEMM_BODY(A + (size_t)(bm + (threadIdx.x >> 2)) * DD,
              W + (size_t)(threadIdx.x >> 4) * DD + bn, DD, DD)

    #pragma unroll
    for (int i = 0; i < 2; i++) {
        int r0 = bm + wm + i * 16 + (lane >> 2);
        #pragma unroll
        for (int j = 0; j < 4; j++) {
            int c0 = bn + wn + j * 8 + (lane & 3) * 2;
            float b0 = bias[c0], b1 = bias[c0 + 1];
            *(float2*)&C[(size_t)r0 * DD + c0]       = make_float2(acc[i][j][0] + b0, acc[i][j][1] + b1);
            *(float2*)&C[(size_t)(r0 + 8) * DD + c0] = make_float2(acc[i][j][2] + b0, acc[i][j][3] + b1);
        }
    }
}

// split-K (2-way) GEMM for Wo: grid.z selects K-half; z=0 -> C0 (+bias), z=1 -> C1 (raw)
__global__ __launch_bounds__(512, 1)
void gemm3_splitk_kernel(const float* __restrict__ A, const float* __restrict__ W,
                         const float* __restrict__ bias,
                         float* __restrict__ C0, float* __restrict__ C1,
                         int M, int N, int K)
{
    const int bm = blockIdx.y * 128;
    const int bn = blockIdx.x * 128;
    const int z  = blockIdx.z;
    const int KH = K >> 1;
    const int k0 = z * KH;
    float* C = z ? C1 : C0;

    GEMM_BODY(A + (size_t)(bm + (threadIdx.x >> 2)) * K + k0,
              W + (size_t)(k0 + (threadIdx.x >> 4)) * N + bn, KH, N)

    #pragma unroll
    for (int i = 0; i < 2; i++) {
        int r0 = bm + wm + i * 16 + (lane >> 2);
        #pragma unroll
        for (int j = 0; j < 4; j++) {
            int c0 = bn + wn + j * 8 + (lane & 3) * 2;
            float b0 = z ? 0.f : bias[c0];
            float b1 = z ? 0.f : bias[c0 + 1];
            *(float2*)&C[(size_t)r0 * N + c0]       = make_float2(acc[i][j][0] + b0, acc[i][j][1] + b1);
            *(float2*)&C[(size_t)(r0 + 8) * N + c0] = make_float2(acc[i][j][2] + b0, acc[i][j][3] + b1);
        }
    }
}

// ---------------- per-batch mean over sequence ----------------
__global__ void pool_kernel(const float* __restrict__ h, float* __restrict__ hmean)
{
    int b = blockIdx.x;
    int d = threadIdx.x;
    float s = 0.f;
    for (int t = 0; t < SS; t++) s += h[((size_t)b * SS + t) * DD + d];
    hmean[b * DD + d] = s * (1.0f / SS);
}

// ---------------- cw = sigmoid((hmean @ Wcp + bcp)[:64]) ----------------
__global__ void cw_kernel(const float* __restrict__ hmean, const float* __restrict__ Wcp,
                          const float* __restrict__ bcp, float* __restrict__ cw)
{
    int b = blockIdx.x;
    int j = threadIdx.x; // 0..63
    float acc = bcp[j];
    const float* hm = hmean + b * DD;
    for (int d = 0; d < DD; d++) acc = fmaf(hm[d], Wcp[(size_t)d * DD + j], acc);
    cw[b * HDD + j] = 1.f / (1.f + expf(-acc));
}

// ---------------- metric build + 64x64 inverse (Gauss-Jordan) ----------------
__global__ __launch_bounds__(256)
void ginv_kernel(const float* __restrict__ Lm_l, const float* __restrict__ diag_l,
                 const float* __restrict__ cw, float* __restrict__ ginv)
{
    int b = blockIdx.x, tid = threadIdx.x;
    __shared__ float L[64][64];
    __shared__ float A[64][65];
    __shared__ float fcol[64];

    for (int it = 0; it < 16; it++) {
        int idx = it * 256 + tid; int i = idx >> 6, j = idx & 63;
        L[i][j] = Lm_l[i * 64 + j] * cw[b * HDD + i];
    }
    __syncthreads();
    for (int it = 0; it < 16; it++) {
        int idx = it * 256 + tid; int i = idx >> 6, j = idx & 63;
        float s = 0.f;
        for (int t2 = 0; t2 < 64; t2++) s = fmaf(L[i][t2], L[j][t2], s);
        if (i == j) s += diag_l[i] + 1e-6f + 0.1f;
        A[i][j] = s;
    }
    __syncthreads();
    for (int it = 0; it < 16; it++) {
        int idx = it * 256 + tid; int i = idx >> 6, j = idx & 63;
        L[i][j] = (i == j) ? 1.f : 0.f;
    }
    __syncthreads();

    for (int p = 0; p < 64; p++) {
        float ip = 1.f / A[p][p];
        float myf = (tid < 64) ? A[tid][p] : 0.f;
        __syncthreads();
        if (tid < 64)        A[p][tid]       *= ip;
        else if (tid < 128)  L[p][tid - 64]  *= ip;
        if (tid < 64) fcol[tid] = (tid == p) ? 0.f : myf;
        __syncthreads();
        for (int it = 0; it < 32; it++) {
            int idx = it * 256 + tid;
            int r = idx >> 7, c = idx & 127;
            if (r != p) {
                if (c < 64) A[r][c]      -= fcol[r] * A[p][c];
                else        L[r][c - 64] -= fcol[r] * L[p][c - 64];
            }
        }
        __syncthreads();
    }
    for (int it = 0; it < 16; it++) {
        int idx = it * 256 + tid;
        ginv[b * (HDD * HDD) + idx] = L[idx >> 6][idx & 63];
    }
}

// ---------------- qg = q @ g_inv ----------------
__global__ __launch_bounds__(256)
void qg_kernel(const float* __restrict__ q, const float* __restrict__ ginv,
               float* __restrict__ qg)
{
    int m0 = blockIdx.x * 64;
    int h  = blockIdx.y;
    int b  = m0 / SS;
    __shared__ float Qt[64][65];
    __shared__ float G[64][65];
    int tid = threadIdx.x;
    const float* gb = ginv + b * (HDD * HDD);
    #pragma unroll
    for (int it = 0; it < 16; it++) {
        int idx = it * 256 + tid;
        int r = idx >> 6, c = idx & 63;
        Qt[c][r] = q[(size_t)(m0 + r) * DD + h * HDD + c];
        G[r][c]  = gb[idx];
    }
    __syncthreads();
    int tx = tid & 15, ty = tid >> 4;
    float acc[4][4] = {};
    for (int d = 0; d < 64; d++) {
        float a[4], bb[4];
        #pragma unroll
        for (int i = 0; i < 4; i++) a[i] = Qt[d][ty * 4 + i];
        #pragma unroll
        for (int j = 0; j < 4; j++) bb[j] = G[d][tx * 4 + j];
        #pragma unroll
        for (int i = 0; i < 4; i++)
            #pragma unroll
            for (int j = 0; j < 4; j++)
                acc[i][j] = fmaf(a[i], bb[j], acc[i][j]);
    }
    #pragma unroll
    for (int i = 0; i < 4; i++)
        #pragma unroll
        for (int j = 0; j < 4; j++)
            qg[(size_t)(m0 + ty * 4 + i) * DD + h * HDD + tx * 4 + j] = acc[i][j];
}

// ================= attention with tensor cores =================
#define SCR 72

// scores = qg @ k^T / 8
__global__ __launch_bounds__(256)
void scores_mma_kernel(const float* __restrict__ qg, const float* __restrict__ k,
                       float* __restrict__ sc)
{
    int bh = blockIdx.z;
    int b = bh / NHH, h = bh % NHH;
    int i0 = blockIdx.y * 64, j0 = blockIdx.x * 64;
    __shared__ __nv_bfloat16 Q0[64 * SCR], Q1[64 * SCR];
    __shared__ __nv_bfloat16 K0s[64 * SCR], K1s[64 * SCR];
    const int tid = threadIdx.x;
    const int warp = tid >> 5, lane = tid & 31;

    #pragma unroll
    for (int it = 0; it < 4; it++) {
        int f = it * 256 + tid;
        int row = f >> 4, col = (f & 15) * 4;
        float4 vq = *(const float4*)&qg[(size_t)(b * SS + i0 + row) * DD + h * HDD + col];
        float4 vk = *(const float4*)&k [(size_t)(b * SS + j0 + row) * DD + h * HDD + col];
        split4(vq, Q0, Q1, row * SCR + col);
        split4(vk, K0s, K1s, row * SCR + col);
    }
    __syncthreads();

    const uint32_t q0b = (uint32_t)__cvta_generic_to_shared(Q0);
    const uint32_t q1b = (uint32_t)__cvta_generic_to_shared(Q1);
    const uint32_t k0b = (uint32_t)__cvta_generic_to_shared(K0s);
    const uint32_t k1b = (uint32_t)__cvta_generic_to_shared(K1s);

    const int wm = (warp & 3) * 16;
    const int wn = (warp >> 2) * 32;
    float acc[4][4] = {};

    #pragma unroll
    for (int ks = 0; ks < 4; ks++) {
        uint32_t aoff = (uint32_t)(((wm + (lane & 15)) * SCR + ks * 16 + ((lane >> 4) << 3)) * 2);
        uint32_t a0[4], a1[4];
        ldsm_x4(a0[0], a0[1], a0[2], a0[3], q0b + aoff);
        ldsm_x4(a1[0], a1[1], a1[2], a1[3], q1b + aoff);
        uint32_t b0f[4][2], b1f[4][2];
        #pragma unroll
        for (int jt = 0; jt < 2; jt++) {
            uint32_t boff = (uint32_t)(((wn + jt * 16 + (lane & 15)) * SCR + ks * 16 + ((lane >> 4) << 3)) * 2);
            uint32_t r0, r1, r2, r3;
            ldsm_x4(r0, r1, r2, r3, k0b + boff);
            b0f[jt * 2 + 0][0] = r0; b0f[jt * 2 + 0][1] = r2;
            b0f[jt * 2 + 1][0] = r1; b0f[jt * 2 + 1][1] = r3;
            ldsm_x4(r0, r1, r2, r3, k1b + boff);
            b1f[jt * 2 + 0][0] = r0; b1f[jt * 2 + 0][1] = r2;
            b1f[jt * 2 + 1][0] = r1; b1f[jt * 2 + 1][1] = r3;
        }
        #pragma unroll
        for (int n = 0; n < 4; n++) {
            mma_bf16(acc[n], a0, b0f[n]);
            mma_bf16(acc[n], a0, b1f[n]);
            mma_bf16(acc[n], a1, b0f[n]);
        }
    }

    int r0 = i0 + wm + (lane >> 2);
    #pragma unroll
    for (int n = 0; n < 4; n++) {
        int c0 = j0 + wn + n * 8 + (lane & 3) * 2;
        *(float2*)&sc[((size_t)bh * SS + r0) * SS + c0]     = make_float2(acc[n][0] * 0.125f, acc[n][1] * 0.125f);
        *(float2*)&sc[((size_t)bh * SS + r0 + 8) * SS + c0] = make_float2(acc[n][2] * 0.125f, acc[n][3] * 0.125f);
    }
}

// ---------------- warp-per-row softmax over 512 ----------------
__global__ __launch_bounds__(256)
void softmax_kernel(float* __restrict__ sc)
{
    int warp = threadIdx.x >> 5, lane = threadIdx.x & 31;
    size_t row = (size_t)blockIdx.x * 8 + warp;
    float* p = sc + row * SS;
    float4 v[4];
    float mx = -1e30f;
    #pragma unroll
    for (int i = 0; i < 4; i++) {
        v[i] = ((float4*)p)[lane + i * 32];
        mx = fmaxf(mx, fmaxf(fmaxf(v[i].x, v[i].y), fmaxf(v[i].z, v[i].w)));
    }
    #pragma unroll
    for (int o = 16; o > 0; o >>= 1) mx = fmaxf(mx, __shfl_xor_sync(0xffffffffu, mx, o));
    float sum = 0.f;
    #pragma unroll
    for (int i = 0; i < 4; i++) {
        v[i].x = expf(v[i].x - mx); v[i].y = expf(v[i].y - mx);
        v[i].z = expf(v[i].z - mx); v[i].w = expf(v[i].w - mx);
        sum += v[i].x + v[i].y + v[i].z + v[i].w;
    }
    #pragma unroll
    for (int o = 16; o > 0; o >>= 1) sum += __shfl_xor_sync(0xffffffffu, sum, o);
    float inv = 1.f / sum;
    #pragma unroll
    for (int i = 0; i < 4; i++) {
        v[i].x *= inv; v[i].y *= inv; v[i].z *= inv; v[i].w *= inv;
        ((float4*)p)[lane + i * 32] = v[i];
    }
}

// ---------------- ctx = attn @ v ----------------
__global__ __launch_bounds__(256)
void ctx_mma_kernel(const float* __restrict__ attn, const float* __restrict__ v,
                    float* __restrict__ ctx)
{
    int bh = blockIdx.y;
    int b = bh / NHH, h = bh % NHH;
    int i0 = blockIdx.x * 64;
    __shared__ __nv_bfloat16 P0[64 * SCR], P1[64 * SCR];
    __shared__ __nv_bfloat16 V0[64 * SCR], V1[64 * SCR];
    const int tid = threadIdx.x;
    const int warp = tid >> 5, lane = tid & 31;
    const int wm = (warp & 3) * 16;
    const int wn = (warp >> 2) * 32;

    const uint32_t p0b = (uint32_t)__cvta_generic_to_shared(P0);
    const uint32_t p1b = (uint32_t)__cvta_generic_to_shared(P1);
    const uint32_t v0b = (uint32_t)__cvta_generic_to_shared(V0);
    const uint32_t v1b = (uint32_t)__cvta_generic_to_shared(V1);

    float acc[4][4] = {};

    for (int jt8 = 0; jt8 < 8; jt8++) {
        int j0 = jt8 * 64;
        #pragma unroll
        for (int it = 0; it < 4; it++) {
            int f = it * 256 + tid;
            int row = f >> 4, col = (f & 15) * 4;
            float4 vp = *(const float4*)&attn[((size_t)bh * SS + i0 + row) * SS + j0 + col];
            float4 vv = *(const float4*)&v[(size_t)(b * SS + j0 + row) * DD + h * HDD + col];
            split4(vp, P0, P1, row * SCR + col);
            split4(vv, V0, V1, row * SCR + col);
        }
        __syncthreads();

        #pragma unroll
        for (int ks = 0; ks < 4; ks++) {
            uint32_t aoff = (uint32_t)(((wm + (lane & 15)) * SCR + ks * 16 + ((lane >> 4) << 3)) * 2);
            uint32_t a0[4], a1[4];
            ldsm_x4(a0[0], a0[1], a0[2], a0[3], p0b + aoff);
            ldsm_x4(a1[0], a1[1], a1[2], a1[3], p1b + aoff);
            uint32_t b0f[4][2], b1f[4][2];
            #pragma unroll
            for (int jt = 0; jt < 2; jt++) {
                uint32_t boff = (uint32_t)(((ks * 16 + (lane & 15)) * SCR + wn + jt * 16 + ((lane >> 4) << 3)) * 2);
                uint32_t r0, r1, r2, r3;
                ldsm_x4_t(r0, r1, r2, r3, v0b + boff);
                b0f[jt * 2 + 0][0] = r0; b0f[jt * 2 + 0][1] = r1;
                b0f[jt * 2 + 1][0] = r2; b0f[jt * 2 + 1][1] = r3;
                ldsm_x4_t(r0, r1, r2, r3, v1b + boff);
                b1f[jt * 2 + 0][0] = r0; b1f[jt * 2 + 0][1] = r1;
                b1f[jt * 2 + 1][0] = r2; b1f[jt * 2 + 1][1] = r3;
            }
            #pragma unroll
            for (int n = 0; n < 4; n++) {
                mma_bf16(acc[n], a0, b0f[n]);
                mma_bf16(acc[n], a0, b1f[n]);
                mma_bf16(acc[n], a1, b0f[n]);
            }
        }
        __syncthreads();
    }

    int r0 = i0 + wm + (lane >> 2);
    #pragma unroll
    for (int n = 0; n < 4; n++) {
        int c0 = h * HDD + wn + n * 8 + (lane & 3) * 2;
        *(float2*)&ctx[(size_t)(b * SS + r0) * DD + c0]     = make_float2(acc[n][0], acc[n][1]);
        *(float2*)&ctx[(size_t)(b * SS + r0 + 8) * DD + c0] = make_float2(acc[n][2], acc[n][3]);
    }
}

// ---------------- launcher ----------------
extern "C" void kernel_launch(void* const* d_in, const int* in_sizes, int n_in,
                              void* d_out, int out_size)
{
    const int*   ids  = (const int*)d_in[0];
    const int*   tts  = (const int*)d_in[1];
    const float* we   = (const float*)d_in[2];
    const float* pe   = (const float*)d_in[3];
    const float* te   = (const float*)d_in[4];
    const float* lnew = (const float*)d_in[5];
    const float* lneb = (const float*)d_in[6];
    const float* Wq   = (const float*)d_in[7];
    const float* bq   = (const float*)d_in[8];
    const float* Wk   = (const float*)d_in[9];
    const float* bk   = (const float*)d_in[10];
    const float* Wv   = (const float*)d_in[11];
    const float* bv   = (const float*)d_in[12];
    const float* Lm   = (const float*)d_in[13];
    const float* dg   = (const float*)d_in[14];
    const float* Wcp  = (const float*)d_in[15];
    const float* bcp  = (const float*)d_in[16];
    const float* Wi   = (const float*)d_in[17];
    const float* bi   = (const float*)d_in[18];
    const float* Wo   = (const float*)d_in[19];
    const float* bo   = (const float*)d_in[20];
    const float* l1w  = (const float*)d_in[21];
    const float* l1b  = (const float*)d_in[22];
    const float* l2w  = (const float*)d_in[23];
    const float* l2b  = (const float*)d_in[24];

    float *h, *q, *k, *v, *qg, *attn, *ctx, *a, *f, *o, *o2, *hmean, *cw, *ginv;
    cudaGetSymbolAddress((void**)&h,     g_h);
    cudaGetSymbolAddress((void**)&q,     g_q);
    cudaGetSymbolAddress((void**)&k,     g_k);
    cudaGetSymbolAddress((void**)&v,     g_v);
    cudaGetSymbolAddress((void**)&qg,    g_qg);
    cudaGetSymbolAddress((void**)&attn,  g_attn);
    cudaGetSymbolAddress((void**)&ctx,   g_ctx);
    cudaGetSymbolAddress((void**)&a,     g_a);
    cudaGetSymbolAddress((void**)&f,     g_f);
    cudaGetSymbolAddress((void**)&o,     g_o);
    cudaGetSymbolAddress((void**)&o2,    g_o2);
    cudaGetSymbolAddress((void**)&hmean, g_hmean);
    cudaGetSymbolAddress((void**)&cw,    g_cw);
    cudaGetSymbolAddress((void**)&ginv,  g_ginv);

    cudaFuncSetAttribute(gemm3_kernel,        cudaFuncAttributeMaxDynamicSharedMemorySize, GEMM_SMEM);
    cudaFuncSetAttribute(gemm3_qkv_kernel,    cudaFuncAttributeMaxDynamicSharedMemorySize, GEMM_SMEM);
    cudaFuncSetAttribute(gemm3_splitk_kernel, cudaFuncAttributeMaxDynamicSharedMemorySize, GEMM_SMEM);

    embed_ln_kernel<<<MT, 256>>>(ids, tts, we, pe, te, lnew, lneb, h);

    for (int l = 0; l < NLL; l++) {
        const float* Wq_l  = Wq  + (size_t)l * DD * DD;
        const float* Wk_l  = Wk  + (size_t)l * DD * DD;
        const float* Wv_l  = Wv  + (size_t)l * DD * DD;
        const float* Wcp_l = Wcp + (size_t)l * DD * DD;
        const float* Wi_l  = Wi  + (size_t)l * DD * FFF;
        const float* Wo_l  = Wo  + (size_t)l * FFF * DD;
        const float* Lm_l  = Lm  + (size_t)l * DD * 64;
        const float* dg_l  = dg  + (size_t)l * DD;
        const float* bq_l  = bq  + (size_t)l * DD;
        const float* bk_l  = bk  + (size_t)l * DD;
        const float* bv_l  = bv  + (size_t)l * DD;
        const float* bcp_l = bcp + (size_t)l * DD;
        const float* bi_l  = bi  + (size_t)l * FFF;
        const float* bo_l  = bo  + (size_t)l * DD;
        const float* l1w_l = l1w + (size_t)l * DD;
        const float* l1b_l = l1b + (size_t)l * DD;
        const float* l2w_l = l2w + (size_t)l * DD;
        const float* l2b_l = l2b + (size_t)l * DD;

        // fused QKV projections
        gemm3_qkv_kernel<<<dim3(18, 32), 512, GEMM_SMEM>>>(h, Wq_l, Wk_l, Wv_l,
                                                           bq_l, bk_l, bv_l, q, k, v);

        // metric tensor path
        pool_kernel<<<BB, DD>>>(h, hmean);
        cw_kernel<<<BB, HDD>>>(hmean, Wcp_l, bcp_l, cw);
        ginv_kernel<<<BB, 256>>>(Lm_l, dg_l, cw, ginv);

        // attention
        qg_kernel<<<dim3(MT / 64, NHH), 256>>>(q, ginv, qg);
        scores_mma_kernel<<<dim3(SS / 64, SS / 64, BB * NHH), 256>>>(qg, k, attn);
        softmax_kernel<<<BB * NHH * SS / 8, 256>>>(attn);
        ctx_mma_kernel<<<dim3(SS / 64, BB * NHH), 256>>>(attn, v, ctx);

        add_ln_kernel<<<MT, 256>>>(ctx, h, l1w_l, l1b_l, a);

        // FFN
        gemm3_kernel<<<dim3(FFF / 128, MT / 128), 512, GEMM_SMEM>>>(a, Wi_l, bi_l, f, MT, FFF, DD, 1);
        gemm3_splitk_kernel<<<dim3(DD / 128, MT / 128, 2), 512, GEMM_SMEM>>>(f, Wo_l, bo_l, o, o2, MT, DD, FFF);

        float* out_h = (l == NLL - 1) ? (float*)d_out : h;
        add_ln3_kernel<<<MT, 256>>>(o, o2, a, l2w_l, l2b_l, out_h);
    }
}

// round 8
// speedup vs baseline: 2.4131x; 1.0078x over previous
#include <cuda_runtime.h>
#include <cuda_bf16.h>
#include <stdint.h>
#include <math.h>

#define BB  8
#define SS  512
#define DD  768
#define NHH 12
#define HDD 64
#define FFF 3072
#define NLL 12
#define MT  (BB*SS)   // 4096 tokens

// ---------------- scratch (static device globals; no allocation) ----------------
__device__ float g_h[MT*DD];
__device__ float g_q[MT*DD];
__device__ float g_k[MT*DD];
__device__ float g_v[MT*DD];
__device__ float g_qg[MT*DD];
__device__ float g_attn[(size_t)BB*NHH*SS*SS];   // 100 MB
__device__ float g_ctx[MT*DD];
__device__ float g_a[MT*DD];
__device__ float g_f[MT*FFF];
__device__ float g_o[MT*DD];
__device__ float g_o2[MT*DD];
__device__ float g_hmean[BB*DD];
__device__ float g_cw[BB*HDD];
__device__ float g_ginv[BB*HDD*HDD];

// ---------------- mma helpers ----------------
__device__ __forceinline__ void ldsm_x4(uint32_t& r0, uint32_t& r1, uint32_t& r2, uint32_t& r3, uint32_t addr)
{
    asm volatile("ldmatrix.sync.aligned.m8n8.x4.shared.b16 {%0,%1,%2,%3}, [%4];\n"
                 : "=r"(r0), "=r"(r1), "=r"(r2), "=r"(r3) : "r"(addr));
}
__device__ __forceinline__ void ldsm_x4_t(uint32_t& r0, uint32_t& r1, uint32_t& r2, uint32_t& r3, uint32_t addr)
{
    asm volatile("ldmatrix.sync.aligned.m8n8.x4.trans.shared.b16 {%0,%1,%2,%3}, [%4];\n"
                 : "=r"(r0), "=r"(r1), "=r"(r2), "=r"(r3) : "r"(addr));
}
__device__ __forceinline__ void mma_bf16(float* c, const uint32_t* a, const uint32_t* b)
{
    asm volatile("mma.sync.aligned.m16n8k16.row.col.f32.bf16.bf16.f32 "
                 "{%0,%1,%2,%3}, {%4,%5,%6,%7}, {%8,%9}, {%0,%1,%2,%3};\n"
                 : "+f"(c[0]), "+f"(c[1]), "+f"(c[2]), "+f"(c[3])
                 : "r"(a[0]), "r"(a[1]), "r"(a[2]), "r"(a[3]), "r"(b[0]), "r"(b[1]));
}
// packed split: hi to S0, residual to S1, 4 elems -> 2 x 4B stores each
__device__ __forceinline__ void split4(const float4 v, __nv_bfloat16* S0, __nv_bfloat16* S1, int o)
{
    __nv_bfloat162 h01 = __floats2bfloat162_rn(v.x, v.y);
    __nv_bfloat162 h23 = __floats2bfloat162_rn(v.z, v.w);
    *(__nv_bfloat162*)(S0 + o)     = h01;
    *(__nv_bfloat162*)(S0 + o + 2) = h23;
    __nv_bfloat162 l01 = __floats2bfloat162_rn(v.x - __low2float(h01), v.y - __high2float(h01));
    __nv_bfloat162 l23 = __floats2bfloat162_rn(v.z - __low2float(h23), v.w - __high2float(h23));
    *(__nv_bfloat162*)(S1 + o)     = l01;
    *(__nv_bfloat162*)(S1 + o + 2) = l23;
}

// ---------------- embedding gather + LayerNorm ----------------
__global__ __launch_bounds__(256)
void embed_ln_kernel(const int* __restrict__ ids, const int* __restrict__ tts,
                     const float* __restrict__ we, const float* __restrict__ pe,
                     const float* __restrict__ te,
                     const float* __restrict__ w, const float* __restrict__ bb,
                     float* __restrict__ out)
{
    int t = blockIdx.x;
    int s = t % SS;
    int tid = threadIdx.x;
    int id = ids[t], tt = tts[t];
    const float* wr = we + (size_t)id * DD;
    const float* pr = pe + (size_t)s  * DD;
    const float* tr = te + (size_t)tt * DD;
    __shared__ float red[256];
    float v[3];
    float sum = 0.f;
    #pragma unroll
    for (int i = 0; i < 3; i++) {
        int d = tid + i * 256;
        v[i] = wr[d] + pr[d] + tr[d];
        sum += v[i];
    }
    red[tid] = sum; __syncthreads();
    for (int o = 128; o > 0; o >>= 1) { if (tid < o) red[tid] += red[tid + o]; __syncthreads(); }
    float mean = red[0] * (1.0f / DD);
    __syncthreads();
    float vs = 0.f;
    #pragma unroll
    for (int i = 0; i < 3; i++) { float d0 = v[i] - mean; vs += d0 * d0; }
    red[tid] = vs; __syncthreads();
    for (int o = 128; o > 0; o >>= 1) { if (tid < o) red[tid] += red[tid + o]; __syncthreads(); }
    float var = red[0] * (1.0f / DD);
    float rstd = rsqrtf(var + 1e-12f);
    size_t base = (size_t)t * DD;
    #pragma unroll
    for (int i = 0; i < 3; i++) {
        int d = tid + i * 256;
        out[base + d] = (v[i] - mean) * rstd * w[d] + bb[d];
    }
}

// ---------------- out = LayerNorm(x + y) * w + b ----------------
__global__ __launch_bounds__(256)
void add_ln_kernel(const float* __restrict__ x, const float* __restrict__ y,
                   const float* __restrict__ w, const float* __restrict__ bb,
                   float* __restrict__ out)
{
    int t = blockIdx.x;
    int tid = threadIdx.x;
    __shared__ float red[256];
    size_t base = (size_t)t * DD;
    float v[3];
    float sum = 0.f;
    #pragma unroll
    for (int i = 0; i < 3; i++) {
        int d = tid + i * 256;
        v[i] = x[base + d] + y[base + d];
        sum += v[i];
    }
    red[tid] = sum; __syncthreads();
    for (int o = 128; o > 0; o >>= 1) { if (tid < o) red[tid] += red[tid + o]; __syncthreads(); }
    float mean = red[0] * (1.0f / DD);
    __syncthreads();
    float vs = 0.f;
    #pragma unroll
    for (int i = 0; i < 3; i++) { float d0 = v[i] - mean; vs += d0 * d0; }
    red[tid] = vs; __syncthreads();
    for (int o = 128; o > 0; o >>= 1) { if (tid < o) red[tid] += red[tid + o]; __syncthreads(); }
    float var = red[0] * (1.0f / DD);
    float rstd = rsqrtf(var + 1e-12f);
    #pragma unroll
    for (int i = 0; i < 3; i++) {
        int d = tid + i * 256;
        out[base + d] = (v[i] - mean) * rstd * w[d] + bb[d];
    }
}

// ---------------- out = LayerNorm(x1 + x2 + y) * w + b (split-K epilogue) ----------------
__global__ __launch_bounds__(256)
void add_ln3_kernel(const float* __restrict__ x1, const float* __restrict__ x2,
                    const float* __restrict__ y,
                    const float* __restrict__ w, const float* __restrict__ bb,
                    float* __restrict__ out)
{
    int t = blockIdx.x;
    int tid = threadIdx.x;
    __shared__ float red[256];
    size_t base = (size_t)t * DD;
    float v[3];
    float sum = 0.f;
    #pragma unroll
    for (int i = 0; i < 3; i++) {
        int d = tid + i * 256;
        v[i] = x1[base + d] + x2[base + d] + y[base + d];
        sum += v[i];
    }
    red[tid] = sum; __syncthreads();
    for (int o = 128; o > 0; o >>= 1) { if (tid < o) red[tid] += red[tid + o]; __syncthreads(); }
    float mean = red[0] * (1.0f / DD);
    __syncthreads();
    float vs = 0.f;
    #pragma unroll
    for (int i = 0; i < 3; i++) { float d0 = v[i] - mean; vs += d0 * d0; }
    red[tid] = vs; __syncthreads();
    for (int o = 128; o > 0; o >>= 1) { if (tid < o) red[tid] += red[tid + o]; __syncthreads(); }
    float var = red[0] * (1.0f / DD);
    float rstd = rsqrtf(var + 1e-12f);
    #pragma unroll
    for (int i = 0; i < 3; i++) {
        int d = tid + i * 256;
        out[base + d] = (v[i] - mean) * rstd * w[d] + bb[d];
    }
}

// ================= bf16x3 tensor-core GEMM, double-buffered =================
#define RA 40
#define RB 136
#define ASZ (128*RA)
#define BSZ (32*RB)
#define STAGE_ELEMS (2*ASZ + 2*BSZ)
#define STAGE_BYTES (STAGE_ELEMS*2)
#define GEMM_SMEM   (2*STAGE_BYTES)    // 75776 B

// core mainloop shared by all gemm variants (macro to avoid device-fn reg bloat)
#define GEMM_BODY(Aptr, Wptr, Klen, Nld)                                             \
    extern __shared__ char dynsmem[];                                                \
    const int tid  = threadIdx.x;                                                    \
    const int warp = tid >> 5;                                                       \
    const int lane = tid & 31;                                                       \
    const int wm = (warp & 3) * 32;                                                  \
    const int wn = (warp >> 2) * 32;                                                 \
    const int ar = tid >> 2;                                                         \
    const int ac = (tid & 3) * 8;                                                    \
    const int br = tid >> 4;                                                         \
    const int bc = (tid & 15) * 8;                                                   \
    const float* Ag = (Aptr) + ac;                                                   \
    const float* Wg = (Wptr) + bc;                                                   \
    float4 pa0 = *(const float4*)(Ag);                                               \
    float4 pa1 = *(const float4*)(Ag + 4);                                           \
    float4 pb0 = *(const float4*)(Wg);                                               \
    float4 pb1 = *(const float4*)(Wg + 4);                                           \
    float acc[2][4][4];                                                              \
    _Pragma("unroll") for (int i = 0; i < 2; i++)                                    \
        _Pragma("unroll") for (int j = 0; j < 4; j++)                                \
            _Pragma("unroll") for (int e = 0; e < 4; e++) acc[i][j][e] = 0.f;        \
    const uint32_t sb = (uint32_t)__cvta_generic_to_shared(dynsmem);                 \
    const int oa = ar * RA + ac;                                                     \
    const int ob = br * RB + bc;                                                     \
    const int KT = (Klen) >> 5;                                                      \
    {                                                                                \
        __nv_bfloat16* A0 = (__nv_bfloat16*)(dynsmem);                               \
        split4(pa0, A0, A0 + ASZ, oa);                                               \
        split4(pa1, A0, A0 + ASZ, oa + 4);                                           \
        split4(pb0, A0 + 2*ASZ, A0 + 2*ASZ + BSZ, ob);                               \
        split4(pb1, A0 + 2*ASZ, A0 + 2*ASZ + BSZ, ob + 4);                           \
    }                                                                                \
    __syncthreads();                                                                 \
    for (int t = 0; t < KT; t++) {                                                   \
        if (t + 1 < KT) {                                                            \
            Ag += 32;                                                                \
            Wg += (size_t)32 * (Nld);                                                \
            pa0 = *(const float4*)(Ag);                                              \
            pa1 = *(const float4*)(Ag + 4);                                          \
            pb0 = *(const float4*)(Wg);                                              \
            pb1 = *(const float4*)(Wg + 4);                                          \
        }                                                                            \
        const uint32_t base = sb + (uint32_t)(t & 1) * STAGE_BYTES;                  \
        const uint32_t as0 = base;                                                   \
        const uint32_t as1 = base + ASZ * 2;                                         \
        const uint32_t bs0 = base + 2 * ASZ * 2;                                     \
        const uint32_t bs1 = base + (2 * ASZ + BSZ) * 2;                             \
        _Pragma("unroll")                                                            \
        for (int ks = 0; ks < 2; ks++) {                                             \
            uint32_t af[2][2][4];                                                    \
            _Pragma("unroll")                                                        \
            for (int i = 0; i < 2; i++) {                                            \
                uint32_t off = (uint32_t)(((wm + i * 16 + (lane & 15)) * RA + ks * 16 + ((lane >> 4) << 3)) * 2); \
                ldsm_x4(af[0][i][0], af[0][i][1], af[0][i][2], af[0][i][3], as0 + off); \
                ldsm_x4(af[1][i][0], af[1][i][1], af[1][i][2], af[1][i][3], as1 + off); \
            }                                                                        \
            uint32_t bfr[2][4][2];                                                   \
            _Pragma("unroll")                                                        \
            for (int j = 0; j < 2; j++) {                                            \
                uint32_t off = (uint32_t)(((ks * 16 + (lane & 15)) * RB + wn + j * 16 + ((lane >> 4) << 3)) * 2); \
                uint32_t r0, r1, r2, r3;                                             \
                ldsm_x4_t(r0, r1, r2, r3, bs0 + off);                                \
                bfr[0][j * 2 + 0][0] = r0; bfr[0][j * 2 + 0][1] = r1;                \
                bfr[0][j * 2 + 1][0] = r2; bfr[0][j * 2 + 1][1] = r3;                \
                ldsm_x4_t(r0, r1, r2, r3, bs1 + off);                                \
                bfr[1][j * 2 + 0][0] = r0; bfr[1][j * 2 + 0][1] = r1;                \
                bfr[1][j * 2 + 1][0] = r2; bfr[1][j * 2 + 1][1] = r3;                \
            }                                                                        \
            _Pragma("unroll")                                                        \
            for (int i = 0; i < 2; i++)                                              \
                _Pragma("unroll")                                                    \
                for (int j = 0; j < 4; j++) {                                        \
                    mma_bf16(acc[i][j], af[0][i], bfr[0][j]);                        \
                    mma_bf16(acc[i][j], af[0][i], bfr[1][j]);                        \
                    mma_bf16(acc[i][j], af[1][i], bfr[0][j]);                        \
                }                                                                    \
        }                                                                            \
        if (t + 1 < KT) {                                                            \
            __nv_bfloat16* A0 = (__nv_bfloat16*)(dynsmem + ((t + 1) & 1) * STAGE_BYTES); \
            split4(pa0, A0, A0 + ASZ, oa);                                           \
            split4(pa1, A0, A0 + ASZ, oa + 4);                                       \
            split4(pb0, A0 + 2*ASZ, A0 + 2*ASZ + BSZ, ob);                           \
            split4(pb1, A0 + 2*ASZ, A0 + 2*ASZ + BSZ, ob + 4);                       \
        }                                                                            \
        __syncthreads();                                                             \
    }

// generic: C = A@W + bias, optional GELU
__global__ __launch_bounds__(512, 1)
void gemm3_kernel(const float* __restrict__ A, const float* __restrict__ W,
                  const float* __restrict__ bias, float* __restrict__ C,
                  int M, int N, int K, int act)
{
    const int bm = blockIdx.y * 128;
    const int bn = blockIdx.x * 128;
    GEMM_BODY(A + (size_t)(bm + (threadIdx.x >> 2)) * K,
              W + (size_t)(threadIdx.x >> 4) * N + bn, K, N)

    #pragma unroll
    for (int i = 0; i < 2; i++) {
        int r0 = bm + wm + i * 16 + (lane >> 2);
        #pragma unroll
        for (int j = 0; j < 4; j++) {
            int c0 = bn + wn + j * 8 + (lane & 3) * 2;
            float b0 = bias[c0], b1 = bias[c0 + 1];
            float v0 = acc[i][j][0] + b0;
            float v1 = acc[i][j][1] + b1;
            float v2 = acc[i][j][2] + b0;
            float v3 = acc[i][j][3] + b1;
            if (act == 1) {
                v0 = 0.5f * v0 * (1.f + erff(v0 * 0.70710678118654752f));
                v1 = 0.5f * v1 * (1.f + erff(v1 * 0.70710678118654752f));
                v2 = 0.5f * v2 * (1.f + erff(v2 * 0.70710678118654752f));
                v3 = 0.5f * v3 * (1.f + erff(v3 * 0.70710678118654752f));
            }
            *(float2*)&C[(size_t)r0 * N + c0]       = make_float2(v0, v1);
            *(float2*)&C[(size_t)(r0 + 8) * N + c0] = make_float2(v2, v3);
        }
    }
}

// fused QKV: grid.x = 18 (3 outputs x 6 ntiles), grid.y = 32
__global__ __launch_bounds__(512, 1)
void gemm3_qkv_kernel(const float* __restrict__ A,
                      const float* __restrict__ W0, const float* __restrict__ W1, const float* __restrict__ W2,
                      const float* __restrict__ bias0, const float* __restrict__ bias1, const float* __restrict__ bias2,
                      float* __restrict__ C0, float* __restrict__ C1, float* __restrict__ C2)
{
    const int nt  = blockIdx.x;
    const int sel = nt / 6;
    const int bm = blockIdx.y * 128;
    const int bn = (nt % 6) * 128;
    const float* W    = (sel == 0) ? W0 : (sel == 1) ? W1 : W2;
    const float* bias = (sel == 0) ? bias0 : (sel == 1) ? bias1 : bias2;
    float* C          = (sel == 0) ? C0 : (sel == 1) ? C1 : C2;

    GEMM_BODY(A + (size_t)(bm + (threadIdx.x >> 2)) * DD,
              W + (size_t)(threadIdx.x >> 4) * DD + bn, DD, DD)

    #pragma unroll
    for (int i = 0; i < 2; i++) {
        int r0 = bm + wm + i * 16 + (lane >> 2);
        #pragma unroll
        for (int j = 0; j < 4; j++) {
            int c0 = bn + wn + j * 8 + (lane & 3) * 2;
            float b0 = bias[c0], b1 = bias[c0 + 1];
            *(float2*)&C[(size_t)r0 * DD + c0]       = make_float2(acc[i][j][0] + b0, acc[i][j][1] + b1);
            *(float2*)&C[(size_t)(r0 + 8) * DD + c0] = make_float2(acc[i][j][2] + b0, acc[i][j][3] + b1);
        }
    }
}

// split-K (2-way) GEMM for Wo: grid.z selects K-half; z=0 -> C0 (+bias), z=1 -> C1 (raw)
__global__ __launch_bounds__(512, 1)
void gemm3_splitk_kernel(const float* __restrict__ A, const float* __restrict__ W,
                         const float* __restrict__ bias,
                         float* __restrict__ C0, float* __restrict__ C1,
                         int M, int N, int K)
{
    const int bm = blockIdx.y * 128;
    const int bn = blockIdx.x * 128;
    const int z  = blockIdx.z;
    const int KH = K >> 1;
    const int k0 = z * KH;
    float* C = z ? C1 : C0;

    GEMM_BODY(A + (size_t)(bm + (threadIdx.x >> 2)) * K + k0,
              W + (size_t)(k0 + (threadIdx.x >> 4)) * N + bn, KH, N)

    #pragma unroll
    for (int i = 0; i < 2; i++) {
        int r0 = bm + wm + i * 16 + (lane >> 2);
        #pragma unroll
        for (int j = 0; j < 4; j++) {
            int c0 = bn + wn + j * 8 + (lane & 3) * 2;
            float b0 = z ? 0.f : bias[c0];
            float b1 = z ? 0.f : bias[c0 + 1];
            *(float2*)&C[(size_t)r0 * N + c0]       = make_float2(acc[i][j][0] + b0, acc[i][j][1] + b1);
            *(float2*)&C[(size_t)(r0 + 8) * N + c0] = make_float2(acc[i][j][2] + b0, acc[i][j][3] + b1);
        }
    }
}

// ---------------- per-batch mean over sequence ----------------
__global__ void pool_kernel(const float* __restrict__ h, float* __restrict__ hmean)
{
    int b = blockIdx.x;
    int d = threadIdx.x;
    float s = 0.f;
    for (int t = 0; t < SS; t++) s += h[((size_t)b * SS + t) * DD + d];
    hmean[b * DD + d] = s * (1.0f / SS);
}

// ---------------- cw = sigmoid((hmean @ Wcp + bcp)[:64]) ----------------
__global__ void cw_kernel(const float* __restrict__ hmean, const float* __restrict__ Wcp,
                          const float* __restrict__ bcp, float* __restrict__ cw)
{
    int b = blockIdx.x;
    int j = threadIdx.x; // 0..63
    float acc = bcp[j];
    const float* hm = hmean + b * DD;
    for (int d = 0; d < DD; d++) acc = fmaf(hm[d], Wcp[(size_t)d * DD + j], acc);
    cw[b * HDD + j] = 1.f / (1.f + expf(-acc));
}

// ---------------- metric build + 64x64 inverse (Gauss-Jordan) ----------------
__global__ __launch_bounds__(256)
void ginv_kernel(const float* __restrict__ Lm_l, const float* __restrict__ diag_l,
                 const float* __restrict__ cw, float* __restrict__ ginv)
{
    int b = blockIdx.x, tid = threadIdx.x;
    __shared__ float L[64][64];
    __shared__ float A[64][65];
    __shared__ float fcol[64];

    for (int it = 0; it < 16; it++) {
        int idx = it * 256 + tid; int i = idx >> 6, j = idx & 63;
        L[i][j] = Lm_l[i * 64 + j] * cw[b * HDD + i];
    }
    __syncthreads();
    for (int it = 0; it < 16; it++) {
        int idx = it * 256 + tid; int i = idx >> 6, j = idx & 63;
        float s = 0.f;
        for (int t2 = 0; t2 < 64; t2++) s = fmaf(L[i][t2], L[j][t2], s);
        if (i == j) s += diag_l[i] + 1e-6f + 0.1f;
        A[i][j] = s;
    }
    __syncthreads();
    for (int it = 0; it < 16; it++) {
        int idx = it * 256 + tid; int i = idx >> 6, j = idx & 63;
        L[i][j] = (i == j) ? 1.f : 0.f;
    }
    __syncthreads();

    for (int p = 0; p < 64; p++) {
        float ip = 1.f / A[p][p];
        float myf = (tid < 64) ? A[tid][p] : 0.f;
        __syncthreads();
        if (tid < 64)        A[p][tid]       *= ip;
        else if (tid < 128)  L[p][tid - 64]  *= ip;
        if (tid < 64) fcol[tid] = (tid == p) ? 0.f : myf;
        __syncthreads();
        for (int it = 0; it < 32; it++) {
            int idx = it * 256 + tid;
            int r = idx >> 7, c = idx & 127;
            if (r != p) {
                if (c < 64) A[r][c]      -= fcol[r] * A[p][c];
                else        L[r][c - 64] -= fcol[r] * L[p][c - 64];
            }
        }
        __syncthreads();
    }
    for (int it = 0; it < 16; it++) {
        int idx = it * 256 + tid;
        ginv[b * (HDD * HDD) + idx] = L[idx >> 6][idx & 63];
    }
}

// ---------------- qg = q @ g_inv ----------------
__global__ __launch_bounds__(256)
void qg_kernel(const float* __restrict__ q, const float* __restrict__ ginv,
               float* __restrict__ qg)
{
    int m0 = blockIdx.x * 64;
    int h  = blockIdx.y;
    int b  = m0 / SS;
    __shared__ float Qt[64][65];
    __shared__ float G[64][65];
    int tid = threadIdx.x;
    const float* gb = ginv + b * (HDD * HDD);
    #pragma unroll
    for (int it = 0; it < 16; it++) {
        int idx = it * 256 + tid;
        int r = idx >> 6, c = idx & 63;
        Qt[c][r] = q[(size_t)(m0 + r) * DD + h * HDD + c];
        G[r][c]  = gb[idx];
    }
    __syncthreads();
    int tx = tid & 15, ty = tid >> 4;
    float acc[4][4] = {};
    for (int d = 0; d < 64; d++) {
        float a[4], bb[4];
        #pragma unroll
        for (int i = 0; i < 4; i++) a[i] = Qt[d][ty * 4 + i];
        #pragma unroll
        for (int j = 0; j < 4; j++) bb[j] = G[d][tx * 4 + j];
        #pragma unroll
        for (int i = 0; i < 4; i++)
            #pragma unroll
            for (int j = 0; j < 4; j++)
                acc[i][j] = fmaf(a[i], bb[j], acc[i][j]);
    }
    #pragma unroll
    for (int i = 0; i < 4; i++)
        #pragma unroll
        for (int j = 0; j < 4; j++)
            qg[(size_t)(m0 + ty * 4 + i) * DD + h * HDD + tx * 4 + j] = acc[i][j];
}

// ================= attention with tensor cores =================
#define SCR 72

// scores = qg @ k^T / 8
__global__ __launch_bounds__(256)
void scores_mma_kernel(const float* __restrict__ qg, const float* __restrict__ k,
                       float* __restrict__ sc)
{
    int bh = blockIdx.z;
    int b = bh / NHH, h = bh % NHH;
    int i0 = blockIdx.y * 64, j0 = blockIdx.x * 64;
    __shared__ __nv_bfloat16 Q0[64 * SCR], Q1[64 * SCR];
    __shared__ __nv_bfloat16 K0s[64 * SCR], K1s[64 * SCR];
    const int tid = threadIdx.x;
    const int warp = tid >> 5, lane = tid & 31;

    #pragma unroll
    for (int it = 0; it < 4; it++) {
        int f = it * 256 + tid;
        int row = f >> 4, col = (f & 15) * 4;
        float4 vq = *(const float4*)&qg[(size_t)(b * SS + i0 + row) * DD + h * HDD + col];
        float4 vk = *(const float4*)&k [(size_t)(b * SS + j0 + row) * DD + h * HDD + col];
        split4(vq, Q0, Q1, row * SCR + col);
        split4(vk, K0s, K1s, row * SCR + col);
    }
    __syncthreads();

    const uint32_t q0b = (uint32_t)__cvta_generic_to_shared(Q0);
    const uint32_t q1b = (uint32_t)__cvta_generic_to_shared(Q1);
    const uint32_t k0b = (uint32_t)__cvta_generic_to_shared(K0s);
    const uint32_t k1b = (uint32_t)__cvta_generic_to_shared(K1s);

    const int wm = (warp & 3) * 16;
    const int wn = (warp >> 2) * 32;
    float acc[4][4] = {};

    #pragma unroll
    for (int ks = 0; ks < 4; ks++) {
        uint32_t aoff = (uint32_t)(((wm + (lane & 15)) * SCR + ks * 16 + ((lane >> 4) << 3)) * 2);
        uint32_t a0[4], a1[4];
        ldsm_x4(a0[0], a0[1], a0[2], a0[3], q0b + aoff);
        ldsm_x4(a1[0], a1[1], a1[2], a1[3], q1b + aoff);
        uint32_t b0f[4][2], b1f[4][2];
        #pragma unroll
        for (int jt = 0; jt < 2; jt++) {
            uint32_t boff = (uint32_t)(((wn + jt * 16 + (lane & 15)) * SCR + ks * 16 + ((lane >> 4) << 3)) * 2);
            uint32_t r0, r1, r2, r3;
            ldsm_x4(r0, r1, r2, r3, k0b + boff);
            b0f[jt * 2 + 0][0] = r0; b0f[jt * 2 + 0][1] = r2;
            b0f[jt * 2 + 1][0] = r1; b0f[jt * 2 + 1][1] = r3;
            ldsm_x4(r0, r1, r2, r3, k1b + boff);
            b1f[jt * 2 + 0][0] = r0; b1f[jt * 2 + 0][1] = r2;
            b1f[jt * 2 + 1][0] = r1; b1f[jt * 2 + 1][1] = r3;
        }
        #pragma unroll
        for (int n = 0; n < 4; n++) {
            mma_bf16(acc[n], a0, b0f[n]);
            mma_bf16(acc[n], a0, b1f[n]);
            mma_bf16(acc[n], a1, b0f[n]);
        }
    }

    int r0 = i0 + wm + (lane >> 2);
    #pragma unroll
    for (int n = 0; n < 4; n++) {
        int c0 = j0 + wn + n * 8 + (lane & 3) * 2;
        *(float2*)&sc[((size_t)bh * SS + r0) * SS + c0]     = make_float2(acc[n][0] * 0.125f, acc[n][1] * 0.125f);
        *(float2*)&sc[((size_t)bh * SS + r0 + 8) * SS + c0] = make_float2(acc[n][2] * 0.125f, acc[n][3] * 0.125f);
    }
}

// ---------------- warp-per-row softmax over 512 ----------------
__global__ __launch_bounds__(256)
void softmax_kernel(float* __restrict__ sc)
{
    int warp = threadIdx.x >> 5, lane = threadIdx.x & 31;
    size_t row = (size_t)blockIdx.x * 8 + warp;
    float* p = sc + row * SS;
    float4 v[4];
    float mx = -1e30f;
    #pragma unroll
    for (int i = 0; i < 4; i++) {
        v[i] = ((float4*)p)[lane + i * 32];
        mx = fmaxf(mx, fmaxf(fmaxf(v[i].x, v[i].y), fmaxf(v[i].z, v[i].w)));
    }
    #pragma unroll
    for (int o = 16; o > 0; o >>= 1) mx = fmaxf(mx, __shfl_xor_sync(0xffffffffu, mx, o));
    float sum = 0.f;
    #pragma unroll
    for (int i = 0; i < 4; i++) {
        v[i].x = expf(v[i].x - mx); v[i].y = expf(v[i].y - mx);
        v[i].z = expf(v[i].z - mx); v[i].w = expf(v[i].w - mx);
        sum += v[i].x + v[i].y + v[i].z + v[i].w;
    }
    #pragma unroll
    for (int o = 16; o > 0; o >>= 1) sum += __shfl_xor_sync(0xffffffffu, sum, o);
    float inv = 1.f / sum;
    #pragma unroll
    for (int i = 0; i < 4; i++) {
        v[i].x *= inv; v[i].y *= inv; v[i].z *= inv; v[i].w *= inv;
        ((float4*)p)[lane + i * 32] = v[i];
    }
}

// ---------------- ctx = attn @ v ----------------
__global__ __launch_bounds__(256)
void ctx_mma_kernel(const float* __restrict__ attn, const float* __restrict__ v,
                    float* __restrict__ ctx)
{
    int bh = blockIdx.y;
    int b = bh / NHH, h = bh % NHH;
    int i0 = blockIdx.x * 64;
    __shared__ __nv_bfloat16 P0[64 * SCR], P1[64 * SCR];
    __shared__ __nv_bfloat16 V0[64 * SCR], V1[64 * SCR];
    const int tid = threadIdx.x;
    const int warp = tid >> 5, lane = tid & 31;
    const int wm = (warp & 3) * 16;
    const int wn = (warp >> 2) * 32;

    const uint32_t p0b = (uint32_t)__cvta_generic_to_shared(P0);
    const uint32_t p1b = (uint32_t)__cvta_generic_to_shared(P1);
    const uint32_t v0b = (uint32_t)__cvta_generic_to_shared(V0);
    const uint32_t v1b = (uint32_t)__cvta_generic_to_shared(V1);

    float acc[4][4] = {};

    for (int jt8 = 0; jt8 < 8; jt8++) {
        int j0 = jt8 * 64;
        #pragma unroll
        for (int it = 0; it < 4; it++) {
            int f = it * 256 + tid;
            int row = f >> 4, col = (f & 15) * 4;
            float4 vp = *(const float4*)&attn[((size_t)bh * SS + i0 + row) * SS + j0 + col];
            float4 vv = *(const float4*)&v[(size_t)(b * SS + j0 + row) * DD + h * HDD + col];
            split4(vp, P0, P1, row * SCR + col);
            split4(vv, V0, V1, row * SCR + col);
        }
        __syncthreads();

        #pragma unroll
        for (int ks = 0; ks < 4; ks++) {
            uint32_t aoff = (uint32_t)(((wm + (lane & 15)) * SCR + ks * 16 + ((lane >> 4) << 3)) * 2);
            uint32_t a0[4], a1[4];
            ldsm_x4(a0[0], a0[1], a0[2], a0[3], p0b + aoff);
            ldsm_x4(a1[0], a1[1], a1[2], a1[3], p1b + aoff);
            uint32_t b0f[4][2], b1f[4][2];
            #pragma unroll
            for (int jt = 0; jt < 2; jt++) {
                uint32_t boff = (uint32_t)(((ks * 16 + (lane & 15)) * SCR + wn + jt * 16 + ((lane >> 4) << 3)) * 2);
                uint32_t r0, r1, r2, r3;
                ldsm_x4_t(r0, r1, r2, r3, v0b + boff);
                b0f[jt * 2 + 0][0] = r0; b0f[jt * 2 + 0][1] = r1;
                b0f[jt * 2 + 1][0] = r2; b0f[jt * 2 + 1][1] = r3;
                ldsm_x4_t(r0, r1, r2, r3, v1b + boff);
                b1f[jt * 2 + 0][0] = r0; b1f[jt * 2 + 0][1] = r1;
                b1f[jt * 2 + 1][0] = r2; b1f[jt * 2 + 1][1] = r3;
            }
            #pragma unroll
            for (int n = 0; n < 4; n++) {
                mma_bf16(acc[n], a0, b0f[n]);
                mma_bf16(acc[n], a0, b1f[n]);
                mma_bf16(acc[n], a1, b0f[n]);
            }
        }
        __syncthreads();
    }

    int r0 = i0 + wm + (lane >> 2);
    #pragma unroll
    for (int n = 0; n < 4; n++) {
        int c0 = h * HDD + wn + n * 8 + (lane & 3) * 2;
        *(float2*)&ctx[(size_t)(b * SS + r0) * DD + c0]     = make_float2(acc[n][0], acc[n][1]);
        *(float2*)&ctx[(size_t)(b * SS + r0 + 8) * DD + c0] = make_float2(acc[n][2], acc[n][3]);
    }
}

// ---------------- launcher ----------------
extern "C" void kernel_launch(void* const* d_in, const int* in_sizes, int n_in,
                              void* d_out, int out_size)
{
    const int*   ids  = (const int*)d_in[0];
    const int*   tts  = (const int*)d_in[1];
    const float* we   = (const float*)d_in[2];
    const float* pe   = (const float*)d_in[3];
    const float* te   = (const float*)d_in[4];
    const float* lnew = (const float*)d_in[5];
    const float* lneb = (const float*)d_in[6];
    const float* Wq   = (const float*)d_in[7];
    const float* bq   = (const float*)d_in[8];
    const float* Wk   = (const float*)d_in[9];
    const float* bk   = (const float*)d_in[10];
    const float* Wv   = (const float*)d_in[11];
    const float* bv   = (const float*)d_in[12];
    const float* Lm   = (const float*)d_in[13];
    const float* dg   = (const float*)d_in[14];
    const float* Wcp  = (const float*)d_in[15];
    const float* bcp  = (const float*)d_in[16];
    const float* Wi   = (const float*)d_in[17];
    const float* bi   = (const float*)d_in[18];
    const float* Wo   = (const float*)d_in[19];
    const float* bo   = (const float*)d_in[20];
    const float* l1w  = (const float*)d_in[21];
    const float* l1b  = (const float*)d_in[22];
    const float* l2w  = (const float*)d_in[23];
    const float* l2b  = (const float*)d_in[24];

    float *h, *q, *k, *v, *qg, *attn, *ctx, *a, *f, *o, *o2, *hmean, *cw, *ginv;
    cudaGetSymbolAddress((void**)&h,     g_h);
    cudaGetSymbolAddress((void**)&q,     g_q);
    cudaGetSymbolAddress((void**)&k,     g_k);
    cudaGetSymbolAddress((void**)&v,     g_v);
    cudaGetSymbolAddress((void**)&qg,    g_qg);
    cudaGetSymbolAddress((void**)&attn,  g_attn);
    cudaGetSymbolAddress((void**)&ctx,   g_ctx);
    cudaGetSymbolAddress((void**)&a,     g_a);
    cudaGetSymbolAddress((void**)&f,     g_f);
    cudaGetSymbolAddress((void**)&o,     g_o);
    cudaGetSymbolAddress((void**)&o2,    g_o2);
    cudaGetSymbolAddress((void**)&hmean, g_hmean);
    cudaGetSymbolAddress((void**)&cw,    g_cw);
    cudaGetSymbolAddress((void**)&ginv,  g_ginv);

    cudaFuncSetAttribute(gemm3_kernel,        cudaFuncAttributeMaxDynamicSharedMemorySize, GEMM_SMEM);
    cudaFuncSetAttribute(gemm3_qkv_kernel,    cudaFuncAttributeMaxDynamicSharedMemorySize, GEMM_SMEM);
    cudaFuncSetAttribute(gemm3_splitk_kernel, cudaFuncAttributeMaxDynamicSharedMemorySize, GEMM_SMEM);

    embed_ln_kernel<<<MT, 256>>>(ids, tts, we, pe, te, lnew, lneb, h);

    for (int l = 0; l < NLL; l++) {
        const float* Wq_l  = Wq  + (size_t)l * DD * DD;
        const float* Wk_l  = Wk  + (size_t)l * DD * DD;
        const float* Wv_l  = Wv  + (size_t)l * DD * DD;
        const float* Wcp_l = Wcp + (size_t)l * DD * DD;
        const float* Wi_l  = Wi  + (size_t)l * DD * FFF;
        const float* Wo_l  = Wo  + (size_t)l * FFF * DD;
        const float* Lm_l  = Lm  + (size_t)l * DD * 64;
        const float* dg_l  = dg  + (size_t)l * DD;
        const float* bq_l  = bq  + (size_t)l * DD;
        const float* bk_l  = bk  + (size_t)l * DD;
        const float* bv_l  = bv  + (size_t)l * DD;
        const float* bcp_l = bcp + (size_t)l * DD;
        const float* bi_l  = bi  + (size_t)l * FFF;
        const float* bo_l  = bo  + (size_t)l * DD;
        const float* l1w_l = l1w + (size_t)l * DD;
        const float* l1b_l = l1b + (size_t)l * DD;
        const float* l2w_l = l2w + (size_t)l * DD;
        const float* l2b_l = l2b + (size_t)l * DD;

        // fused QKV projections
        gemm3_qkv_kernel<<<dim3(18, 32), 512, GEMM_SMEM>>>(h, Wq_l, Wk_l, Wv_l,
                                                           bq_l, bk_l, bv_l, q, k, v);

        // metric tensor path
        pool_kernel<<<BB, DD>>>(h, hmean);
        cw_kernel<<<BB, HDD>>>(hmean, Wcp_l, bcp_l, cw);
        ginv_kernel<<<BB, 256>>>(Lm_l, dg_l, cw, ginv);

        // attention
        qg_kernel<<<dim3(MT / 64, NHH), 256>>>(q, ginv, qg);
        scores_mma_kernel<<<dim3(SS / 64, SS / 64, BB * NHH), 256>>>(qg, k, attn);
        softmax_kernel<<<BB * NHH * SS / 8, 256>>>(attn);
        ctx_mma_kernel<<<dim3(SS / 64, BB * NHH), 256>>>(attn, v, ctx);

        add_ln_kernel<<<MT, 256>>>(ctx, h, l1w_l, l1b_l, a);

        // FFN
        gemm3_kernel<<<dim3(FFF / 128, MT / 128), 512, GEMM_SMEM>>>(a, Wi_l, bi_l, f, MT, FFF, DD, 1);
        gemm3_splitk_kernel<<<dim3(DD / 128, MT / 128, 2), 512, GEMM_SMEM>>>(f, Wo_l, bo_l, o, o2, MT, DD, FFF);

        float* out_h = (l == NLL - 1) ? (float*)d_out : h;
        add_ln3_kernel<<<MT, 256>>>(o, o2, a, l2w_l, l2b_l, out_h);
    }
}

// round 10
// speedup vs baseline: 2.6231x; 1.0870x over previous
#include <cuda_runtime.h>
#include <cuda_bf16.h>
#include <stdint.h>
#include <math.h>

#define BB 8
#define SS 512
#define DD 768
#define NHH 12
#define HDD 64
#define FFF 3072
#define NLL 12
#define MT (BB*SS)

__device__ float g_h[MT*DD];
__device__ float g_q[MT*DD];
__device__ float g_k[MT*DD];
__device__ float g_v[MT*DD];
__device__ float g_qg[MT*DD];
__device__ float g_attn[(size_t)BB*NHH*SS*SS];
__device__ float g_ctx[MT*DD];
__device__ float g_a[MT*DD];
__device__ float g_f[MT*FFF];
__device__ float g_o[MT*DD];
__device__ float g_o2[MT*DD];
__device__ float g_hmean[BB*DD];
__device__ float g_cw[BB*HDD];
__device__ float g_ginv[BB*HDD*HDD];
// pre-split bf16 weights (hi/lo) + activation pairs
__device__ __nv_bfloat16 g_wq_h[NLL*DD*DD], g_wq_l[NLL*DD*DD];
__device__ __nv_bfloat16 g_wk_h[NLL*DD*DD], g_wk_l[NLL*DD*DD];
__device__ __nv_bfloat16 g_wv_h[NLL*DD*DD], g_wv_l[NLL*DD*DD];
__device__ __nv_bfloat16 g_wi_h[(size_t)NLL*DD*FFF], g_wi_l[(size_t)NLL*DD*FFF];
__device__ __nv_bfloat16 g_wo_h[(size_t)NLL*FFF*DD], g_wo_l[(size_t)NLL*FFF*DD];
__device__ __nv_bfloat16 g_hh[MT*DD], g_hl[MT*DD];
__device__ __nv_bfloat16 g_ah[MT*DD], g_al[MT*DD];
__device__ __nv_bfloat16 g_fh[MT*FFF], g_fl[MT*FFF];

// ---- helpers ----
__device__ __forceinline__ void ldsm_x4(uint32_t& r0, uint32_t& r1, uint32_t& r2, uint32_t& r3, uint32_t a)
{ asm volatile("ldmatrix.sync.aligned.m8n8.x4.shared.b16 {%0,%1,%2,%3},[%4];" : "=r"(r0),"=r"(r1),"=r"(r2),"=r"(r3) : "r"(a)); }
__device__ __forceinline__ void ldsm_x4_t(uint32_t& r0, uint32_t& r1, uint32_t& r2, uint32_t& r3, uint32_t a)
{ asm volatile("ldmatrix.sync.aligned.m8n8.x4.trans.shared.b16 {%0,%1,%2,%3},[%4];" : "=r"(r0),"=r"(r1),"=r"(r2),"=r"(r3) : "r"(a)); }
__device__ __forceinline__ void mma_bf16(float* c, const uint32_t* a, const uint32_t* b)
{ asm volatile("mma.sync.aligned.m16n8k16.row.col.f32.bf16.bf16.f32 {%0,%1,%2,%3},{%4,%5,%6,%7},{%8,%9},{%0,%1,%2,%3};"
               : "+f"(c[0]),"+f"(c[1]),"+f"(c[2]),"+f"(c[3])
               : "r"(a[0]),"r"(a[1]),"r"(a[2]),"r"(a[3]),"r"(b[0]),"r"(b[1])); }
__device__ __forceinline__ void split4(const float4 v, __nv_bfloat16* S0, __nv_bfloat16* S1, int o)
{
    __nv_bfloat162 h01 = __floats2bfloat162_rn(v.x, v.y), h23 = __floats2bfloat162_rn(v.z, v.w);
    *(__nv_bfloat162*)(S0+o) = h01; *(__nv_bfloat162*)(S0+o+2) = h23;
    __nv_bfloat162 l01 = __floats2bfloat162_rn(v.x-__low2float(h01), v.y-__high2float(h01));
    __nv_bfloat162 l23 = __floats2bfloat162_rn(v.z-__low2float(h23), v.w-__high2float(h23));
    *(__nv_bfloat162*)(S1+o) = l01; *(__nv_bfloat162*)(S1+o+2) = l23;
}
__device__ __forceinline__ float gelu(float x) { return 0.5f*x*(1.f+erff(x*0.70710678118654752f)); }
__device__ __forceinline__ uint32_t packpair(float x, float y, uint32_t& lo)
{
    __nv_bfloat162 h = __floats2bfloat162_rn(x, y);
    __nv_bfloat162 l = __floats2bfloat162_rn(x-__low2float(h), y-__high2float(h));
    lo = *(uint32_t*)&l; return *(uint32_t*)&h;
}
__device__ __forceinline__ void cp16(uint32_t s, const void* g)
{ asm volatile("cp.async.cg.shared.global [%0],[%1],16;" :: "r"(s),"l"(g) : "memory"); }

// ---- weight pre-split ----
__global__ __launch_bounds__(256)
void split_w_kernel(const float* __restrict__ src, __nv_bfloat16* __restrict__ dh,
                    __nv_bfloat16* __restrict__ dl, int n4)
{
    for (int i = blockIdx.x*256 + threadIdx.x; i < n4; i += gridDim.x*256) {
        float4 v = ((const float4*)src)[i];
        uint32_t l0, h0 = packpair(v.x, v.y, l0);
        uint32_t l1, h1 = packpair(v.z, v.w, l1);
        ((uint32_t*)dh)[i*2] = h0; ((uint32_t*)dh)[i*2+1] = h1;
        ((uint32_t*)dl)[i*2] = l0; ((uint32_t*)dl)[i*2+1] = l1;
    }
}

// ================= bf16x3 GEMM: pre-split inputs, cp.async, 8 warps, 2 CTA/SM ================
#define GRA 40
#define GRB 136
#define GASZ (128*GRA)
#define GBSZ (32*GRB)
#define GSTG_B ((2*GASZ + 2*GBSZ)*2)   // 37888 B / stage
#define G_SMEM (2*GSTG_B)              // 75776 B

__device__ __forceinline__ void gemm_core(
    const __nv_bfloat16* Ah, const __nv_bfloat16* Al, int lda,
    const __nv_bfloat16* Wh, const __nv_bfloat16* Wl, int ldw,
    const float* bias, float* C, __nv_bfloat16* Ch, __nv_bfloat16* Cl, int ldc,
    int K, int act, int bm, int bn, int addb)
{
    extern __shared__ char smem[];
    const int tid = threadIdx.x, warp = tid >> 5, lane = tid & 31;
    const int wm = (warp & 3) * 32, wn = (warp >> 2) * 64;
    const uint32_t sb = (uint32_t)__cvta_generic_to_shared(smem);
    const int KT = K >> 5;
    float acc[2][8][4] = {};

    #define ISSUE(buf, k0) do { \
        uint32_t st = sb + (uint32_t)(buf)*GSTG_B; \
        _Pragma("unroll") for (int kk = 0; kk < 2; kk++) { \
            int ch = tid + kk*256; \
            int r = ch >> 2, o = (ch & 3) * 8; \
            uint32_t d = st + (uint32_t)(r*GRA + o)*2; \
            cp16(d,          Ah + (size_t)(bm+r)*lda + (k0) + o); \
            cp16(d + GASZ*2, Al + (size_t)(bm+r)*lda + (k0) + o); \
            int r2 = ch >> 4, o2 = (ch & 15) * 8; \
            uint32_t d2 = st + (uint32_t)(2*GASZ + r2*GRB + o2)*2; \
            cp16(d2,          Wh + (size_t)((k0)+r2)*ldw + bn + o2); \
            cp16(d2 + GBSZ*2, Wl + (size_t)((k0)+r2)*ldw + bn + o2); \
        } \
        asm volatile("cp.async.commit_group;" ::: "memory"); \
    } while(0)

    ISSUE(0, 0);
    for (int t = 0; t < KT; t++) {
        if (t + 1 < KT) { ISSUE((t+1)&1, (t+1)*32); asm volatile("cp.async.wait_group 1;" ::: "memory"); }
        else            { asm volatile("cp.async.wait_group 0;" ::: "memory"); }
        __syncthreads();
        uint32_t base = sb + (uint32_t)(t & 1) * GSTG_B;
        uint32_t a0b = base, a1b = base + GASZ*2, b0b = base + 2*GASZ*2, b1b = base + (2*GASZ+GBSZ)*2;
        #pragma unroll
        for (int ks = 0; ks < 2; ks++) {
            uint32_t a0[2][4], a1[2][4];
            #pragma unroll
            for (int i = 0; i < 2; i++) {
                uint32_t off = (uint32_t)(((wm + i*16 + (lane&15))*GRA + ks*16 + ((lane>>4)<<3))*2);
                ldsm_x4(a0[i][0],a0[i][1],a0[i][2],a0[i][3], a0b+off);
                ldsm_x4(a1[i][0],a1[i][1],a1[i][2],a1[i][3], a1b+off);
            }
            #pragma unroll
            for (int j = 0; j < 4; j++) {
                uint32_t boff = (uint32_t)(((ks*16 + (lane&15))*GRB + wn + j*16 + ((lane>>4)<<3))*2);
                uint32_t h0,h1,h2,h3, l0,l1,l2,l3;
                ldsm_x4_t(h0,h1,h2,h3, b0b+boff);
                ldsm_x4_t(l0,l1,l2,l3, b1b+boff);
                uint32_t bh0[2]={h0,h1}, bh1[2]={h2,h3}, bl0[2]={l0,l1}, bl1[2]={l2,l3};
                #pragma unroll
                for (int i = 0; i < 2; i++) {
                    mma_bf16(acc[i][j*2],   a0[i], bh0); mma_bf16(acc[i][j*2],   a0[i], bl0); mma_bf16(acc[i][j*2],   a1[i], bh0);
                    mma_bf16(acc[i][j*2+1], a0[i], bh1); mma_bf16(acc[i][j*2+1], a0[i], bl1); mma_bf16(acc[i][j*2+1], a1[i], bh1);
                }
            }
        }
        __syncthreads();
    }
    #undef ISSUE

    #pragma unroll
    for (int i = 0; i < 2; i++) {
        int r0 = bm + wm + i*16 + (lane >> 2);
        #pragma unroll
        for (int j = 0; j < 8; j++) {
            int c0 = bn + wn + j*8 + (lane & 3)*2;
            float b0v = addb ? bias[c0] : 0.f, b1v = addb ? bias[c0+1] : 0.f;
            float v0 = acc[i][j][0]+b0v, v1 = acc[i][j][1]+b1v;
            float v2 = acc[i][j][2]+b0v, v3 = acc[i][j][3]+b1v;
            if (act) { v0 = gelu(v0); v1 = gelu(v1); v2 = gelu(v2); v3 = gelu(v3); }
            *(float2*)&C[(size_t)r0*ldc + c0]     = make_float2(v0, v1);
            *(float2*)&C[(size_t)(r0+8)*ldc + c0] = make_float2(v2, v3);
            if (Ch) {
                uint32_t lo, hi = packpair(v0, v1, lo);
                *(uint32_t*)&Ch[(size_t)r0*ldc + c0] = hi; *(uint32_t*)&Cl[(size_t)r0*ldc + c0] = lo;
                hi = packpair(v2, v3, lo);
                *(uint32_t*)&Ch[(size_t)(r0+8)*ldc + c0] = hi; *(uint32_t*)&Cl[(size_t)(r0+8)*ldc + c0] = lo;
            }
        }
    }
}

__global__ __launch_bounds__(256, 2)
void gemm_kernel(const __nv_bfloat16* __restrict__ Ah, const __nv_bfloat16* __restrict__ Al,
                 const __nv_bfloat16* __restrict__ Wh, const __nv_bfloat16* __restrict__ Wl,
                 const float* __restrict__ bias, float* __restrict__ C,
                 __nv_bfloat16* __restrict__ Ch, __nv_bfloat16* __restrict__ Cl, int N, int K, int act)
{ gemm_core(Ah, Al, K, Wh, Wl, N, bias, C, Ch, Cl, N, K, act, blockIdx.y*128, blockIdx.x*128, 1); }

__global__ __launch_bounds__(256, 2)
void gemm_qkv_kernel(const __nv_bfloat16* __restrict__ Ah, const __nv_bfloat16* __restrict__ Al,
                     const __nv_bfloat16* Wqh, const __nv_bfloat16* Wql,
                     const __nv_bfloat16* Wkh, const __nv_bfloat16* Wkl,
                     const __nv_bfloat16* Wvh, const __nv_bfloat16* Wvl,
                     const float* b0, const float* b1, const float* b2,
                     float* C0, float* C1, float* C2)
{
    int sel = blockIdx.x / 6, bn = (blockIdx.x % 6) * 128;
    gemm_core(Ah, Al, DD, sel==0?Wqh:sel==1?Wkh:Wvh, sel==0?Wql:sel==1?Wkl:Wvl, DD,
              sel==0?b0:sel==1?b1:b2, sel==0?C0:sel==1?C1:C2, nullptr, nullptr, DD,
              DD, 0, blockIdx.y*128, bn, 1);
}

__global__ __launch_bounds__(256, 2)
void gemm_splitk_kernel(const __nv_bfloat16* __restrict__ Ah, const __nv_bfloat16* __restrict__ Al,
                        const __nv_bfloat16* __restrict__ Wh, const __nv_bfloat16* __restrict__ Wl,
                        const float* __restrict__ bias, float* __restrict__ C0, float* __restrict__ C1)
{
    int z = blockIdx.z;
    gemm_core(Ah + z*(FFF/2), Al + z*(FFF/2), FFF,
              Wh + (size_t)(z*(FFF/2))*DD, Wl + (size_t)(z*(FFF/2))*DD, DD,
              bias, z ? C1 : C0, nullptr, nullptr, DD, FFF/2, 0, blockIdx.y*128, blockIdx.x*128, z == 0);
}

// ---- LayerNorm family (optional bf16 pair emission) ----
#define LN_BODY(EXPR) \
    int t = blockIdx.x, tid = threadIdx.x; \
    __shared__ float red[256]; \
    size_t base = (size_t)t * DD; \
    float v[3]; float sum = 0.f; \
    _Pragma("unroll") for (int i = 0; i < 3; i++) { int d = tid + i*256; v[i] = (EXPR); sum += v[i]; } \
    red[tid] = sum; __syncthreads(); \
    for (int o = 128; o > 0; o >>= 1) { if (tid < o) red[tid] += red[tid+o]; __syncthreads(); } \
    float mean = red[0] * (1.0f/DD); __syncthreads(); \
    float vs = 0.f; \
    _Pragma("unroll") for (int i = 0; i < 3; i++) { float d0 = v[i]-mean; vs += d0*d0; } \
    red[tid] = vs; __syncthreads(); \
    for (int o = 128; o > 0; o >>= 1) { if (tid < o) red[tid] += red[tid+o]; __syncthreads(); } \
    float rstd = rsqrtf(red[0]*(1.0f/DD) + 1e-12f); \
    _Pragma("unroll") for (int i = 0; i < 3; i++) { int d = tid + i*256; \
        float vv = (v[i]-mean)*rstd*w[d] + bb[d]; out[base+d] = vv; \
        if (oh) { __nv_bfloat16 hb = __float2bfloat16(vv); oh[base+d] = hb; \
                  ol[base+d] = __float2bfloat16(vv - __bfloat162float(hb)); } }

__global__ __launch_bounds__(256)
void embed_ln_kernel(const int* __restrict__ ids, const int* __restrict__ tts,
                     const float* __restrict__ we, const float* __restrict__ pe, const float* __restrict__ te,
                     const float* __restrict__ w, const float* __restrict__ bb, float* __restrict__ out,
                     __nv_bfloat16* __restrict__ oh, __nv_bfloat16* __restrict__ ol)
{
    int s = blockIdx.x % SS;
    const float* wr = we + (size_t)ids[blockIdx.x] * DD;
    const float* pr = pe + (size_t)s * DD;
    const float* tr = te + (size_t)tts[blockIdx.x] * DD;
    LN_BODY(wr[d] + pr[d] + tr[d])
}
__global__ __launch_bounds__(256)
void add_ln_kernel(const float* __restrict__ x, const float* __restrict__ y,
                   const float* __restrict__ w, const float* __restrict__ bb, float* __restrict__ out,
                   __nv_bfloat16* __restrict__ oh, __nv_bfloat16* __restrict__ ol)
{ LN_BODY(x[base+d] + y[base+d]) }
__global__ __launch_bounds__(256)
void add_ln3_kernel(const float* __restrict__ x1, const float* __restrict__ x2, const float* __restrict__ y,
                    const float* __restrict__ w, const float* __restrict__ bb, float* __restrict__ out,
                    __nv_bfloat16* __restrict__ oh, __nv_bfloat16* __restrict__ ol)
{ LN_BODY(x1[base+d] + x2[base+d] + y[base+d]) }

// ---- metric path ----
__global__ __launch_bounds__(256)
void pool_kernel(const float* __restrict__ h, float* __restrict__ hmean)
{
    int b = blockIdx.x, c0 = blockIdx.y * 128, tid = threadIdx.x;
    int col = c0 + (tid & 127), rg = tid >> 7;
    __shared__ float part[256];
    float s = 0.f;
    for (int t = rg*256; t < rg*256 + 256; t++) s += h[((size_t)b*SS + t)*DD + col];
    part[tid] = s; __syncthreads();
    if (tid < 128) hmean[b*DD + col] = (part[tid] + part[tid+128]) * (1.0f/SS);
}
__global__ __launch_bounds__(256)
void cw_kernel(const float* __restrict__ hmean, const float* __restrict__ Wcp,
               const float* __restrict__ bcp, float* __restrict__ cw)
{
    int b = blockIdx.x, tid = threadIdx.x;
    __shared__ float hm[DD]; __shared__ float part[256];
    for (int i = tid; i < DD; i += 256) hm[i] = hmean[b*DD + i];
    __syncthreads();
    int j = tid & 63, d0 = (tid >> 6) * 192;
    float acc = 0.f;
    #pragma unroll 4
    for (int d = d0; d < d0 + 192; d++) acc = fmaf(hm[d], Wcp[(size_t)d*DD + j], acc);
    part[tid] = acc; __syncthreads();
    if (tid < 64) {
        float y = bcp[tid] + part[tid] + part[tid+64] + part[tid+128] + part[tid+192];
        cw[b*HDD + tid] = 1.f / (1.f + expf(-y));
    }
}
__global__ __launch_bounds__(256)
void ginv_kernel(const float* __restrict__ Lm_l, const float* __restrict__ diag_l,
                 const float* __restrict__ cw, float* __restrict__ ginv)
{
    int b = blockIdx.x, tid = threadIdx.x;
    __shared__ float L[64][64]; __shared__ float A[64][65]; __shared__ float fcol[64];
    for (int it = 0; it < 16; it++) { int idx = it*256+tid; L[idx>>6][idx&63] = Lm_l[idx] * cw[b*HDD + (idx>>6)]; }
    __syncthreads();
    for (int it = 0; it < 16; it++) {
        int idx = it*256+tid, i = idx>>6, j = idx&63;
        float s = 0.f;
        for (int t2 = 0; t2 < 64; t2++) s = fmaf(L[i][t2], L[j][t2], s);
        if (i == j) s += diag_l[i] + 1e-6f + 0.1f;
        A[i][j] = s;
    }
    __syncthreads();
    for (int it = 0; it < 16; it++) { int idx = it*256+tid; L[idx>>6][idx&63] = ((idx>>6)==(idx&63)) ? 1.f : 0.f; }
    __syncthreads();
    for (int p = 0; p < 64; p++) {
        float ip = 1.f / A[p][p];
        float myf = (tid < 64) ? A[tid][p] : 0.f;
        __syncthreads();
        if (tid < 64) A[p][tid] *= ip; else if (tid < 128) L[p][tid-64] *= ip;
        if (tid < 64) fcol[tid] = (tid == p) ? 0.f : myf;
        __syncthreads();
        for (int it = 0; it < 32; it++) {
            int idx = it*256+tid, r = idx>>7, c = idx&127;
            if (r != p) { if (c < 64) A[r][c] -= fcol[r]*A[p][c]; else L[r][c-64] -= fcol[r]*L[p][c-64]; }
        }
        __syncthreads();
    }
    for (int it = 0; it < 16; it++) { int idx = it*256+tid; ginv[b*(HDD*HDD) + idx] = L[idx>>6][idx&63]; }
}
__global__ __launch_bounds__(256)
void qg_kernel(const float* __restrict__ q, const float* __restrict__ ginv, float* __restrict__ qg)
{
    int m0 = blockIdx.x * 64, h = blockIdx.y, b = m0 / SS, tid = threadIdx.x;
    __shared__ float Qt[64][65]; __shared__ float G[64][65];
    const float* gb = ginv + b * (HDD*HDD);
    #pragma unroll
    for (int it = 0; it < 16; it++) {
        int idx = it*256+tid, r = idx>>6, c = idx&63;
        Qt[c][r] = q[(size_t)(m0+r)*DD + h*HDD + c];
        G[r][c] = gb[idx];
    }
    __syncthreads();
    int tx = tid & 15, ty = tid >> 4;
    float acc[4][4] = {};
    for (int d = 0; d < 64; d++) {
        float a[4], bb2[4];
        #pragma unroll
        for (int i = 0; i < 4; i++) a[i] = Qt[d][ty*4+i];
        #pragma unroll
        for (int j = 0; j < 4; j++) bb2[j] = G[d][tx*4+j];
        #pragma unroll
        for (int i = 0; i < 4; i++)
            #pragma unroll
            for (int j = 0; j < 4; j++) acc[i][j] = fmaf(a[i], bb2[j], acc[i][j]);
    }
    #pragma unroll
    for (int i = 0; i < 4; i++)
        #pragma unroll
        for (int j = 0; j < 4; j++)
            qg[(size_t)(m0+ty*4+i)*DD + h*HDD + tx*4+j] = acc[i][j];
}

// ---- attention (unchanged from R7) ----
#define SCR 72
__global__ __launch_bounds__(256)
void scores_mma_kernel(const float* __restrict__ qg, const float* __restrict__ k, float* __restrict__ sc)
{
    int bh = blockIdx.z, b = bh / NHH, h = bh % NHH;
    int i0 = blockIdx.y * 64, j0 = blockIdx.x * 64;
    __shared__ __nv_bfloat16 Q0[64*SCR], Q1[64*SCR], K0s[64*SCR], K1s[64*SCR];
    const int tid = threadIdx.x, warp = tid >> 5, lane = tid & 31;
    #pragma unroll
    for (int it = 0; it < 4; it++) {
        int f = it*256 + tid, row = f >> 4, col = (f & 15) * 4;
        split4(*(const float4*)&qg[(size_t)(b*SS+i0+row)*DD + h*HDD + col], Q0, Q1, row*SCR + col);
        split4(*(const float4*)&k [(size_t)(b*SS+j0+row)*DD + h*HDD + col], K0s, K1s, row*SCR + col);
    }
    __syncthreads();
    const uint32_t q0b = (uint32_t)__cvta_generic_to_shared(Q0), q1b = (uint32_t)__cvta_generic_to_shared(Q1);
    const uint32_t k0b = (uint32_t)__cvta_generic_to_shared(K0s), k1b = (uint32_t)__cvta_generic_to_shared(K1s);
    const int wm = (warp & 3) * 16, wn = (warp >> 2) * 32;
    float acc[4][4] = {};
    #pragma unroll
    for (int ks = 0; ks < 4; ks++) {
        uint32_t aoff = (uint32_t)(((wm + (lane&15))*SCR + ks*16 + ((lane>>4)<<3))*2);
        uint32_t a0[4], a1[4];
        ldsm_x4(a0[0],a0[1],a0[2],a0[3], q0b+aoff);
        ldsm_x4(a1[0],a1[1],a1[2],a1[3], q1b+aoff);
        uint32_t b0f[4][2], b1f[4][2];
        #pragma unroll
        for (int jt = 0; jt < 2; jt++) {
            uint32_t boff = (uint32_t)(((wn + jt*16 + (lane&15))*SCR + ks*16 + ((lane>>4)<<3))*2);
            uint32_t r0,r1,r2,r3;
            ldsm_x4(r0,r1,r2,r3, k0b+boff);
            b0f[jt*2][0]=r0; b0f[jt*2][1]=r2; b0f[jt*2+1][0]=r1; b0f[jt*2+1][1]=r3;
            ldsm_x4(r0,r1,r2,r3, k1b+boff);
            b1f[jt*2][0]=r0; b1f[jt*2][1]=r2; b1f[jt*2+1][0]=r1; b1f[jt*2+1][1]=r3;
        }
        #pragma unroll
        for (int n = 0; n < 4; n++) { mma_bf16(acc[n],a0,b0f[n]); mma_bf16(acc[n],a0,b1f[n]); mma_bf16(acc[n],a1,b0f[n]); }
    }
    int r0 = i0 + wm + (lane >> 2);
    #pragma unroll
    for (int n = 0; n < 4; n++) {
        int c0 = j0 + wn + n*8 + (lane&3)*2;
        *(float2*)&sc[((size_t)bh*SS + r0)*SS + c0]   = make_float2(acc[n][0]*0.125f, acc[n][1]*0.125f);
        *(float2*)&sc[((size_t)bh*SS + r0+8)*SS + c0] = make_float2(acc[n][2]*0.125f, acc[n][3]*0.125f);
    }
}
__global__ __launch_bounds__(256)
void softmax_kernel(float* __restrict__ sc)
{
    int warp = threadIdx.x >> 5, lane = threadIdx.x & 31;
    float* p = sc + ((size_t)blockIdx.x * 8 + warp) * SS;
    float4 v[4]; float mx = -1e30f;
    #pragma unroll
    for (int i = 0; i < 4; i++) {
        v[i] = ((float4*)p)[lane + i*32];
        mx = fmaxf(mx, fmaxf(fmaxf(v[i].x, v[i].y), fmaxf(v[i].z, v[i].w)));
    }
    #pragma unroll
    for (int o = 16; o > 0; o >>= 1) mx = fmaxf(mx, __shfl_xor_sync(~0u, mx, o));
    float sum = 0.f;
    #pragma unroll
    for (int i = 0; i < 4; i++) {
        v[i].x = expf(v[i].x-mx); v[i].y = expf(v[i].y-mx); v[i].z = expf(v[i].z-mx); v[i].w = expf(v[i].w-mx);
        sum += v[i].x + v[i].y + v[i].z + v[i].w;
    }
    #pragma unroll
    for (int o = 16; o > 0; o >>= 1) sum += __shfl_xor_sync(~0u, sum, o);
    float inv = 1.f / sum;
    #pragma unroll
    for (int i = 0; i < 4; i++) { v[i].x *= inv; v[i].y *= inv; v[i].z *= inv; v[i].w *= inv; ((float4*)p)[lane + i*32] = v[i]; }
}
__global__ __launch_bounds__(256)
void ctx_mma_kernel(const float* __restrict__ attn, const float* __restrict__ v, float* __restrict__ ctx)
{
    int bh = blockIdx.y, b = bh / NHH, h = bh % NHH, i0 = blockIdx.x * 64;
    __shared__ __nv_bfloat16 P0[64*SCR], P1[64*SCR], V0[64*SCR], V1[64*SCR];
    const int tid = threadIdx.x, warp = tid >> 5, lane = tid & 31;
    const int wm = (warp & 3) * 16, wn = (warp >> 2) * 32;
    const uint32_t p0b = (uint32_t)__cvta_generic_to_shared(P0), p1b = (uint32_t)__cvta_generic_to_shared(P1);
    const uint32_t v0b = (uint32_t)__cvta_generic_to_shared(V0), v1b = (uint32_t)__cvta_generic_to_shared(V1);
    float acc[4][4] = {};
    for (int jt8 = 0; jt8 < 8; jt8++) {
        int j0 = jt8 * 64;
        #pragma unroll
        for (int it = 0; it < 4; it++) {
            int f = it*256 + tid, row = f >> 4, col = (f & 15) * 4;
            split4(*(const float4*)&attn[((size_t)bh*SS + i0+row)*SS + j0 + col], P0, P1, row*SCR + col);
            split4(*(const float4*)&v[(size_t)(b*SS + j0+row)*DD + h*HDD + col], V0, V1, row*SCR + col);
        }
        __syncthreads();
        #pragma unroll
        for (int ks = 0; ks < 4; ks++) {
            uint32_t aoff = (uint32_t)(((wm + (lane&15))*SCR + ks*16 + ((lane>>4)<<3))*2);
            uint32_t a0[4], a1[4];
            ldsm_x4(a0[0],a0[1],a0[2],a0[3], p0b+aoff);
            ldsm_x4(a1[0],a1[1],a1[2],a1[3], p1b+aoff);
            uint32_t b0f[4][2], b1f[4][2];
            #pragma unroll
            for (int jt = 0; jt < 2; jt++) {
                uint32_t boff = (uint32_t)(((ks*16 + (lane&15))*SCR + wn + jt*16 + ((lane>>4)<<3))*2);
                uint32_t r0,r1,r2,r3;
                ldsm_x4_t(r0,r1,r2,r3, v0b+boff);
                b0f[jt*2][0]=r0; b0f[jt*2][1]=r1; b0f[jt*2+1][0]=r2; b0f[jt*2+1][1]=r3;
                ldsm_x4_t(r0,r1,r2,r3, v1b+boff);
                b1f[jt*2][0]=r0; b1f[jt*2][1]=r1; b1f[jt*2+1][0]=r2; b1f[jt*2+1][1]=r3;
            }
            #pragma unroll
            for (int n = 0; n < 4; n++) { mma_bf16(acc[n],a0,b0f[n]); mma_bf16(acc[n],a0,b1f[n]); mma_bf16(acc[n],a1,b0f[n]); }
        }
        __syncthreads();
    }
    int r0 = i0 + wm + (lane >> 2);
    #pragma unroll
    for (int n = 0; n < 4; n++) {
        int c0 = h*HDD + wn + n*8 + (lane&3)*2;
        *(float2*)&ctx[(size_t)(b*SS + r0)*DD + c0]   = make_float2(acc[n][0], acc[n][1]);
        *(float2*)&ctx[(size_t)(b*SS + r0+8)*DD + c0] = make_float2(acc[n][2], acc[n][3]);
    }
}

#define SYM(p, s) cudaGetSymbolAddress((void**)&p, s)

extern "C" void kernel_launch(void* const* d_in, const int* in_sizes, int n_in, void* d_out, int out_size)
{
    const int* ids = (const int*)d_in[0];
    const int* tts = (const int*)d_in[1];
    const float* we = (const float*)d_in[2];
    const float* pe = (const float*)d_in[3];
    const float* te = (const float*)d_in[4];
    const float* lnew = (const float*)d_in[5];
    const float* lneb = (const float*)d_in[6];
    const float* Wq = (const float*)d_in[7];
    const float* bq = (const float*)d_in[8];
    const float* Wk = (const float*)d_in[9];
    const float* bk = (const float*)d_in[10];
    const float* Wv = (const float*)d_in[11];
    const float* bv = (const float*)d_in[12];
    const float* Lm = (const float*)d_in[13];
    const float* dg = (const float*)d_in[14];
    const float* Wcp = (const float*)d_in[15];
    const float* bcp = (const float*)d_in[16];
    const float* Wi = (const float*)d_in[17];
    const float* bi = (const float*)d_in[18];
    const float* Wo = (const float*)d_in[19];
    const float* bo = (const float*)d_in[20];
    const float* l1w = (const float*)d_in[21];
    const float* l1b = (const float*)d_in[22];
    const float* l2w = (const float*)d_in[23];
    const float* l2b = (const float*)d_in[24];

    float *h,*q,*k,*v,*qg,*attn,*ctx,*a,*f,*o,*o2,*hmean,*cw,*ginv;
    __nv_bfloat16 *wqh,*wql,*wkh,*wkl,*wvh,*wvl,*wih,*wil,*woh,*wol,*hh,*hl,*ah,*al,*fh,*fl;
    SYM(h,g_h); SYM(q,g_q); SYM(k,g_k); SYM(v,g_v); SYM(qg,g_qg); SYM(attn,g_attn);
    SYM(ctx,g_ctx); SYM(a,g_a); SYM(f,g_f); SYM(o,g_o); SYM(o2,g_o2);
    SYM(hmean,g_hmean); SYM(cw,g_cw); SYM(ginv,g_ginv);
    SYM(wqh,g_wq_h); SYM(wql,g_wq_l); SYM(wkh,g_wk_h); SYM(wkl,g_wk_l);
    SYM(wvh,g_wv_h); SYM(wvl,g_wv_l); SYM(wih,g_wi_h); SYM(wil,g_wi_l);
    SYM(woh,g_wo_h); SYM(wol,g_wo_l);
    SYM(hh,g_hh); SYM(hl,g_hl); SYM(ah,g_ah); SYM(al,g_al); SYM(fh,g_fh); SYM(fl,g_fl);

    cudaFuncSetAttribute(gemm_kernel,        cudaFuncAttributeMaxDynamicSharedMemorySize, G_SMEM);
    cudaFuncSetAttribute(gemm_qkv_kernel,    cudaFuncAttributeMaxDynamicSharedMemorySize, G_SMEM);
    cudaFuncSetAttribute(gemm_splitk_kernel, cudaFuncAttributeMaxDynamicSharedMemorySize, G_SMEM);

    // pre-split all weights (once per launch; deterministic)
    split_w_kernel<<<1024, 256>>>(Wq, wqh, wql, NLL*DD*DD/4);
    split_w_kernel<<<1024, 256>>>(Wk, wkh, wkl, NLL*DD*DD/4);
    split_w_kernel<<<1024, 256>>>(Wv, wvh, wvl, NLL*DD*DD/4);
    split_w_kernel<<<2048, 256>>>(Wi, wih, wil, NLL*DD*FFF/4);
    split_w_kernel<<<2048, 256>>>(Wo, woh, wol, NLL*FFF*DD/4);

    embed_ln_kernel<<<MT, 256>>>(ids, tts, we, pe, te, lnew, lneb, h, hh, hl);

    for (int l = 0; l < NLL; l++) {
        size_t od = (size_t)l*DD*DD, of = (size_t)l*DD*FFF;

        gemm_qkv_kernel<<<dim3(18, 32), 256, G_SMEM>>>(hh, hl, wqh+od, wql+od, wkh+od, wkl+od,
            wvh+od, wvl+od, bq + l*DD, bk + l*DD, bv + l*DD, q, k, v);

        pool_kernel<<<dim3(BB, 6), 256>>>(h, hmean);
        cw_kernel<<<BB, 256>>>(hmean, Wcp + od, bcp + l*DD, cw);
        ginv_kernel<<<BB, 256>>>(Lm + (size_t)l*DD*64, dg + l*DD, cw, ginv);

        qg_kernel<<<dim3(MT/64, NHH), 256>>>(q, ginv, qg);
        scores_mma_kernel<<<dim3(SS/64, SS/64, BB*NHH), 256>>>(qg, k, attn);
        softmax_kernel<<<BB*NHH*SS/8, 256>>>(attn);
        ctx_mma_kernel<<<dim3(SS/64, BB*NHH), 256>>>(attn, v, ctx);

        add_ln_kernel<<<MT, 256>>>(ctx, h, l1w + l*DD, l1b + l*DD, a, ah, al);

        gemm_kernel<<<dim3(FFF/128, 32), 256, G_SMEM>>>(ah, al, wih+of, wil+of,
            bi + (size_t)l*FFF, f, fh, fl, FFF, DD, 1);
        gemm_splitk_kernel<<<dim3(DD/128, 32, 2), 256, G_SMEM>>>(fh, fl, woh+of, wol+of,
            bo + l*DD, o, o2);

        float* out_h = (l == NLL-1) ? (float*)d_out : h;
        add_ln3_kernel<<<MT, 256>>>(o, o2, a, l2w + l*DD, l2b + l*DD, out_h,
                                    (l == NLL-1) ? nullptr : hh, (l == NLL-1) ? nullptr : hl);
    }
}

// round 13
// speedup vs baseline: 2.7781x; 1.0591x over previous
#include <cuda_runtime.h>
#include <cuda_bf16.h>
#include <stdint.h>
#include <math.h>

#define BB 8
#define SS 512
#define DD 768
#define NHH 12
#define HDD 64
#define FFF 3072
#define NLL 12
#define MT (BB*SS)

__device__ float g_h[MT*DD];
__device__ float g_q[MT*DD];
__device__ float g_k[MT*DD];
__device__ float g_v[MT*DD];
__device__ float g_qg[MT*DD];
__device__ float g_ctx[MT*DD];
__device__ float g_a[MT*DD];
__device__ float g_f[MT*FFF];
__device__ float g_o[MT*DD];
__device__ float g_o2[MT*DD];
__device__ float g_hmean[BB*DD];
__device__ float g_cw[BB*HDD];
__device__ float g_ginv[BB*HDD*HDD];
__device__ __nv_bfloat16 g_wq_h[NLL*DD*DD], g_wq_l[NLL*DD*DD];
__device__ __nv_bfloat16 g_wk_h[NLL*DD*DD], g_wk_l[NLL*DD*DD];
__device__ __nv_bfloat16 g_wv_h[NLL*DD*DD], g_wv_l[NLL*DD*DD];
__device__ __nv_bfloat16 g_wi_h[(size_t)NLL*DD*FFF], g_wi_l[(size_t)NLL*DD*FFF];
__device__ __nv_bfloat16 g_wo_h[(size_t)NLL*FFF*DD], g_wo_l[(size_t)NLL*FFF*DD];
__device__ __nv_bfloat16 g_hh[MT*DD], g_hl[MT*DD];
__device__ __nv_bfloat16 g_ah[MT*DD], g_al[MT*DD];
__device__ __nv_bfloat16 g_fh[MT*FFF], g_fl[MT*FFF];

__device__ __forceinline__ void ldsm_x4(uint32_t& r0, uint32_t& r1, uint32_t& r2, uint32_t& r3, uint32_t a)
{ asm volatile("ldmatrix.sync.aligned.m8n8.x4.shared.b16 {%0,%1,%2,%3},[%4];" : "=r"(r0),"=r"(r1),"=r"(r2),"=r"(r3) : "r"(a)); }
__device__ __forceinline__ void ldsm_x4_t(uint32_t& r0, uint32_t& r1, uint32_t& r2, uint32_t& r3, uint32_t a)
{ asm volatile("ldmatrix.sync.aligned.m8n8.x4.trans.shared.b16 {%0,%1,%2,%3},[%4];" : "=r"(r0),"=r"(r1),"=r"(r2),"=r"(r3) : "r"(a)); }
__device__ __forceinline__ void mma_bf16(float* c, const uint32_t* a, const uint32_t* b)
{ asm volatile("mma.sync.aligned.m16n8k16.row.col.f32.bf16.bf16.f32 {%0,%1,%2,%3},{%4,%5,%6,%7},{%8,%9},{%0,%1,%2,%3};"
               : "+f"(c[0]),"+f"(c[1]),"+f"(c[2]),"+f"(c[3])
               : "r"(a[0]),"r"(a[1]),"r"(a[2]),"r"(a[3]),"r"(b[0]),"r"(b[1])); }
__device__ __forceinline__ void split4(const float4 v, __nv_bfloat16* S0, __nv_bfloat16* S1, int o)
{
    __nv_bfloat162 h01 = __floats2bfloat162_rn(v.x, v.y), h23 = __floats2bfloat162_rn(v.z, v.w);
    *(__nv_bfloat162*)(S0+o) = h01; *(__nv_bfloat162*)(S0+o+2) = h23;
    __nv_bfloat162 l01 = __floats2bfloat162_rn(v.x-__low2float(h01), v.y-__high2float(h01));
    __nv_bfloat162 l23 = __floats2bfloat162_rn(v.z-__low2float(h23), v.w-__high2float(h23));
    *(__nv_bfloat162*)(S1+o) = l01; *(__nv_bfloat162*)(S1+o+2) = l23;
}
__device__ __forceinline__ float gelu(float x) { return 0.5f*x*(1.f+erff(x*0.70710678118654752f)); }
__device__ __forceinline__ uint32_t packpair(float x, float y, uint32_t& lo)
{
    __nv_bfloat162 h = __floats2bfloat162_rn(x, y);
    __nv_bfloat162 l = __floats2bfloat162_rn(x-__low2float(h), y-__high2float(h));
    lo = *(uint32_t*)&l; return *(uint32_t*)&h;
}
__device__ __forceinline__ void cp16(uint32_t s, const void* g)
{ asm volatile("cp.async.cg.shared.global [%0],[%1],16;" :: "r"(s),"l"(g) : "memory"); }

__global__ __launch_bounds__(256)
void split_w_kernel(const float* __restrict__ src, __nv_bfloat16* __restrict__ dh,
                    __nv_bfloat16* __restrict__ dl, int n4)
{
    for (int i = blockIdx.x*256 + threadIdx.x; i < n4; i += gridDim.x*256) {
        float4 v = ((const float4*)src)[i];
        uint32_t l0, h0 = packpair(v.x, v.y, l0);
        uint32_t l1, h1 = packpair(v.z, v.w, l1);
        ((uint32_t*)dh)[i*2] = h0; ((uint32_t*)dh)[i*2+1] = h1;
        ((uint32_t*)dl)[i*2] = l0; ((uint32_t*)dl)[i*2+1] = l1;
    }
}

// ================= GEMM (unchanged from R10) ================
#define GRA 40
#define GRB 136
#define GASZ (128*GRA)
#define GBSZ (32*GRB)
#define GSTG_B ((2*GASZ + 2*GBSZ)*2)
#define G_SMEM (2*GSTG_B)

__device__ __forceinline__ void gemm_core(
    const __nv_bfloat16* Ah, const __nv_bfloat16* Al, int lda,
    const __nv_bfloat16* Wh, const __nv_bfloat16* Wl, int ldw,
    const float* bias, float* C, __nv_bfloat16* Ch, __nv_bfloat16* Cl, int ldc,
    int K, int act, int bm, int bn, int addb)
{
    extern __shared__ char smem[];
    const int tid = threadIdx.x, warp = tid >> 5, lane = tid & 31;
    const int wm = (warp & 3) * 32, wn = (warp >> 2) * 64;
    const uint32_t sb = (uint32_t)__cvta_generic_to_shared(smem);
    const int KT = K >> 5;
    float acc[2][8][4] = {};

    #define ISSUE(buf, k0) do { \
        uint32_t st = sb + (uint32_t)(buf)*GSTG_B; \
        _Pragma("unroll") for (int kk = 0; kk < 2; kk++) { \
            int ch = tid + kk*256; \
            int r = ch >> 2, o = (ch & 3) * 8; \
            uint32_t d = st + (uint32_t)(r*GRA + o)*2; \
            cp16(d,          Ah + (size_t)(bm+r)*lda + (k0) + o); \
            cp16(d + GASZ*2, Al + (size_t)(bm+r)*lda + (k0) + o); \
            int r2 = ch >> 4, o2 = (ch & 15) * 8; \
            uint32_t d2 = st + (uint32_t)(2*GASZ + r2*GRB + o2)*2; \
            cp16(d2,          Wh + (size_t)((k0)+r2)*ldw + bn + o2); \
            cp16(d2 + GBSZ*2, Wl + (size_t)((k0)+r2)*ldw + bn + o2); \
        } \
        asm volatile("cp.async.commit_group;" ::: "memory"); \
    } while(0)

    ISSUE(0, 0);
    for (int t = 0; t < KT; t++) {
        if (t + 1 < KT) { ISSUE((t+1)&1, (t+1)*32); asm volatile("cp.async.wait_group 1;" ::: "memory"); }
        else            { asm volatile("cp.async.wait_group 0;" ::: "memory"); }
        __syncthreads();
        uint32_t base = sb + (uint32_t)(t & 1) * GSTG_B;
        uint32_t a0b = base, a1b = base + GASZ*2, b0b = base + 2*GASZ*2, b1b = base + (2*GASZ+GBSZ)*2;
        #pragma unroll
        for (int ks = 0; ks < 2; ks++) {
            uint32_t a0[2][4], a1[2][4];
            #pragma unroll
            for (int i = 0; i < 2; i++) {
                uint32_t off = (uint32_t)(((wm + i*16 + (lane&15))*GRA + ks*16 + ((lane>>4)<<3))*2);
                ldsm_x4(a0[i][0],a0[i][1],a0[i][2],a0[i][3], a0b+off);
                ldsm_x4(a1[i][0],a1[i][1],a1[i][2],a1[i][3], a1b+off);
            }
            #pragma unroll
            for (int j = 0; j < 4; j++) {
                uint32_t boff = (uint32_t)(((ks*16 + (lane&15))*GRB + wn + j*16 + ((lane>>4)<<3))*2);
                uint32_t h0,h1,h2,h3, l0,l1,l2,l3;
                ldsm_x4_t(h0,h1,h2,h3, b0b+boff);
                ldsm_x4_t(l0,l1,l2,l3, b1b+boff);
                uint32_t bh0[2]={h0,h1}, bh1[2]={h2,h3}, bl0[2]={l0,l1}, bl1[2]={l2,l3};
                #pragma unroll
                for (int i = 0; i < 2; i++) {
                    mma_bf16(acc[i][j*2],   a0[i], bh0); mma_bf16(acc[i][j*2],   a0[i], bl0); mma_bf16(acc[i][j*2],   a1[i], bh0);
                    mma_bf16(acc[i][j*2+1], a0[i], bh1); mma_bf16(acc[i][j*2+1], a0[i], bl1); mma_bf16(acc[i][j*2+1], a1[i], bh1);
                }
            }
        }
        __syncthreads();
    }
    #undef ISSUE

    #pragma unroll
    for (int i = 0; i < 2; i++) {
        int r0 = bm + wm + i*16 + (lane >> 2);
        #pragma unroll
        for (int j = 0; j < 8; j++) {
            int c0 = bn + wn + j*8 + (lane & 3)*2;
            float b0v = addb ? bias[c0] : 0.f, b1v = addb ? bias[c0+1] : 0.f;
            float v0 = acc[i][j][0]+b0v, v1 = acc[i][j][1]+b1v;
            float v2 = acc[i][j][2]+b0v, v3 = acc[i][j][3]+b1v;
            if (act) { v0 = gelu(v0); v1 = gelu(v1); v2 = gelu(v2); v3 = gelu(v3); }
            *(float2*)&C[(size_t)r0*ldc + c0]     = make_float2(v0, v1);
            *(float2*)&C[(size_t)(r0+8)*ldc + c0] = make_float2(v2, v3);
            if (Ch) {
                uint32_t lo, hi = packpair(v0, v1, lo);
                *(uint32_t*)&Ch[(size_t)r0*ldc + c0] = hi; *(uint32_t*)&Cl[(size_t)r0*ldc + c0] = lo;
                hi = packpair(v2, v3, lo);
                *(uint32_t*)&Ch[(size_t)(r0+8)*ldc + c0] = hi; *(uint32_t*)&Cl[(size_t)(r0+8)*ldc + c0] = lo;
            }
        }
    }
}

__global__ __launch_bounds__(256, 2)
void gemm_kernel(const __nv_bfloat16* __restrict__ Ah, const __nv_bfloat16* __restrict__ Al,
                 const __nv_bfloat16* __restrict__ Wh, const __nv_bfloat16* __restrict__ Wl,
                 const float* __restrict__ bias, float* __restrict__ C,
                 __nv_bfloat16* __restrict__ Ch, __nv_bfloat16* __restrict__ Cl, int N, int K, int act)
{ gemm_core(Ah, Al, K, Wh, Wl, N, bias, C, Ch, Cl, N, K, act, blockIdx.y*128, blockIdx.x*128, 1); }

__global__ __launch_bounds__(256, 2)
void gemm_qkv_kernel(const __nv_bfloat16* __restrict__ Ah, const __nv_bfloat16* __restrict__ Al,
                     const __nv_bfloat16* Wqh, const __nv_bfloat16* Wql,
                     const __nv_bfloat16* Wkh, const __nv_bfloat16* Wkl,
                     const __nv_bfloat16* Wvh, const __nv_bfloat16* Wvl,
                     const float* b0, const float* b1, const float* b2,
                     float* C0, float* C1, float* C2)
{
    int sel = blockIdx.x / 6, bn = (blockIdx.x % 6) * 128;
    gemm_core(Ah, Al, DD, sel==0?Wqh:sel==1?Wkh:Wvh, sel==0?Wql:sel==1?Wkl:Wvl, DD,
              sel==0?b0:sel==1?b1:b2, sel==0?C0:sel==1?C1:C2, nullptr, nullptr, DD,
              DD, 0, blockIdx.y*128, bn, 1);
}

__global__ __launch_bounds__(256, 2)
void gemm_splitk_kernel(const __nv_bfloat16* __restrict__ Ah, const __nv_bfloat16* __restrict__ Al,
                        const __nv_bfloat16* __restrict__ Wh, const __nv_bfloat16* __restrict__ Wl,
                        const float* __restrict__ bias, float* __restrict__ C0, float* __restrict__ C1)
{
    int z = blockIdx.z;
    gemm_core(Ah + z*(FFF/2), Al + z*(FFF/2), FFF,
              Wh + (size_t)(z*(FFF/2))*DD, Wl + (size_t)(z*(FFF/2))*DD, DD,
              bias, z ? C1 : C0, nullptr, nullptr, DD, FFF/2, 0, blockIdx.y*128, blockIdx.x*128, z == 0);
}

// ================= fused flash attention ================
// grid (SS/128, BB*NHH), 256 thr. Each warp owns 16 q-rows, loops all j-tiles.
#define SCR 72
#define FQ0 0
#define FQ1 (128*SCR)
#define FK0 (2*128*SCR)
#define FK1 (FK0 + 64*SCR)
#define FV0 (FK0 + 2*64*SCR)
#define FV1 (FK0 + 3*64*SCR)
#define FL_SMEM ((2*128*SCR + 4*64*SCR)*2)

__global__ __launch_bounds__(256, 1)
void flash_kernel(const float* __restrict__ qg, const float* __restrict__ k,
                  const float* __restrict__ v, float* __restrict__ ctx)
{
    extern __shared__ __nv_bfloat16 fs[];
    const int bh = blockIdx.y, b = bh / NHH, h = bh % NHH;
    const int i0 = blockIdx.x * 128;
    const int tid = threadIdx.x, warp = tid >> 5, lane = tid & 31;
    const int wm = warp * 16;

    // stage Q (128x64) hi/lo
    #pragma unroll
    for (int it = 0; it < 8; it++) {
        int f = it*256 + tid, row = f >> 4, col = (f & 15) * 4;
        split4(*(const float4*)&qg[(size_t)(b*SS + i0 + row)*DD + h*HDD + col], fs+FQ0, fs+FQ1, row*SCR + col);
    }

    const uint32_t q0b = (uint32_t)__cvta_generic_to_shared(fs+FQ0);
    const uint32_t q1b = (uint32_t)__cvta_generic_to_shared(fs+FQ1);
    const uint32_t k0b = (uint32_t)__cvta_generic_to_shared(fs+FK0);
    const uint32_t k1b = (uint32_t)__cvta_generic_to_shared(fs+FK1);
    const uint32_t v0b = (uint32_t)__cvta_generic_to_shared(fs+FV0);
    const uint32_t v1b = (uint32_t)__cvta_generic_to_shared(fs+FV1);

    float m0 = -1e30f, m1 = -1e30f, l0 = 0.f, l1 = 0.f;
    float acc[8][4] = {};

    for (int j0 = 0; j0 < SS; j0 += 64) {
        __syncthreads();
        // stage K,V (64x64 each) hi/lo
        #pragma unroll
        for (int it = 0; it < 4; it++) {
            int f = it*256 + tid, row = f >> 4, col = (f & 15) * 4;
            split4(*(const float4*)&k[(size_t)(b*SS + j0 + row)*DD + h*HDD + col], fs+FK0, fs+FK1, row*SCR + col);
            split4(*(const float4*)&v[(size_t)(b*SS + j0 + row)*DD + h*HDD + col], fs+FV0, fs+FV1, row*SCR + col);
        }
        __syncthreads();

        // S = QG @ K^T / 8  (bf16x3) : 8 n-frags over 64 j-cols
        float s[8][4] = {};
        #pragma unroll
        for (int ks = 0; ks < 4; ks++) {
            uint32_t aoff = (uint32_t)(((wm + (lane&15))*SCR + ks*16 + ((lane>>4)<<3))*2);
            uint32_t a0[4], a1[4];
            ldsm_x4(a0[0],a0[1],a0[2],a0[3], q0b+aoff);
            ldsm_x4(a1[0],a1[1],a1[2],a1[3], q1b+aoff);
            #pragma unroll
            for (int jt = 0; jt < 4; jt++) {
                uint32_t boff = (uint32_t)(((jt*16 + (lane&15))*SCR + ks*16 + ((lane>>4)<<3))*2);
                uint32_t r0,r1,r2,r3;
                uint32_t bh0[2], bh1[2], bl0[2], bl1[2];
                ldsm_x4(r0,r1,r2,r3, k0b+boff);
                bh0[0]=r0; bh0[1]=r2; bh1[0]=r1; bh1[1]=r3;
                ldsm_x4(r0,r1,r2,r3, k1b+boff);
                bl0[0]=r0; bl0[1]=r2; bl1[0]=r1; bl1[1]=r3;
                mma_bf16(s[jt*2],   a0, bh0); mma_bf16(s[jt*2],   a0, bl0); mma_bf16(s[jt*2],   a1, bh0);
                mma_bf16(s[jt*2+1], a0, bh1); mma_bf16(s[jt*2+1], a0, bl1); mma_bf16(s[jt*2+1], a1, bh1);
            }
        }
        // online softmax (rows r = lane>>2 and r+8, fully warp-local via quad shuffles)
        float mt0 = -1e30f, mt1 = -1e30f;
        #pragma unroll
        for (int n = 0; n < 8; n++) {
            s[n][0] *= 0.125f; s[n][1] *= 0.125f; s[n][2] *= 0.125f; s[n][3] *= 0.125f;
            mt0 = fmaxf(mt0, fmaxf(s[n][0], s[n][1]));
            mt1 = fmaxf(mt1, fmaxf(s[n][2], s[n][3]));
        }
        #pragma unroll
        for (int o = 1; o < 4; o <<= 1) {
            mt0 = fmaxf(mt0, __shfl_xor_sync(~0u, mt0, o));
            mt1 = fmaxf(mt1, __shfl_xor_sync(~0u, mt1, o));
        }
        float mn0 = fmaxf(m0, mt0), mn1 = fmaxf(m1, mt1);
        float al0 = expf(m0 - mn0), al1 = expf(m1 - mn1);
        float sum0 = 0.f, sum1 = 0.f;
        #pragma unroll
        for (int n = 0; n < 8; n++) {
            s[n][0] = expf(s[n][0]-mn0); s[n][1] = expf(s[n][1]-mn0);
            s[n][2] = expf(s[n][2]-mn1); s[n][3] = expf(s[n][3]-mn1);
            sum0 += s[n][0] + s[n][1]; sum1 += s[n][2] + s[n][3];
        }
        #pragma unroll
        for (int o = 1; o < 4; o <<= 1) {
            sum0 += __shfl_xor_sync(~0u, sum0, o);
            sum1 += __shfl_xor_sync(~0u, sum1, o);
        }
        m0 = mn0; m1 = mn1;
        l0 = l0*al0 + sum0; l1 = l1*al1 + sum1;
        #pragma unroll
        for (int n = 0; n < 8; n++) {
            acc[n][0] *= al0; acc[n][1] *= al0; acc[n][2] *= al1; acc[n][3] *= al1;
        }
        // P @ V (bf16x3): A frags from S C-frags (identity packing)
        #pragma unroll
        for (int ks = 0; ks < 4; ks++) {
            uint32_t ph[4], pl[4];
            ph[0] = packpair(s[2*ks][0],   s[2*ks][1],   pl[0]);
            ph[1] = packpair(s[2*ks][2],   s[2*ks][3],   pl[1]);
            ph[2] = packpair(s[2*ks+1][0], s[2*ks+1][1], pl[2]);
            ph[3] = packpair(s[2*ks+1][2], s[2*ks+1][3], pl[3]);
            #pragma unroll
            for (int jt = 0; jt < 4; jt++) {
                uint32_t boff = (uint32_t)(((ks*16 + (lane&15))*SCR + jt*16 + ((lane>>4)<<3))*2);
                uint32_t r0,r1,r2,r3;
                uint32_t bh0[2], bh1[2], bl0[2], bl1[2];
                ldsm_x4_t(r0,r1,r2,r3, v0b+boff);
                bh0[0]=r0; bh0[1]=r1; bh1[0]=r2; bh1[1]=r3;
                ldsm_x4_t(r0,r1,r2,r3, v1b+boff);
                bl0[0]=r0; bl0[1]=r1; bl1[0]=r2; bl1[1]=r3;
                mma_bf16(acc[jt*2],   ph, bh0); mma_bf16(acc[jt*2],   ph, bl0); mma_bf16(acc[jt*2],   pl, bh0);
                mma_bf16(acc[jt*2+1], ph, bh1); mma_bf16(acc[jt*2+1], ph, bl1); mma_bf16(acc[jt*2+1], pl, bh1);
            }
        }
    }
    float il0 = 1.f / l0, il1 = 1.f / l1;
    int r0 = i0 + wm + (lane >> 2);
    #pragma unroll
    for (int n = 0; n < 8; n++) {
        int c0 = h*HDD + n*8 + (lane&3)*2;
        *(float2*)&ctx[(size_t)(b*SS + r0)*DD + c0]   = make_float2(acc[n][0]*il0, acc[n][1]*il0);
        *(float2*)&ctx[(size_t)(b*SS + r0+8)*DD + c0] = make_float2(acc[n][2]*il1, acc[n][3]*il1);
    }
}

// ---- LayerNorm family ----
#define LN_BODY(EXPR) \
    int t = blockIdx.x, tid = threadIdx.x; \
    __shared__ float red[256]; \
    size_t base = (size_t)t * DD; \
    float v[3]; float sum = 0.f; \
    _Pragma("unroll") for (int i = 0; i < 3; i++) { int d = tid + i*256; v[i] = (EXPR); sum += v[i]; } \
    red[tid] = sum; __syncthreads(); \
    for (int o = 128; o > 0; o >>= 1) { if (tid < o) red[tid] += red[tid+o]; __syncthreads(); } \
    float mean = red[0] * (1.0f/DD); __syncthreads(); \
    float vs = 0.f; \
    _Pragma("unroll") for (int i = 0; i < 3; i++) { float d0 = v[i]-mean; vs += d0*d0; } \
    red[tid] = vs; __syncthreads(); \
    for (int o = 128; o > 0; o >>= 1) { if (tid < o) red[tid] += red[tid+o]; __syncthreads(); } \
    float rstd = rsqrtf(red[0]*(1.0f/DD) + 1e-12f); \
    _Pragma("unroll") for (int i = 0; i < 3; i++) { int d = tid + i*256; \
        float vv = (v[i]-mean)*rstd*w[d] + bb[d]; out[base+d] = vv; \
        if (oh) { __nv_bfloat16 hb = __float2bfloat16(vv); oh[base+d] = hb; \
                  ol[base+d] = __float2bfloat16(vv - __bfloat162float(hb)); } }

__global__ __launch_bounds__(256)
void embed_ln_kernel(const int* __restrict__ ids, const int* __restrict__ tts,
                     const float* __restrict__ we, const float* __restrict__ pe, const float* __restrict__ te,
                     const float* __restrict__ w, const float* __restrict__ bb, float* __restrict__ out,
                     __nv_bfloat16* __restrict__ oh, __nv_bfloat16* __restrict__ ol)
{
    int s = blockIdx.x % SS;
    const float* wr = we + (size_t)ids[blockIdx.x] * DD;
    const float* pr = pe + (size_t)s * DD;
    const float* tr = te + (size_t)tts[blockIdx.x] * DD;
    LN_BODY(wr[d] + pr[d] + tr[d])
}
__global__ __launch_bounds__(256)
void add_ln_kernel(const float* __restrict__ x, const float* __restrict__ y,
                   const float* __restrict__ w, const float* __restrict__ bb, float* __restrict__ out,
                   __nv_bfloat16* __restrict__ oh, __nv_bfloat16* __restrict__ ol)
{ LN_BODY(x[base+d] + y[base+d]) }
__global__ __launch_bounds__(256)
void add_ln3_kernel(const float* __restrict__ x1, const float* __restrict__ x2, const float* __restrict__ y,
                    const float* __restrict__ w, const float* __restrict__ bb, float* __restrict__ out,
                    __nv_bfloat16* __restrict__ oh, __nv_bfloat16* __restrict__ ol)
{ LN_BODY(x1[base+d] + x2[base+d] + y[base+d]) }

// ---- metric path ----
__global__ __launch_bounds__(256)
void pool_kernel(const float* __restrict__ h, float* __restrict__ hmean)
{
    int b = blockIdx.x, c0 = blockIdx.y * 128, tid = threadIdx.x;
    int col = c0 + (tid & 127), rg = tid >> 7;
    __shared__ float part[256];
    float s = 0.f;
    for (int t = rg*256; t < rg*256 + 256; t++) s += h[((size_t)b*SS + t)*DD + col];
    part[tid] = s; __syncthreads();
    if (tid < 128) hmean[b*DD + col] = (part[tid] + part[tid+128]) * (1.0f/SS);
}
__global__ __launch_bounds__(256)
void cw_kernel(const float* __restrict__ hmean, const float* __restrict__ Wcp,
               const float* __restrict__ bcp, float* __restrict__ cw)
{
    int b = blockIdx.x, tid = threadIdx.x;
    __shared__ float hm[DD]; __shared__ float part[256];
    for (int i = tid; i < DD; i += 256) hm[i] = hmean[b*DD + i];
    __syncthreads();
    int j = tid & 63, d0 = (tid >> 6) * 192;
    float acc = 0.f;
    #pragma unroll 4
    for (int d = d0; d < d0 + 192; d++) acc = fmaf(hm[d], Wcp[(size_t)d*DD + j], acc);
    part[tid] = acc; __syncthreads();
    if (tid < 64) {
        float y = bcp[tid] + part[tid] + part[tid+64] + part[tid+128] + part[tid+192];
        cw[b*HDD + tid] = 1.f / (1.f + expf(-y));
    }
}
__global__ __launch_bounds__(256)
void ginv_kernel(const float* __restrict__ Lm_l, const float* __restrict__ diag_l,
                 const float* __restrict__ cw, float* __restrict__ ginv)
{
    int b = blockIdx.x, tid = threadIdx.x;
    __shared__ float L[64][64]; __shared__ float A[64][65]; __shared__ float fcol[64];
    for (int it = 0; it < 16; it++) { int idx = it*256+tid; L[idx>>6][idx&63] = Lm_l[idx] * cw[b*HDD + (idx>>6)]; }
    __syncthreads();
    for (int it = 0; it < 16; it++) {
        int idx = it*256+tid, i = idx>>6, j = idx&63;
        float s = 0.f;
        for (int t2 = 0; t2 < 64; t2++) s = fmaf(L[i][t2], L[j][t2], s);
        if (i == j) s += diag_l[i] + 1e-6f + 0.1f;
        A[i][j] = s;
    }
    __syncthreads();
    for (int it = 0; it < 16; it++) { int idx = it*256+tid; L[idx>>6][idx&63] = ((idx>>6)==(idx&63)) ? 1.f : 0.f; }
    __syncthreads();
    for (int p = 0; p < 64; p++) {
        float ip = 1.f / A[p][p];
        float myf = (tid < 64) ? A[tid][p] : 0.f;
        __syncthreads();
        if (tid < 64) A[p][tid] *= ip; else if (tid < 128) L[p][tid-64] *= ip;
        if (tid < 64) fcol[tid] = (tid == p) ? 0.f : myf;
        __syncthreads();
        for (int it = 0; it < 32; it++) {
            int idx = it*256+tid, r = idx>>7, c = idx&127;
            if (r != p) { if (c < 64) A[r][c] -= fcol[r]*A[p][c]; else L[r][c-64] -= fcol[r]*L[p][c-64]; }
        }
        __syncthreads();
    }
    for (int it = 0; it < 16; it++) { int idx = it*256+tid; ginv[b*(HDD*HDD) + idx] = L[idx>>6][idx&63]; }
}
__global__ __launch_bounds__(256)
void qg_kernel(const float* __restrict__ q, const float* __restrict__ ginv, float* __restrict__ qg)
{
    int m0 = blockIdx.x * 64, h = blockIdx.y, b = m0 / SS, tid = threadIdx.x;
    __shared__ float Qt[64][65]; __shared__ float G[64][65];
    const float* gb = ginv + b * (HDD*HDD);
    #pragma unroll
    for (int it = 0; it < 16; it++) {
        int idx = it*256+tid, r = idx>>6, c = idx&63;
        Qt[c][r] = q[(size_t)(m0+r)*DD + h*HDD + c];
        G[r][c] = gb[idx];
    }
    __syncthreads();
    int tx = tid & 15, ty = tid >> 4;
    float acc[4][4] = {};
    for (int d = 0; d < 64; d++) {
        float a[4], bb2[4];
        #pragma unroll
        for (int i = 0; i < 4; i++) a[i] = Qt[d][ty*4+i];
        #pragma unroll
        for (int j = 0; j < 4; j++) bb2[j] = G[d][tx*4+j];
        #pragma unroll
        for (int i = 0; i < 4; i++)
            #pragma unroll
            for (int j = 0; j < 4; j++) acc[i][j] = fmaf(a[i], bb2[j], acc[i][j]);
    }
    #pragma unroll
    for (int i = 0; i < 4; i++)
        #pragma unroll
        for (int j = 0; j < 4; j++)
            qg[(size_t)(m0+ty*4+i)*DD + h*HDD + tx*4+j] = acc[i][j];
}

#define SYM(p, s) cudaGetSymbolAddress((void**)&p, s)

extern "C" void kernel_launch(void* const* d_in, const int* in_sizes, int n_in, void* d_out, int out_size)
{
    const int* ids = (const int*)d_in[0];
    const int* tts = (const int*)d_in[1];
    const float* we = (const float*)d_in[2];
    const float* pe = (const float*)d_in[3];
    const float* te = (const float*)d_in[4];
    const float* lnew = (const float*)d_in[5];
    const float* lneb = (const float*)d_in[6];
    const float* Wq = (const float*)d_in[7];
    const float* bq = (const float*)d_in[8];
    const float* Wk = (const float*)d_in[9];
    const float* bk = (const float*)d_in[10];
    const float* Wv = (const float*)d_in[11];
    const float* bv = (const float*)d_in[12];
    const float* Lm = (const float*)d_in[13];
    const float* dg = (const float*)d_in[14];
    const float* Wcp = (const float*)d_in[15];
    const float* bcp = (const float*)d_in[16];
    const float* Wi = (const float*)d_in[17];
    const float* bi = (const float*)d_in[18];
    const float* Wo = (const float*)d_in[19];
    const float* bo = (const float*)d_in[20];
    const float* l1w = (const float*)d_in[21];
    const float* l1b = (const float*)d_in[22];
    const float* l2w = (const float*)d_in[23];
    const float* l2b = (const float*)d_in[24];

    float *h,*q,*k,*v,*qg,*ctx,*a,*f,*o,*o2,*hmean,*cw,*ginv;
    __nv_bfloat16 *wqh,*wql,*wkh,*wkl,*wvh,*wvl,*wih,*wil,*woh,*wol,*hh,*hl,*ah,*al,*fh,*fl;
    SYM(h,g_h); SYM(q,g_q); SYM(k,g_k); SYM(v,g_v); SYM(qg,g_qg);
    SYM(ctx,g_ctx); SYM(a,g_a); SYM(f,g_f); SYM(o,g_o); SYM(o2,g_o2);
    SYM(hmean,g_hmean); SYM(cw,g_cw); SYM(ginv,g_ginv);
    SYM(wqh,g_wq_h); SYM(wql,g_wq_l); SYM(wkh,g_wk_h); SYM(wkl,g_wk_l);
    SYM(wvh,g_wv_h); SYM(wvl,g_wv_l); SYM(wih,g_wi_h); SYM(wil,g_wi_l);
    SYM(woh,g_wo_h); SYM(wol,g_wo_l);
    SYM(hh,g_hh); SYM(hl,g_hl); SYM(ah,g_ah); SYM(al,g_al); SYM(fh,g_fh); SYM(fl,g_fl);

    cudaFuncSetAttribute(gemm_kernel,        cudaFuncAttributeMaxDynamicSharedMemorySize, G_SMEM);
    cudaFuncSetAttribute(gemm_qkv_kernel,    cudaFuncAttributeMaxDynamicSharedMemorySize, G_SMEM);
    cudaFuncSetAttribute(gemm_splitk_kernel, cudaFuncAttributeMaxDynamicSharedMemorySize, G_SMEM);
    cudaFuncSetAttribute(flash_kernel,       cudaFuncAttributeMaxDynamicSharedMemorySize, FL_SMEM);

    split_w_kernel<<<1024, 256>>>(Wq, wqh, wql, NLL*DD*DD/4);
    split_w_kernel<<<1024, 256>>>(Wk, wkh, wkl, NLL*DD*DD/4);
    split_w_kernel<<<1024, 256>>>(Wv, wvh, wvl, NLL*DD*DD/4);
    split_w_kernel<<<2048, 256>>>(Wi, wih, wil, NLL*DD*FFF/4);
    split_w_kernel<<<2048, 256>>>(Wo, woh, wol, NLL*FFF*DD/4);

    embed_ln_kernel<<<MT, 256>>>(ids, tts, we, pe, te, lnew, lneb, h, hh, hl);

    for (int l = 0; l < NLL; l++) {
        size_t od = (size_t)l*DD*DD, of = (size_t)l*DD*FFF;

        gemm_qkv_kernel<<<dim3(18, 32), 256, G_SMEM>>>(hh, hl, wqh+od, wql+od, wkh+od, wkl+od,
            wvh+od, wvl+od, bq + l*DD, bk + l*DD, bv + l*DD, q, k, v);

        pool_kernel<<<dim3(BB, 6), 256>>>(h, hmean);
        cw_kernel<<<BB, 256>>>(hmean, Wcp + od, bcp + l*DD, cw);
        ginv_kernel<<<BB, 256>>>(Lm + (size_t)l*DD*64, dg + l*DD, cw, ginv);

        qg_kernel<<<dim3(MT/64, NHH), 256>>>(q, ginv, qg);
        flash_kernel<<<dim3(SS/128, BB*NHH), 256, FL_SMEM>>>(qg, k, v, ctx);

        add_ln_kernel<<<MT, 256>>>(ctx, h, l1w + l*DD, l1b + l*DD, a, ah, al);

        gemm_kernel<<<dim3(FFF/128, 32), 256, G_SMEM>>>(ah, al, wih+of, wil+of,
            bi + (size_t)l*FFF, f, fh, fl, FFF, DD, 1);
        gemm_splitk_kernel<<<dim3(DD/128, 32, 2), 256, G_SMEM>>>(fh, fl, woh+of, wol+of,
            bo + l*DD, o, o2);

        float* out_h = (l == NLL-1) ? (float*)d_out : h;
        add_ln3_kernel<<<MT, 256>>>(o, o2, a, l2w + l*DD, l2b + l*DD, out_h,
                                    (l == NLL-1) ? nullptr : hh, (l == NLL-1) ? nullptr : hl);
    }
}